// round 7
// baseline (speedup 1.0000x reference)
#include <cuda_runtime.h>
#include <cuda_bf16.h>
#include <math.h>
#include <stdint.h>

#define BATCH 4
#define HW    512
#define CMID  64

// ---------------------------------------------------------------------------
// Scratch (allocation-free rule: __device__ globals)
// ---------------------------------------------------------------------------
__device__ __align__(256) float g_bufA[(size_t)BATCH * HW * HW * CMID];   // conv2 offsets out
__device__ __align__(256) float g_bufB[(size_t)BATCH * HW * HW * CMID];   // conv2 weights out
__device__ __align__(256) __nv_bfloat16 g_pHo[(size_t)BATCH * HW * HW * CMID];
__device__ __align__(256) __nv_bfloat16 g_pLo[(size_t)BATCH * HW * HW * CMID];
__device__ __align__(256) __nv_bfloat16 g_pHw[(size_t)BATCH * HW * HW * CMID];
__device__ __align__(256) __nv_bfloat16 g_pLw[(size_t)BATCH * HW * HW * CMID];
__device__ __align__(256) __nv_bfloat16 g_wp1o[9 * 2 * 64 * 32];
__device__ __align__(256) __nv_bfloat16 g_wp1w[9 * 2 * 64 * 32];
__device__ __align__(256) __nv_bfloat16 g_wp2o[9 * 2 * 64 * 64];
__device__ __align__(256) __nv_bfloat16 g_wp2w[9 * 2 * 64 * 64];
__device__ int g_cls[BATCH];

__device__ __forceinline__ uint32_t smem_u32(const void* p) {
    uint32_t a;
    asm("{ .reg .u64 t; cvta.to.shared.u64 t, %1; cvt.u32.u64 %0, t; }"
        : "=r"(a) : "l"(p));
    return a;
}
__device__ __forceinline__ void ldm_x4(uint32_t* r, uint32_t addr) {
    asm volatile("ldmatrix.sync.aligned.m8n8.x4.shared.b16 {%0,%1,%2,%3}, [%4];"
                 : "=r"(r[0]), "=r"(r[1]), "=r"(r[2]), "=r"(r[3]) : "r"(addr));
}
__device__ __forceinline__ void mma16816(float* d, const uint32_t* a, const uint32_t* b) {
    asm volatile(
        "mma.sync.aligned.m16n8k16.row.col.f32.bf16.bf16.f32 "
        "{%0,%1,%2,%3}, {%4,%5,%6,%7}, {%8,%9}, {%0,%1,%2,%3};"
        : "+f"(d[0]), "+f"(d[1]), "+f"(d[2]), "+f"(d[3])
        : "r"(a[0]), "r"(a[1]), "r"(a[2]), "r"(a[3]), "r"(b[0]), "r"(b[1]));
}

// ---------------------------------------------------------------------------
// Weight prep: HWIO fp32 w[(tap*CIN+ci)*64+co] ->
//   wp[((tap*2+split)*64 + co)*CIN + ci]  (bf16 hi/lo split)
// ---------------------------------------------------------------------------
__global__ void prep_weights(const float* __restrict__ w, __nv_bfloat16* __restrict__ wp,
                             int CIN)
{
    int total = 9 * CIN * 64;
    for (int i = blockIdx.x * 256 + threadIdx.x; i < total; i += gridDim.x * 256) {
        int co  = i % 64;
        int ci  = (i / 64) % CIN;
        int tap = i / (64 * CIN);
        float f = w[i];
        __nv_bfloat16 h = __float2bfloat16(f);
        __nv_bfloat16 l = __float2bfloat16(f - __bfloat162float(h));
        wp[((size_t)(tap * 2 + 0) * 64 + co) * CIN + ci] = h;
        wp[((size_t)(tap * 2 + 1) * 64 + co) * CIN + ci] = l;
    }
}

// ---------------------------------------------------------------------------
// conv1: 32 -> 64, ReLU, outputs pre-split bf16 hi/lo planes.
// Block: 128 px of one row x 64 co. 8 warps = 4(M) x 2(N). (R5-proven shape.)
// ---------------------------------------------------------------------------
__global__ void __launch_bounds__(256, 2)
conv1_hmma(const float* __restrict__ in, const __nv_bfloat16* __restrict__ wp,
           const float* __restrict__ bias,
           __nv_bfloat16* __restrict__ pH, __nv_bfloat16* __restrict__ pL)
{
    constexpr int CIN = 32;
    constexpr int SAB = CIN * 2 + 16;     // 80
    constexpr int SBB = CIN * 2 + 16;
    constexpr int KSTEPS = CIN / 16;      // 2

    extern __shared__ char sm[];
    float* bias_s = (float*)sm;
    char*  Ah = sm + 256;
    char*  Al = Ah + 130 * SAB;
    char*  Bs = Al + 130 * SAB;

    const int tid  = threadIdx.x;
    const int lane = tid & 31;
    const int wid  = tid >> 5;
    const int wm   = wid >> 1;
    const int wn   = wid & 1;
    const int x0   = blockIdx.x * 128;
    const int y    = blockIdx.y;
    const int bz   = blockIdx.z;

    if (tid < 64) bias_s[tid] = bias[tid];

    float acc[2][4][4];
#pragma unroll
    for (int mf = 0; mf < 2; ++mf)
#pragma unroll
        for (int nf = 0; nf < 4; ++nf)
#pragma unroll
            for (int q = 0; q < 4; ++q) acc[mf][nf][q] = 0.f;

    const uint32_t AhU = smem_u32(Ah);
    const uint32_t AlU = smem_u32(Al);
    const uint32_t BsU = smem_u32(Bs);

    for (int ky = 0; ky < 3; ++ky) {
        __syncthreads();

        // B: 6 lt x 64 rows x 4 uint4
        for (int i = tid; i < 6 * 64 * 4; i += 256) {
            int c   = i & 3;
            int row = (i >> 2) & 63;
            int lt  = i >> 8;                 // kx*2+split
            int split = lt & 1, kx = lt >> 1;
            uint4 v = *(const uint4*)&wp[((size_t)((ky * 3 + kx) * 2 + split) * 64 + row) * CIN + c * 8];
            *(uint4*)(Bs + (lt * 64 + row) * SBB + c * 16) = v;
        }

        // A strip: 130 px of row y+ky-1, fp32 -> hi/lo bf16
        {
            const int gy = y + ky - 1;
            const bool rowok = (unsigned)gy < HW;
            const float* src = in + (((size_t)bz * HW + gy) * HW) * CIN;
            for (int i = tid; i < 130 * (CIN / 4); i += 256) {
                int ci4 = i & 7;
                int r   = i >> 3;
                int gx  = x0 - 1 + r;
                float4 v = make_float4(0.f, 0.f, 0.f, 0.f);
                if (rowok && (unsigned)gx < HW)
                    v = *(const float4*)&src[(size_t)gx * CIN + ci4 * 4];
                __nv_bfloat162 h0 = __float22bfloat162_rn(make_float2(v.x, v.y));
                __nv_bfloat162 h1 = __float22bfloat162_rn(make_float2(v.z, v.w));
                __nv_bfloat162 l0 = __float22bfloat162_rn(make_float2(
                    v.x - __bfloat162float(h0.x), v.y - __bfloat162float(h0.y)));
                __nv_bfloat162 l1 = __float22bfloat162_rn(make_float2(
                    v.z - __bfloat162float(h1.x), v.w - __bfloat162float(h1.y)));
                *(uint2*)(Ah + r * SAB + ci4 * 8) = make_uint2(*(uint32_t*)&h0, *(uint32_t*)&h1);
                *(uint2*)(Al + r * SAB + ci4 * 8) = make_uint2(*(uint32_t*)&l0, *(uint32_t*)&l1);
            }
        }
        __syncthreads();

        const int arow_base = wm * 32 + (lane & 15);
        const int acol      = (lane >> 4) * 16;
        const int brow_in   = (lane & 7) + ((lane >> 4) & 1) * 8;
        const int bcol      = ((lane >> 3) & 1) * 16;

#pragma unroll
        for (int kx = 0; kx < 3; ++kx) {
            const uint32_t Bh = BsU + ((kx * 2 + 0) * 64) * SBB;
            const uint32_t Bl = BsU + ((kx * 2 + 1) * 64) * SBB;
#pragma unroll
            for (int ks = 0; ks < KSTEPS; ++ks) {
                uint32_t a_h[2][4], a_l[2][4];
#pragma unroll
                for (int mf = 0; mf < 2; ++mf) {
                    uint32_t off = (uint32_t)((arow_base + mf * 16 + kx) * SAB + ks * 32 + acol);
                    ldm_x4(a_h[mf], AhU + off);
                    ldm_x4(a_l[mf], AlU + off);
                }
                uint32_t b_h[2][4], b_l[2][4];
#pragma unroll
                for (int nh = 0; nh < 2; ++nh) {
                    uint32_t roff = (uint32_t)((wn * 32 + nh * 16 + brow_in) * SBB + ks * 32 + bcol);
                    ldm_x4(b_h[nh], Bh + roff);
                    ldm_x4(b_l[nh], Bl + roff);
                }
#pragma unroll
                for (int mf = 0; mf < 2; ++mf)
#pragma unroll
                    for (int nf = 0; nf < 4; ++nf) {
                        const uint32_t* bh = &b_h[nf >> 1][(nf & 1) * 2];
                        const uint32_t* bl = &b_l[nf >> 1][(nf & 1) * 2];
                        mma16816(acc[mf][nf], a_h[mf], bh);
                        mma16816(acc[mf][nf], a_h[mf], bl);
                        mma16816(acc[mf][nf], a_l[mf], bh);
                    }
            }
        }
    }

    // epilogue: bias + relu, split to hi/lo bf16 planes
    const int prow  = lane >> 2;
    const int cbase = wn * 32 + 2 * (lane & 3);
#pragma unroll
    for (int mf = 0; mf < 2; ++mf) {
#pragma unroll
        for (int nf = 0; nf < 4; ++nf) {
            int co = cbase + nf * 8;
            float b0 = bias_s[co], b1 = bias_s[co + 1];
#pragma unroll
            for (int half = 0; half < 2; ++half) {
                int px = x0 + wm * 32 + mf * 16 + prow + half * 8;
                float f0 = fmaxf(acc[mf][nf][half * 2 + 0] + b0, 0.f);
                float f1 = fmaxf(acc[mf][nf][half * 2 + 1] + b1, 0.f);
                __nv_bfloat162 h2 = __float22bfloat162_rn(make_float2(f0, f1));
                __nv_bfloat162 l2 = __float22bfloat162_rn(make_float2(
                    f0 - __bfloat162float(h2.x), f1 - __bfloat162float(h2.y)));
                size_t o = (((size_t)bz * HW + y) * HW + px) * 64 + co;
                *(uint32_t*)&pH[o] = *(uint32_t*)&h2;
                *(uint32_t*)&pL[o] = *(uint32_t*)&l2;
            }
        }
    }
}

// ---------------------------------------------------------------------------
// conv2: 64 -> 64, ReLU, inputs pre-split bf16 planes (pure-copy staging).
// Block: 128 px x 64 co, 8 warps = 4(M) x 2(N), fp32 NHWC output.
// ---------------------------------------------------------------------------
__global__ void __launch_bounds__(256, 2)
conv2_hmma(const __nv_bfloat16* __restrict__ inH, const __nv_bfloat16* __restrict__ inL,
           const __nv_bfloat16* __restrict__ wp, const float* __restrict__ bias,
           float* __restrict__ out)
{
    constexpr int CIN = 64;
    constexpr int SAB = CIN * 2 + 16;     // 144
    constexpr int SBB = CIN * 2 + 16;
    constexpr int KSTEPS = CIN / 16;      // 4

    extern __shared__ char sm[];
    float* bias_s = (float*)sm;
    char*  Ah = sm + 256;
    char*  Al = Ah + 130 * SAB;
    char*  Bs = Al + 130 * SAB;

    const int tid  = threadIdx.x;
    const int lane = tid & 31;
    const int wid  = tid >> 5;
    const int wm   = wid >> 1;
    const int wn   = wid & 1;
    const int x0   = blockIdx.x * 128;
    const int y    = blockIdx.y;
    const int bz   = blockIdx.z;

    if (tid < 64) bias_s[tid] = bias[tid];

    float acc[2][4][4];
#pragma unroll
    for (int mf = 0; mf < 2; ++mf)
#pragma unroll
        for (int nf = 0; nf < 4; ++nf)
#pragma unroll
            for (int q = 0; q < 4; ++q) acc[mf][nf][q] = 0.f;

    const uint32_t AhU = smem_u32(Ah);
    const uint32_t AlU = smem_u32(Al);
    const uint32_t BsU = smem_u32(Bs);

    for (int ky = 0; ky < 3; ++ky) {
        __syncthreads();

        // B: 6 lt x 64 rows x 8 uint4
        for (int i = tid; i < 6 * 64 * 8; i += 256) {
            int c   = i & 7;
            int row = (i >> 3) & 63;
            int lt  = i >> 9;
            int split = lt & 1, kx = lt >> 1;
            uint4 v = *(const uint4*)&wp[((size_t)((ky * 3 + kx) * 2 + split) * 64 + row) * CIN + c * 8];
            *(uint4*)(Bs + (lt * 64 + row) * SBB + c * 16) = v;
        }

        // A strip: pure uint4 copies from hi/lo planes
        {
            const int gy = y + ky - 1;
            const bool rowok = (unsigned)gy < HW;
            const size_t rbase = ((size_t)bz * HW + gy) * HW;
            for (int i = tid; i < 130 * 8; i += 256) {
                int c  = i & 7;
                int r  = i >> 3;
                int gx = x0 - 1 + r;
                uint4 vh = make_uint4(0, 0, 0, 0), vl = vh;
                if (rowok && (unsigned)gx < HW) {
                    size_t g = (rbase + gx) * 64 + c * 8;
                    vh = *(const uint4*)&inH[g];
                    vl = *(const uint4*)&inL[g];
                }
                *(uint4*)(Ah + r * SAB + c * 16) = vh;
                *(uint4*)(Al + r * SAB + c * 16) = vl;
            }
        }
        __syncthreads();

        const int arow_base = wm * 32 + (lane & 15);
        const int acol      = (lane >> 4) * 16;
        const int brow_in   = (lane & 7) + ((lane >> 4) & 1) * 8;
        const int bcol      = ((lane >> 3) & 1) * 16;

#pragma unroll
        for (int kx = 0; kx < 3; ++kx) {
            const uint32_t Bh = BsU + ((kx * 2 + 0) * 64) * SBB;
            const uint32_t Bl = BsU + ((kx * 2 + 1) * 64) * SBB;
#pragma unroll
            for (int ks = 0; ks < KSTEPS; ++ks) {
                uint32_t a_h[2][4], a_l[2][4];
#pragma unroll
                for (int mf = 0; mf < 2; ++mf) {
                    uint32_t off = (uint32_t)((arow_base + mf * 16 + kx) * SAB + ks * 32 + acol);
                    ldm_x4(a_h[mf], AhU + off);
                    ldm_x4(a_l[mf], AlU + off);
                }
                uint32_t b_h[2][4], b_l[2][4];
#pragma unroll
                for (int nh = 0; nh < 2; ++nh) {
                    uint32_t roff = (uint32_t)((wn * 32 + nh * 16 + brow_in) * SBB + ks * 32 + bcol);
                    ldm_x4(b_h[nh], Bh + roff);
                    ldm_x4(b_l[nh], Bl + roff);
                }
#pragma unroll
                for (int mf = 0; mf < 2; ++mf)
#pragma unroll
                    for (int nf = 0; nf < 4; ++nf) {
                        const uint32_t* bh = &b_h[nf >> 1][(nf & 1) * 2];
                        const uint32_t* bl = &b_l[nf >> 1][(nf & 1) * 2];
                        mma16816(acc[mf][nf], a_h[mf], bh);
                        mma16816(acc[mf][nf], a_h[mf], bl);
                        mma16816(acc[mf][nf], a_l[mf], bh);
                    }
            }
        }
    }

    const int prow  = lane >> 2;
    const int cbase = wn * 32 + 2 * (lane & 3);
#pragma unroll
    for (int mf = 0; mf < 2; ++mf) {
#pragma unroll
        for (int nf = 0; nf < 4; ++nf) {
            int co = cbase + nf * 8;
            float b0 = bias_s[co], b1 = bias_s[co + 1];
            int p0 = x0 + wm * 32 + mf * 16 + prow;
            float* o0 = out + (((size_t)bz * HW + y) * HW + p0) * 64 + co;
            float2 v;
            v.x = fmaxf(acc[mf][nf][0] + b0, 0.f);
            v.y = fmaxf(acc[mf][nf][1] + b1, 0.f);
            *(float2*)o0 = v;
            float* o1 = o0 + 8 * 64;
            v.x = fmaxf(acc[mf][nf][2] + b0, 0.f);
            v.y = fmaxf(acc[mf][nf][3] + b1, 0.f);
            *(float2*)o1 = v;
        }
    }
}

// ---------------------------------------------------------------------------
// Head: GAP(f4) -> FC chain -> softmax -> pred_cls + argmax cls
// ---------------------------------------------------------------------------
__global__ void head_kernel(const float* __restrict__ f4,
                            const float* __restrict__ Wc1, const float* __restrict__ bc1,
                            const float* __restrict__ Wc2, const float* __restrict__ bc2,
                            const float* __restrict__ Wc3, const float* __restrict__ bc3,
                            float* __restrict__ out_pred)
{
    __shared__ float gap[256];
    __shared__ float z1[128];
    __shared__ float z2[128];
    __shared__ float logits[3];

    const int b = blockIdx.x;
    const int tid = threadIdx.x;

    const float* p = f4 + (size_t)b * 1024 * 256 + tid;
    float s0 = 0.f, s1 = 0.f, s2 = 0.f, s3 = 0.f;
    for (int i = 0; i < 1024; i += 4) {
        s0 += p[(i + 0) * 256];
        s1 += p[(i + 1) * 256];
        s2 += p[(i + 2) * 256];
        s3 += p[(i + 3) * 256];
    }
    gap[tid] = (s0 + s1 + s2 + s3) * (1.0f / 1024.0f);
    __syncthreads();

    if (tid < 128) {
        float a = bc1[tid];
#pragma unroll 8
        for (int k = 0; k < 256; ++k) a = fmaf(gap[k], Wc1[k * 128 + tid], a);
        z1[tid] = fmaxf(a, 0.f);
    }
    __syncthreads();

    if (tid < 128) {
        float a = bc2[tid];
#pragma unroll 8
        for (int k = 0; k < 128; ++k) a = fmaf(z1[k], Wc2[k * 128 + tid], a);
        z2[tid] = fmaxf(a, 0.f);
    }
    __syncthreads();

    if (tid < 3) {
        float a = bc3[tid];
        for (int k = 0; k < 128; ++k) a = fmaf(z2[k], Wc3[k * 3 + tid], a);
        logits[tid] = a;
    }
    __syncthreads();

    if (tid == 0) {
        float l0 = logits[0], l1 = logits[1], l2 = logits[2];
        float m = fmaxf(l0, fmaxf(l1, l2));
        float e0 = expf(l0 - m), e1 = expf(l1 - m), e2 = expf(l2 - m);
        float inv = 1.f / (e0 + e1 + e2);
        out_pred[b * 3 + 0] = e0 * inv;
        out_pred[b * 3 + 1] = e1 * inv;
        out_pred[b * 3 + 2] = e2 * inv;
        int c = 0; float best = l0;
        if (l1 > best) { best = l1; c = 1; }
        if (l2 > best) { best = l2; c = 2; }
        g_cls[b] = c;
    }
}

// ---------------------------------------------------------------------------
// Final convs fused with channel gather (only selected channels computed).
// ---------------------------------------------------------------------------
__global__ void __launch_bounds__(256, 1)
conv3_select(const float* __restrict__ h2o, const float* __restrict__ h2w,
             const float* __restrict__ Wo3, const float* __restrict__ bo3,
             const float* __restrict__ Ww3, const float* __restrict__ bw3,
             float* __restrict__ out)
{
    extern __shared__ float smem[];
    float* ho = smem;                 // 64 * 342  (ci-major, pitch 19)
    float* hw = smem + 64 * 342;
    float* ws = smem + 2 * 64 * 342;  // 576 * 3 selected weights

    const int b   = blockIdx.z;
    const int y0  = blockIdx.y * 16;
    const int x0  = blockIdx.x * 16;
    const int tid = threadIdx.x;
    const int cls = g_cls[b];

    for (int i = tid; i < 576; i += 256) {
        ws[i * 3 + 0] = Wo3[i * 6 + 2 * cls];
        ws[i * 3 + 1] = Wo3[i * 6 + 2 * cls + 1];
        ws[i * 3 + 2] = Ww3[i * 3 + cls];
    }

    const float* po = h2o + (size_t)b * HW * HW * 64;
    const float* pw = h2w + (size_t)b * HW * HW * 64;
    for (int i = tid; i < 324 * 16; i += 256) {
        int ci4 = i & 15;
        int rc  = i >> 4;
        int r = rc / 18, c = rc % 18;
        int gy = y0 + r - 1, gx = x0 + c - 1;
        float4 vo = make_float4(0.f, 0.f, 0.f, 0.f);
        float4 vw = vo;
        if ((unsigned)gy < HW && (unsigned)gx < HW) {
            size_t g = ((size_t)gy * HW + gx) * 64 + ci4 * 4;
            vo = *(const float4*)&po[g];
            vw = *(const float4*)&pw[g];
        }
        int base = r * 19 + c;
        ho[(ci4 * 4 + 0) * 342 + base] = vo.x;
        ho[(ci4 * 4 + 1) * 342 + base] = vo.y;
        ho[(ci4 * 4 + 2) * 342 + base] = vo.z;
        ho[(ci4 * 4 + 3) * 342 + base] = vo.w;
        hw[(ci4 * 4 + 0) * 342 + base] = vw.x;
        hw[(ci4 * 4 + 1) * 342 + base] = vw.y;
        hw[(ci4 * 4 + 2) * 342 + base] = vw.z;
        hw[(ci4 * 4 + 3) * 342 + base] = vw.w;
    }
    __syncthreads();

    const int r = tid >> 4, c = tid & 15;
    float o0 = bo3[2 * cls], o1 = bo3[2 * cls + 1], wv = bw3[cls];

#pragma unroll 1
    for (int ky = 0; ky < 3; ++ky) {
#pragma unroll 1
        for (int kx = 0; kx < 3; ++kx) {
            int base = (r + ky) * 19 + (c + kx);
            const float* wp = &ws[(ky * 3 + kx) * 64 * 3];
#pragma unroll 8
            for (int ci = 0; ci < 64; ++ci) {
                float ao = ho[ci * 342 + base];
                float aw = hw[ci * 342 + base];
                o0 = fmaf(ao, wp[ci * 3 + 0], o0);
                o1 = fmaf(ao, wp[ci * 3 + 1], o1);
                wv = fmaf(aw, wp[ci * 3 + 2], wv);
            }
        }
    }

    int gy = y0 + r, gx = x0 + c;
    size_t pix = ((size_t)b * HW + gy) * HW + gx;
    *(float2*)&out[pix * 2] = make_float2(o0, o1);
    out[(size_t)BATCH * HW * HW * 2 + pix] = wv;
}

// ---------------------------------------------------------------------------
extern "C" void kernel_launch(void* const* d_in, const int* in_sizes, int n_in,
                              void* d_out, int out_size)
{
    (void)in_sizes; (void)n_in; (void)out_size;
    const float* x0  = (const float*)d_in[0];
    const float* f4  = (const float*)d_in[1];
    const float* Wo1 = (const float*)d_in[2];
    const float* bo1 = (const float*)d_in[3];
    const float* Wo2 = (const float*)d_in[4];
    const float* bo2 = (const float*)d_in[5];
    const float* Wo3 = (const float*)d_in[6];
    const float* bo3 = (const float*)d_in[7];
    const float* Ww1 = (const float*)d_in[8];
    const float* bw1 = (const float*)d_in[9];
    const float* Ww2 = (const float*)d_in[10];
    const float* bw2 = (const float*)d_in[11];
    const float* Ww3 = (const float*)d_in[12];
    const float* bw3 = (const float*)d_in[13];
    const float* Wc1 = (const float*)d_in[14];
    const float* bc1 = (const float*)d_in[15];
    const float* Wc2 = (const float*)d_in[16];
    const float* bc2 = (const float*)d_in[17];
    const float* Wc3 = (const float*)d_in[18];
    const float* bc3 = (const float*)d_in[19];
    float* out = (float*)d_out;

    void *pA, *pB, *pW1o, *pW1w, *pW2o, *pW2w, *pHo, *pLo, *pHw, *pLw;
    cudaGetSymbolAddress(&pA, g_bufA);
    cudaGetSymbolAddress(&pB, g_bufB);
    cudaGetSymbolAddress(&pW1o, g_wp1o);
    cudaGetSymbolAddress(&pW1w, g_wp1w);
    cudaGetSymbolAddress(&pW2o, g_wp2o);
    cudaGetSymbolAddress(&pW2w, g_wp2w);
    cudaGetSymbolAddress(&pHo, g_pHo);
    cudaGetSymbolAddress(&pLo, g_pLo);
    cudaGetSymbolAddress(&pHw, g_pHw);
    cudaGetSymbolAddress(&pLw, g_pLw);

    const size_t smem1 = 256 + (size_t)2 * 130 * 80 + (size_t)6 * 64 * 80;    //  51.8 KB
    const size_t smem2 = 256 + (size_t)2 * 130 * 144 + (size_t)6 * 64 * 144;  //  90.8 KB
    const size_t smem3 = (size_t)(2 * 64 * 342 + 576 * 3) * sizeof(float);    // 182.0 KB

    cudaFuncSetAttribute(conv1_hmma,  cudaFuncAttributeMaxDynamicSharedMemorySize, (int)smem1);
    cudaFuncSetAttribute(conv2_hmma,  cudaFuncAttributeMaxDynamicSharedMemorySize, (int)smem2);
    cudaFuncSetAttribute(conv3_select, cudaFuncAttributeMaxDynamicSharedMemorySize, (int)smem3);

    float* pred = out + (size_t)BATCH * HW * HW * 3;

    // independent prep first (no bubbles between conv layers)
    head_kernel<<<BATCH, 256>>>(f4, Wc1, bc1, Wc2, bc2, Wc3, bc3, pred);
    prep_weights<<<36, 256>>>(Wo1, (__nv_bfloat16*)pW1o, 32);
    prep_weights<<<36, 256>>>(Ww1, (__nv_bfloat16*)pW1w, 32);
    prep_weights<<<72, 256>>>(Wo2, (__nv_bfloat16*)pW2o, 64);
    prep_weights<<<72, 256>>>(Ww2, (__nv_bfloat16*)pW2w, 64);

    dim3 gmma(HW / 128, HW, BATCH);
    conv1_hmma<<<gmma, 256, smem1>>>(x0, (__nv_bfloat16*)pW1o, bo1,
                                     (__nv_bfloat16*)pHo, (__nv_bfloat16*)pLo);
    conv1_hmma<<<gmma, 256, smem1>>>(x0, (__nv_bfloat16*)pW1w, bw1,
                                     (__nv_bfloat16*)pHw, (__nv_bfloat16*)pLw);
    conv2_hmma<<<gmma, 256, smem2>>>((__nv_bfloat16*)pHo, (__nv_bfloat16*)pLo,
                                     (__nv_bfloat16*)pW2o, bo2, (float*)pA);
    conv2_hmma<<<gmma, 256, smem2>>>((__nv_bfloat16*)pHw, (__nv_bfloat16*)pLw,
                                     (__nv_bfloat16*)pW2w, bw2, (float*)pB);

    dim3 g3(HW / 16, HW / 16, BATCH);
    conv3_select<<<g3, 256, smem3>>>((float*)pA, (float*)pB, Wo3, bo3, Ww3, bw3, out);
}

// round 8
// speedup vs baseline: 1.0423x; 1.0423x over previous
#include <cuda_runtime.h>
#include <cuda_bf16.h>
#include <math.h>
#include <stdint.h>

#define BATCH 4
#define HW    512
#define CMID  64

// ---------------------------------------------------------------------------
// Scratch (allocation-free rule: __device__ globals)
// ---------------------------------------------------------------------------
__device__ __align__(256) float g_bufA[(size_t)BATCH * HW * HW * CMID];
__device__ __align__(256) float g_bufB[(size_t)BATCH * HW * HW * CMID];
__device__ __align__(256) float g_bufC[(size_t)BATCH * HW * HW * CMID];
__device__ __align__(256) __nv_bfloat16 g_wp1o[9 * 2 * 64 * 32];
__device__ __align__(256) __nv_bfloat16 g_wp1w[9 * 2 * 64 * 32];
__device__ __align__(256) __nv_bfloat16 g_wp2o[9 * 2 * 64 * 64];
__device__ __align__(256) __nv_bfloat16 g_wp2w[9 * 2 * 64 * 64];
__device__ int g_cls[BATCH];

__device__ __forceinline__ uint32_t smem_u32(const void* p) {
    uint32_t a;
    asm("{ .reg .u64 t; cvta.to.shared.u64 t, %1; cvt.u32.u64 %0, t; }"
        : "=r"(a) : "l"(p));
    return a;
}
__device__ __forceinline__ void ldm_x4(uint32_t* r, uint32_t addr) {
    asm volatile("ldmatrix.sync.aligned.m8n8.x4.shared.b16 {%0,%1,%2,%3}, [%4];"
                 : "=r"(r[0]), "=r"(r[1]), "=r"(r[2]), "=r"(r[3]) : "r"(addr));
}
__device__ __forceinline__ void mma16816(float* d, const uint32_t* a, const uint32_t* b) {
    asm volatile(
        "mma.sync.aligned.m16n8k16.row.col.f32.bf16.bf16.f32 "
        "{%0,%1,%2,%3}, {%4,%5,%6,%7}, {%8,%9}, {%0,%1,%2,%3};"
        : "+f"(d[0]), "+f"(d[1]), "+f"(d[2]), "+f"(d[3])
        : "r"(a[0]), "r"(a[1]), "r"(a[2]), "r"(a[3]), "r"(b[0]), "r"(b[1]));
}

// ---------------------------------------------------------------------------
// Weight prep: HWIO fp32 w[(tap*CIN+ci)*64+co] ->
//   wp[((tap*2+split)*64 + co)*CIN + ci]  (bf16 hi/lo split)
// ---------------------------------------------------------------------------
__global__ void prep_weights(const float* __restrict__ w, __nv_bfloat16* __restrict__ wp,
                             int CIN)
{
    int total = 9 * CIN * 64;
    for (int i = blockIdx.x * 256 + threadIdx.x; i < total; i += gridDim.x * 256) {
        int co  = i % 64;
        int ci  = (i / 64) % CIN;
        int tap = i / (64 * CIN);
        float f = w[i];
        __nv_bfloat16 h = __float2bfloat16(f);
        __nv_bfloat16 l = __float2bfloat16(f - __bfloat162float(h));
        wp[((size_t)(tap * 2 + 0) * 64 + co) * CIN + ci] = h;
        wp[((size_t)(tap * 2 + 1) * 64 + co) * CIN + ci] = l;
    }
}

// ---------------------------------------------------------------------------
// 3x3 SAME conv, CIN -> 64, ReLU, mma.sync bf16x3.
// Block: M = 4 output rows x 32 px (=128), N = 64 co. 8 warps = 4(Mrow) x 2(N).
// A: one 6-row x 34-px input block staged ONCE per block; hi/lo interleaved
//    per pixel row: [hi CIN*2 B][lo CIN*2 B][16 B pad].
// B: per-ky 3 taps staged, same interleaved layout per co row.
// ---------------------------------------------------------------------------
template <int CIN>
__global__ void __launch_bounds__(256, 2)
conv3x3_rows(const float* __restrict__ in, const __nv_bfloat16* __restrict__ wp,
             const float* __restrict__ bias, float* __restrict__ out)
{
    constexpr int DATA   = CIN * 2;          // bytes per split row
    constexpr int PITCH  = 2 * DATA + 16;    // conv2: 272, conv1: 144
    constexpr int KSTEPS = CIN / 16;

    extern __shared__ char sm[];
    float* bias_s = (float*)sm;              // 256 B
    char*  As = sm + 256;                    // 204 * PITCH
    char*  Bs = As + 204 * PITCH;            // 192 * PITCH

    const int tid  = threadIdx.x;
    const int lane = tid & 31;
    const int wid  = tid >> 5;
    const int wm   = wid >> 1;        // output row 0..3
    const int wn   = wid & 1;         // co half
    const int x0   = blockIdx.x * 32;
    const int y0   = blockIdx.y * 4;
    const int bz   = blockIdx.z;

    if (tid < 64) bias_s[tid] = bias[tid];

    float acc[2][4][4];
#pragma unroll
    for (int mf = 0; mf < 2; ++mf)
#pragma unroll
        for (int nf = 0; nf < 4; ++nf)
#pragma unroll
            for (int q = 0; q < 4; ++q) acc[mf][nf][q] = 0.f;

    const uint32_t AsU = smem_u32(As);
    const uint32_t BsU = smem_u32(Bs);

    // --- stage A once: 6 input rows (y0-1 .. y0+4) x 34 px (x0-1 .. x0+32)
    {
        const float* ib = in + (size_t)bz * HW * HW * CIN;
        for (int i = tid; i < 204 * (CIN / 4); i += 256) {
            int ci4 = i % (CIN / 4);
            int px  = i / (CIN / 4);
            int irow = px / 34, c = px % 34;
            int gy = y0 - 1 + irow;
            int gx = x0 - 1 + c;
            float4 v = make_float4(0.f, 0.f, 0.f, 0.f);
            if ((unsigned)gy < HW && (unsigned)gx < HW)
                v = *(const float4*)&ib[((size_t)gy * HW + gx) * CIN + ci4 * 4];
            __nv_bfloat162 h0 = __float22bfloat162_rn(make_float2(v.x, v.y));
            __nv_bfloat162 h1 = __float22bfloat162_rn(make_float2(v.z, v.w));
            __nv_bfloat162 l0 = __float22bfloat162_rn(make_float2(
                v.x - __bfloat162float(h0.x), v.y - __bfloat162float(h0.y)));
            __nv_bfloat162 l1 = __float22bfloat162_rn(make_float2(
                v.z - __bfloat162float(h1.x), v.w - __bfloat162float(h1.y)));
            char* dst = As + px * PITCH + ci4 * 8;
            *(uint2*)dst          = make_uint2(*(uint32_t*)&h0, *(uint32_t*)&h1);
            *(uint2*)(dst + DATA) = make_uint2(*(uint32_t*)&l0, *(uint32_t*)&l1);
        }
    }

    // --- B staging helper (3 taps of row ky, interleaved hi/lo)
    auto stage_B = [&](int ky) {
        constexpr int CH = CIN / 8;             // uint4 chunks per split row
        for (int i = tid; i < 3 * 64 * 2 * CH; i += 256) {
            int c   = i % CH;
            int row = (i / CH) & 63;
            int s   = (i / (CH * 64)) & 1;
            int tap = i / (CH * 64 * 2);
            uint4 v = *(const uint4*)&wp[((size_t)((ky * 3 + tap) * 2 + s) * 64 + row) * CIN + c * 8];
            *(uint4*)(Bs + (tap * 64 + row) * PITCH + s * DATA + c * 16) = v;
        }
    };

    stage_B(0);
    __syncthreads();

    const int brow_in = (lane & 7) + ((lane >> 4) & 1) * 8;
    const int bcol    = ((lane >> 3) & 1) * 16;
    const int acol    = (lane >> 4) * 16;
    const int apx     = (lane & 15);

    for (int ky = 0; ky < 3; ++ky) {
#pragma unroll
        for (int kx = 0; kx < 3; ++kx) {
#pragma unroll
            for (int ks = 0; ks < KSTEPS; ++ks) {
                uint32_t a_h[2][4], a_l[2][4];
#pragma unroll
                for (int mf = 0; mf < 2; ++mf) {
                    int px = (wm + ky) * 34 + mf * 16 + apx + kx;
                    uint32_t off = (uint32_t)(px * PITCH + ks * 32 + acol);
                    ldm_x4(a_h[mf], AsU + off);
                    ldm_x4(a_l[mf], AsU + off + DATA);
                }
                uint32_t b_h[2][4], b_l[2][4];
#pragma unroll
                for (int nh = 0; nh < 2; ++nh) {
                    int row = wn * 32 + nh * 16 + brow_in;
                    uint32_t roff = (uint32_t)((kx * 64 + row) * PITCH + ks * 32 + bcol);
                    ldm_x4(b_h[nh], BsU + roff);
                    ldm_x4(b_l[nh], BsU + roff + DATA);
                }
#pragma unroll
                for (int mf = 0; mf < 2; ++mf)
#pragma unroll
                    for (int nf = 0; nf < 4; ++nf) {
                        const uint32_t* bh = &b_h[nf >> 1][(nf & 1) * 2];
                        const uint32_t* bl = &b_l[nf >> 1][(nf & 1) * 2];
                        mma16816(acc[mf][nf], a_h[mf], bh);
                        mma16816(acc[mf][nf], a_h[mf], bl);
                        mma16816(acc[mf][nf], a_l[mf], bh);
                    }
            }
        }
        if (ky < 2) {
            __syncthreads();       // compute done, B free
            stage_B(ky + 1);
            __syncthreads();       // new B ready
        }
    }

    // --- epilogue: bias + relu, NHWC fp32 store
    const int prow  = lane >> 2;
    const int cbase = wn * 32 + 2 * (lane & 3);
    const int gy    = y0 + wm;
#pragma unroll
    for (int mf = 0; mf < 2; ++mf) {
#pragma unroll
        for (int nf = 0; nf < 4; ++nf) {
            int co = cbase + nf * 8;
            float b0 = bias_s[co], b1 = bias_s[co + 1];
            int gx = x0 + mf * 16 + prow;
            float* o0 = out + (((size_t)bz * HW + gy) * HW + gx) * 64 + co;
            float2 v;
            v.x = fmaxf(acc[mf][nf][0] + b0, 0.f);
            v.y = fmaxf(acc[mf][nf][1] + b1, 0.f);
            *(float2*)o0 = v;
            float* o1 = o0 + 8 * 64;                       // gx + 8
            v.x = fmaxf(acc[mf][nf][2] + b0, 0.f);
            v.y = fmaxf(acc[mf][nf][3] + b1, 0.f);
            *(float2*)o1 = v;
        }
    }
}

// ---------------------------------------------------------------------------
// Head: GAP(f4) -> FC chain -> softmax -> pred_cls + argmax cls
// ---------------------------------------------------------------------------
__global__ void head_kernel(const float* __restrict__ f4,
                            const float* __restrict__ Wc1, const float* __restrict__ bc1,
                            const float* __restrict__ Wc2, const float* __restrict__ bc2,
                            const float* __restrict__ Wc3, const float* __restrict__ bc3,
                            float* __restrict__ out_pred)
{
    __shared__ float gap[256];
    __shared__ float z1[128];
    __shared__ float z2[128];
    __shared__ float logits[3];

    const int b = blockIdx.x;
    const int tid = threadIdx.x;

    const float* p = f4 + (size_t)b * 1024 * 256 + tid;
    float s0 = 0.f, s1 = 0.f, s2 = 0.f, s3 = 0.f;
    for (int i = 0; i < 1024; i += 4) {
        s0 += p[(i + 0) * 256];
        s1 += p[(i + 1) * 256];
        s2 += p[(i + 2) * 256];
        s3 += p[(i + 3) * 256];
    }
    gap[tid] = (s0 + s1 + s2 + s3) * (1.0f / 1024.0f);
    __syncthreads();

    if (tid < 128) {
        float a = bc1[tid];
#pragma unroll 8
        for (int k = 0; k < 256; ++k) a = fmaf(gap[k], Wc1[k * 128 + tid], a);
        z1[tid] = fmaxf(a, 0.f);
    }
    __syncthreads();

    if (tid < 128) {
        float a = bc2[tid];
#pragma unroll 8
        for (int k = 0; k < 128; ++k) a = fmaf(z1[k], Wc2[k * 128 + tid], a);
        z2[tid] = fmaxf(a, 0.f);
    }
    __syncthreads();

    if (tid < 3) {
        float a = bc3[tid];
        for (int k = 0; k < 128; ++k) a = fmaf(z2[k], Wc3[k * 3 + tid], a);
        logits[tid] = a;
    }
    __syncthreads();

    if (tid == 0) {
        float l0 = logits[0], l1 = logits[1], l2 = logits[2];
        float m = fmaxf(l0, fmaxf(l1, l2));
        float e0 = expf(l0 - m), e1 = expf(l1 - m), e2 = expf(l2 - m);
        float inv = 1.f / (e0 + e1 + e2);
        out_pred[b * 3 + 0] = e0 * inv;
        out_pred[b * 3 + 1] = e1 * inv;
        out_pred[b * 3 + 2] = e2 * inv;
        int c = 0; float best = l0;
        if (l1 > best) { best = l1; c = 1; }
        if (l2 > best) { best = l2; c = 2; }
        g_cls[b] = c;
    }
}

// ---------------------------------------------------------------------------
// Final convs fused with channel gather (only selected channels computed).
// ---------------------------------------------------------------------------
__global__ void __launch_bounds__(256, 1)
conv3_select(const float* __restrict__ h2o, const float* __restrict__ h2w,
             const float* __restrict__ Wo3, const float* __restrict__ bo3,
             const float* __restrict__ Ww3, const float* __restrict__ bw3,
             float* __restrict__ out)
{
    extern __shared__ float smem[];
    float* ho = smem;                 // 64 * 342  (ci-major, pitch 19)
    float* hw = smem + 64 * 342;
    float* ws = smem + 2 * 64 * 342;  // 576 * 3 selected weights

    const int b   = blockIdx.z;
    const int y0  = blockIdx.y * 16;
    const int x0  = blockIdx.x * 16;
    const int tid = threadIdx.x;
    const int cls = g_cls[b];

    for (int i = tid; i < 576; i += 256) {
        ws[i * 3 + 0] = Wo3[i * 6 + 2 * cls];
        ws[i * 3 + 1] = Wo3[i * 6 + 2 * cls + 1];
        ws[i * 3 + 2] = Ww3[i * 3 + cls];
    }

    const float* po = h2o + (size_t)b * HW * HW * 64;
    const float* pw = h2w + (size_t)b * HW * HW * 64;
    for (int i = tid; i < 324 * 16; i += 256) {
        int ci4 = i & 15;
        int rc  = i >> 4;
        int r = rc / 18, c = rc % 18;
        int gy = y0 + r - 1, gx = x0 + c - 1;
        float4 vo = make_float4(0.f, 0.f, 0.f, 0.f);
        float4 vw = vo;
        if ((unsigned)gy < HW && (unsigned)gx < HW) {
            size_t g = ((size_t)gy * HW + gx) * 64 + ci4 * 4;
            vo = *(const float4*)&po[g];
            vw = *(const float4*)&pw[g];
        }
        int base = r * 19 + c;
        ho[(ci4 * 4 + 0) * 342 + base] = vo.x;
        ho[(ci4 * 4 + 1) * 342 + base] = vo.y;
        ho[(ci4 * 4 + 2) * 342 + base] = vo.z;
        ho[(ci4 * 4 + 3) * 342 + base] = vo.w;
        hw[(ci4 * 4 + 0) * 342 + base] = vw.x;
        hw[(ci4 * 4 + 1) * 342 + base] = vw.y;
        hw[(ci4 * 4 + 2) * 342 + base] = vw.z;
        hw[(ci4 * 4 + 3) * 342 + base] = vw.w;
    }
    __syncthreads();

    const int r = tid >> 4, c = tid & 15;
    float o0 = bo3[2 * cls], o1 = bo3[2 * cls + 1], wv = bw3[cls];

#pragma unroll 1
    for (int ky = 0; ky < 3; ++ky) {
#pragma unroll 1
        for (int kx = 0; kx < 3; ++kx) {
            int base = (r + ky) * 19 + (c + kx);
            const float* wp = &ws[(ky * 3 + kx) * 64 * 3];
#pragma unroll 8
            for (int ci = 0; ci < 64; ++ci) {
                float ao = ho[ci * 342 + base];
                float aw = hw[ci * 342 + base];
                o0 = fmaf(ao, wp[ci * 3 + 0], o0);
                o1 = fmaf(ao, wp[ci * 3 + 1], o1);
                wv = fmaf(aw, wp[ci * 3 + 2], wv);
            }
        }
    }

    int gy = y0 + r, gx = x0 + c;
    size_t pix = ((size_t)b * HW + gy) * HW + gx;
    *(float2*)&out[pix * 2] = make_float2(o0, o1);
    out[(size_t)BATCH * HW * HW * 2 + pix] = wv;
}

// ---------------------------------------------------------------------------
extern "C" void kernel_launch(void* const* d_in, const int* in_sizes, int n_in,
                              void* d_out, int out_size)
{
    (void)in_sizes; (void)n_in; (void)out_size;
    const float* x0  = (const float*)d_in[0];
    const float* f4  = (const float*)d_in[1];
    const float* Wo1 = (const float*)d_in[2];
    const float* bo1 = (const float*)d_in[3];
    const float* Wo2 = (const float*)d_in[4];
    const float* bo2 = (const float*)d_in[5];
    const float* Wo3 = (const float*)d_in[6];
    const float* bo3 = (const float*)d_in[7];
    const float* Ww1 = (const float*)d_in[8];
    const float* bw1 = (const float*)d_in[9];
    const float* Ww2 = (const float*)d_in[10];
    const float* bw2 = (const float*)d_in[11];
    const float* Ww3 = (const float*)d_in[12];
    const float* bw3 = (const float*)d_in[13];
    const float* Wc1 = (const float*)d_in[14];
    const float* bc1 = (const float*)d_in[15];
    const float* Wc2 = (const float*)d_in[16];
    const float* bc2 = (const float*)d_in[17];
    const float* Wc3 = (const float*)d_in[18];
    const float* bc3 = (const float*)d_in[19];
    float* out = (float*)d_out;

    void *pA, *pB, *pC, *pW1o, *pW1w, *pW2o, *pW2w;
    cudaGetSymbolAddress(&pA, g_bufA);
    cudaGetSymbolAddress(&pB, g_bufB);
    cudaGetSymbolAddress(&pC, g_bufC);
    cudaGetSymbolAddress(&pW1o, g_wp1o);
    cudaGetSymbolAddress(&pW1w, g_wp1w);
    cudaGetSymbolAddress(&pW2o, g_wp2o);
    cudaGetSymbolAddress(&pW2w, g_wp2w);

    const size_t smem1 = 256 + (size_t)(204 + 192) * 144;                    //  57.3 KB
    const size_t smem2 = 256 + (size_t)(204 + 192) * 272;                    // 108.0 KB
    const size_t smem3 = (size_t)(2 * 64 * 342 + 576 * 3) * sizeof(float);   // 182.0 KB

    cudaFuncSetAttribute(conv3x3_rows<32>, cudaFuncAttributeMaxDynamicSharedMemorySize, (int)smem1);
    cudaFuncSetAttribute(conv3x3_rows<64>, cudaFuncAttributeMaxDynamicSharedMemorySize, (int)smem2);
    cudaFuncSetAttribute(conv3_select,     cudaFuncAttributeMaxDynamicSharedMemorySize, (int)smem3);

    float* pred = out + (size_t)BATCH * HW * HW * 3;

    head_kernel<<<BATCH, 256>>>(f4, Wc1, bc1, Wc2, bc2, Wc3, bc3, pred);
    prep_weights<<<36, 256>>>(Wo1, (__nv_bfloat16*)pW1o, 32);
    prep_weights<<<36, 256>>>(Ww1, (__nv_bfloat16*)pW1w, 32);
    prep_weights<<<72, 256>>>(Wo2, (__nv_bfloat16*)pW2o, 64);
    prep_weights<<<72, 256>>>(Ww2, (__nv_bfloat16*)pW2w, 64);

    dim3 gconv(HW / 32, HW / 4, BATCH);   // 16 x-tiles, 128 row-groups, 4 batches
    conv3x3_rows<32><<<gconv, 256, smem1>>>(x0, (__nv_bfloat16*)pW1o, bo1, (float*)pA);
    conv3x3_rows<32><<<gconv, 256, smem1>>>(x0, (__nv_bfloat16*)pW1w, bw1, (float*)pB);
    conv3x3_rows<64><<<gconv, 256, smem2>>>((float*)pA, (__nv_bfloat16*)pW2o, bo2, (float*)pC);
    conv3x3_rows<64><<<gconv, 256, smem2>>>((float*)pB, (__nv_bfloat16*)pW2w, bw2, (float*)pA);

    dim3 g3(HW / 16, HW / 16, BATCH);
    conv3_select<<<g3, 256, smem3>>>((float*)pC, (float*)pA, Wo3, bo3, Ww3, bw3, out);
}

// round 9
// speedup vs baseline: 1.2188x; 1.1693x over previous
#include <cuda_runtime.h>
#include <cuda_fp16.h>
#include <math.h>
#include <stdint.h>

#define BATCH 4
#define HW    512
#define CMID  64

// ---------------------------------------------------------------------------
// Scratch (allocation-free rule: __device__ globals)
// ---------------------------------------------------------------------------
__device__ __align__(256) float g_bufA[(size_t)BATCH * HW * HW * CMID];
__device__ __align__(256) float g_bufB[(size_t)BATCH * HW * HW * CMID];
__device__ __align__(256) float g_bufC[(size_t)BATCH * HW * HW * CMID];
__device__ __align__(256) __half g_wp1o[9 * 2 * 64 * 32];
__device__ __align__(256) __half g_wp1w[9 * 2 * 64 * 32];
__device__ __align__(256) __half g_wp2o[9 * 2 * 64 * 64];
__device__ __align__(256) __half g_wp2w[9 * 2 * 64 * 64];
__device__ int g_cls[BATCH];

__device__ __forceinline__ uint32_t smem_u32(const void* p) {
    uint32_t a;
    asm("{ .reg .u64 t; cvta.to.shared.u64 t, %1; cvt.u32.u64 %0, t; }"
        : "=r"(a) : "l"(p));
    return a;
}
__device__ __forceinline__ void ldm_x4(uint32_t* r, uint32_t addr) {
    asm volatile("ldmatrix.sync.aligned.m8n8.x4.shared.b16 {%0,%1,%2,%3}, [%4];"
                 : "=r"(r[0]), "=r"(r[1]), "=r"(r[2]), "=r"(r[3]) : "r"(addr));
}
__device__ __forceinline__ void mma16816(float* d, const uint32_t* a, const uint32_t* b) {
    asm volatile(
        "mma.sync.aligned.m16n8k16.row.col.f32.f16.f16.f32 "
        "{%0,%1,%2,%3}, {%4,%5,%6,%7}, {%8,%9}, {%0,%1,%2,%3};"
        : "+f"(d[0]), "+f"(d[1]), "+f"(d[2]), "+f"(d[3])
        : "r"(a[0]), "r"(a[1]), "r"(a[2]), "r"(a[3]), "r"(b[0]), "r"(b[1]));
}

// ---------------------------------------------------------------------------
// Weight prep: HWIO fp32 w[(tap*CIN+ci)*64+co] ->
//   wp[((tap*2+split)*64 + co)*CIN + ci]  (fp16 hi/lo split; hi+lo ~exact)
// ---------------------------------------------------------------------------
__global__ void prep_weights(const float* __restrict__ w, __half* __restrict__ wp,
                             int CIN)
{
    int total = 9 * CIN * 64;
    for (int i = blockIdx.x * 256 + threadIdx.x; i < total; i += gridDim.x * 256) {
        int co  = i % 64;
        int ci  = (i / 64) % CIN;
        int tap = i / (64 * CIN);
        float f = w[i];
        __half h = __float2half_rn(f);
        __half l = __float2half_rn(f - __half2float(h));
        wp[((size_t)(tap * 2 + 0) * 64 + co) * CIN + ci] = h;
        wp[((size_t)(tap * 2 + 1) * 64 + co) * CIN + ci] = l;
    }
}

// ---------------------------------------------------------------------------
// 3x3 SAME conv, CIN -> 64, ReLU, mma.sync fp16x2:
//   acc += a_fp16 * (b_hi + b_lo)   (weights ~exact, activations 1 rounding)
// Block: M = 4 output rows x 32 px (=128), N = 64 co. 8 warps = 4(Mrow) x 2(N).
// A: one 6-row x 34-px fp16 block staged ONCE per block (single plane).
// B: per-ky 3 taps staged, [hi CIN*2 B][lo CIN*2 B][16 B pad] per co row.
// ---------------------------------------------------------------------------
template <int CIN>
__global__ void __launch_bounds__(256, 2)
conv3x3_rows(const float* __restrict__ in, const __half* __restrict__ wp,
             const float* __restrict__ bias, float* __restrict__ out)
{
    constexpr int ADATA  = CIN * 2;          // bytes per A pixel row (single plane)
    constexpr int APITCH = ADATA + 16;       // conv2: 144, conv1: 80
    constexpr int BDATA  = CIN * 2;
    constexpr int BPITCH = 2 * BDATA + 16;   // conv2: 272, conv1: 144
    constexpr int KSTEPS = CIN / 16;

    extern __shared__ char sm[];
    float* bias_s = (float*)sm;              // 256 B
    char*  As = sm + 256;                    // 204 * APITCH
    char*  Bs = As + 204 * APITCH;           // 192 * BPITCH

    const int tid  = threadIdx.x;
    const int lane = tid & 31;
    const int wid  = tid >> 5;
    const int wm   = wid >> 1;        // output row 0..3
    const int wn   = wid & 1;         // co half
    const int x0   = blockIdx.x * 32;
    const int y0   = blockIdx.y * 4;
    const int bz   = blockIdx.z;

    if (tid < 64) bias_s[tid] = bias[tid];

    float acc[2][4][4];
#pragma unroll
    for (int mf = 0; mf < 2; ++mf)
#pragma unroll
        for (int nf = 0; nf < 4; ++nf)
#pragma unroll
            for (int q = 0; q < 4; ++q) acc[mf][nf][q] = 0.f;

    const uint32_t AsU = smem_u32(As);
    const uint32_t BsU = smem_u32(Bs);

    // --- stage A once: 6 input rows (y0-1 .. y0+4) x 34 px, fp32 -> fp16
    {
        const float* ib = in + (size_t)bz * HW * HW * CIN;
        for (int i = tid; i < 204 * (CIN / 4); i += 256) {
            int ci4 = i % (CIN / 4);
            int px  = i / (CIN / 4);
            int irow = px / 34, c = px % 34;
            int gy = y0 - 1 + irow;
            int gx = x0 - 1 + c;
            float4 v = make_float4(0.f, 0.f, 0.f, 0.f);
            if ((unsigned)gy < HW && (unsigned)gx < HW)
                v = *(const float4*)&ib[((size_t)gy * HW + gx) * CIN + ci4 * 4];
            __half2 h0 = __float22half2_rn(make_float2(v.x, v.y));
            __half2 h1 = __float22half2_rn(make_float2(v.z, v.w));
            *(uint2*)(As + px * APITCH + ci4 * 8) =
                make_uint2(*(uint32_t*)&h0, *(uint32_t*)&h1);
        }
    }

    // --- B staging helper (3 taps of row ky, hi/lo interleaved)
    auto stage_B = [&](int ky) {
        constexpr int CH = CIN / 8;             // uint4 chunks per split row
        for (int i = tid; i < 3 * 64 * 2 * CH; i += 256) {
            int c   = i % CH;
            int row = (i / CH) & 63;
            int s   = (i / (CH * 64)) & 1;
            int tap = i / (CH * 64 * 2);
            uint4 v = *(const uint4*)&wp[((size_t)((ky * 3 + tap) * 2 + s) * 64 + row) * CIN + c * 8];
            *(uint4*)(Bs + (tap * 64 + row) * BPITCH + s * BDATA + c * 16) = v;
        }
    };

    stage_B(0);
    __syncthreads();

    const int brow_in = (lane & 7) + ((lane >> 4) & 1) * 8;
    const int bcol    = ((lane >> 3) & 1) * 16;
    const int acol    = (lane >> 4) * 16;
    const int apx     = (lane & 15);

    for (int ky = 0; ky < 3; ++ky) {
#pragma unroll
        for (int kx = 0; kx < 3; ++kx) {
#pragma unroll
            for (int ks = 0; ks < KSTEPS; ++ks) {
                uint32_t a_r[2][4];
#pragma unroll
                for (int mf = 0; mf < 2; ++mf) {
                    int px = (wm + ky) * 34 + mf * 16 + apx + kx;
                    ldm_x4(a_r[mf], AsU + (uint32_t)(px * APITCH + ks * 32 + acol));
                }
                uint32_t b_h[2][4], b_l[2][4];
#pragma unroll
                for (int nh = 0; nh < 2; ++nh) {
                    int row = wn * 32 + nh * 16 + brow_in;
                    uint32_t roff = (uint32_t)((kx * 64 + row) * BPITCH + ks * 32 + bcol);
                    ldm_x4(b_h[nh], BsU + roff);
                    ldm_x4(b_l[nh], BsU + roff + BDATA);
                }
#pragma unroll
                for (int mf = 0; mf < 2; ++mf)
#pragma unroll
                    for (int nf = 0; nf < 4; ++nf) {
                        const uint32_t* bh = &b_h[nf >> 1][(nf & 1) * 2];
                        const uint32_t* bl = &b_l[nf >> 1][(nf & 1) * 2];
                        mma16816(acc[mf][nf], a_r[mf], bh);
                        mma16816(acc[mf][nf], a_r[mf], bl);
                    }
            }
        }
        if (ky < 2) {
            __syncthreads();       // compute done, B free
            stage_B(ky + 1);
            __syncthreads();       // new B ready
        }
    }

    // --- epilogue: bias + relu, NHWC fp32 store
    const int prow  = lane >> 2;
    const int cbase = wn * 32 + 2 * (lane & 3);
    const int gy    = y0 + wm;
#pragma unroll
    for (int mf = 0; mf < 2; ++mf) {
#pragma unroll
        for (int nf = 0; nf < 4; ++nf) {
            int co = cbase + nf * 8;
            float b0 = bias_s[co], b1 = bias_s[co + 1];
            int gx = x0 + mf * 16 + prow;
            float* o0 = out + (((size_t)bz * HW + gy) * HW + gx) * 64 + co;
            float2 v;
            v.x = fmaxf(acc[mf][nf][0] + b0, 0.f);
            v.y = fmaxf(acc[mf][nf][1] + b1, 0.f);
            *(float2*)o0 = v;
            float* o1 = o0 + 8 * 64;                       // gx + 8
            v.x = fmaxf(acc[mf][nf][2] + b0, 0.f);
            v.y = fmaxf(acc[mf][nf][3] + b1, 0.f);
            *(float2*)o1 = v;
        }
    }
}

// ---------------------------------------------------------------------------
// Head: GAP(f4) -> FC chain -> softmax -> pred_cls + argmax cls
// ---------------------------------------------------------------------------
__global__ void head_kernel(const float* __restrict__ f4,
                            const float* __restrict__ Wc1, const float* __restrict__ bc1,
                            const float* __restrict__ Wc2, const float* __restrict__ bc2,
                            const float* __restrict__ Wc3, const float* __restrict__ bc3,
                            float* __restrict__ out_pred)
{
    __shared__ float gap[256];
    __shared__ float z1[128];
    __shared__ float z2[128];
    __shared__ float logits[3];

    const int b = blockIdx.x;
    const int tid = threadIdx.x;

    const float* p = f4 + (size_t)b * 1024 * 256 + tid;
    float s0 = 0.f, s1 = 0.f, s2 = 0.f, s3 = 0.f;
    for (int i = 0; i < 1024; i += 4) {
        s0 += p[(i + 0) * 256];
        s1 += p[(i + 1) * 256];
        s2 += p[(i + 2) * 256];
        s3 += p[(i + 3) * 256];
    }
    gap[tid] = (s0 + s1 + s2 + s3) * (1.0f / 1024.0f);
    __syncthreads();

    if (tid < 128) {
        float a = bc1[tid];
#pragma unroll 8
        for (int k = 0; k < 256; ++k) a = fmaf(gap[k], Wc1[k * 128 + tid], a);
        z1[tid] = fmaxf(a, 0.f);
    }
    __syncthreads();

    if (tid < 128) {
        float a = bc2[tid];
#pragma unroll 8
        for (int k = 0; k < 128; ++k) a = fmaf(z1[k], Wc2[k * 128 + tid], a);
        z2[tid] = fmaxf(a, 0.f);
    }
    __syncthreads();

    if (tid < 3) {
        float a = bc3[tid];
        for (int k = 0; k < 128; ++k) a = fmaf(z2[k], Wc3[k * 3 + tid], a);
        logits[tid] = a;
    }
    __syncthreads();

    if (tid == 0) {
        float l0 = logits[0], l1 = logits[1], l2 = logits[2];
        float m = fmaxf(l0, fmaxf(l1, l2));
        float e0 = expf(l0 - m), e1 = expf(l1 - m), e2 = expf(l2 - m);
        float inv = 1.f / (e0 + e1 + e2);
        out_pred[b * 3 + 0] = e0 * inv;
        out_pred[b * 3 + 1] = e1 * inv;
        out_pred[b * 3 + 2] = e2 * inv;
        int c = 0; float best = l0;
        if (l1 > best) { best = l1; c = 1; }
        if (l2 > best) { best = l2; c = 2; }
        g_cls[b] = c;
    }
}

// ---------------------------------------------------------------------------
// Final convs fused with channel gather (only selected channels computed).
// ---------------------------------------------------------------------------
__global__ void __launch_bounds__(256, 1)
conv3_select(const float* __restrict__ h2o, const float* __restrict__ h2w,
             const float* __restrict__ Wo3, const float* __restrict__ bo3,
             const float* __restrict__ Ww3, const float* __restrict__ bw3,
             float* __restrict__ out)
{
    extern __shared__ float smem[];
    float* ho = smem;                 // 64 * 342  (ci-major, pitch 19)
    float* hw = smem + 64 * 342;
    float* ws = smem + 2 * 64 * 342;  // 576 * 3 selected weights

    const int b   = blockIdx.z;
    const int y0  = blockIdx.y * 16;
    const int x0  = blockIdx.x * 16;
    const int tid = threadIdx.x;
    const int cls = g_cls[b];

    for (int i = tid; i < 576; i += 256) {
        ws[i * 3 + 0] = Wo3[i * 6 + 2 * cls];
        ws[i * 3 + 1] = Wo3[i * 6 + 2 * cls + 1];
        ws[i * 3 + 2] = Ww3[i * 3 + cls];
    }

    const float* po = h2o + (size_t)b * HW * HW * 64;
    const float* pw = h2w + (size_t)b * HW * HW * 64;
    for (int i = tid; i < 324 * 16; i += 256) {
        int ci4 = i & 15;
        int rc  = i >> 4;
        int r = rc / 18, c = rc % 18;
        int gy = y0 + r - 1, gx = x0 + c - 1;
        float4 vo = make_float4(0.f, 0.f, 0.f, 0.f);
        float4 vw = vo;
        if ((unsigned)gy < HW && (unsigned)gx < HW) {
            size_t g = ((size_t)gy * HW + gx) * 64 + ci4 * 4;
            vo = *(const float4*)&po[g];
            vw = *(const float4*)&pw[g];
        }
        int base = r * 19 + c;
        ho[(ci4 * 4 + 0) * 342 + base] = vo.x;
        ho[(ci4 * 4 + 1) * 342 + base] = vo.y;
        ho[(ci4 * 4 + 2) * 342 + base] = vo.z;
        ho[(ci4 * 4 + 3) * 342 + base] = vo.w;
        hw[(ci4 * 4 + 0) * 342 + base] = vw.x;
        hw[(ci4 * 4 + 1) * 342 + base] = vw.y;
        hw[(ci4 * 4 + 2) * 342 + base] = vw.z;
        hw[(ci4 * 4 + 3) * 342 + base] = vw.w;
    }
    __syncthreads();

    const int r = tid >> 4, c = tid & 15;
    float o0 = bo3[2 * cls], o1 = bo3[2 * cls + 1], wv = bw3[cls];

#pragma unroll 1
    for (int ky = 0; ky < 3; ++ky) {
#pragma unroll 1
        for (int kx = 0; kx < 3; ++kx) {
            int base = (r + ky) * 19 + (c + kx);
            const float* wp = &ws[(ky * 3 + kx) * 64 * 3];
#pragma unroll 8
            for (int ci = 0; ci < 64; ++ci) {
                float ao = ho[ci * 342 + base];
                float aw = hw[ci * 342 + base];
                o0 = fmaf(ao, wp[ci * 3 + 0], o0);
                o1 = fmaf(ao, wp[ci * 3 + 1], o1);
                wv = fmaf(aw, wp[ci * 3 + 2], wv);
            }
        }
    }

    int gy = y0 + r, gx = x0 + c;
    size_t pix = ((size_t)b * HW + gy) * HW + gx;
    *(float2*)&out[pix * 2] = make_float2(o0, o1);
    out[(size_t)BATCH * HW * HW * 2 + pix] = wv;
}

// ---------------------------------------------------------------------------
extern "C" void kernel_launch(void* const* d_in, const int* in_sizes, int n_in,
                              void* d_out, int out_size)
{
    (void)in_sizes; (void)n_in; (void)out_size;
    const float* x0  = (const float*)d_in[0];
    const float* f4  = (const float*)d_in[1];
    const float* Wo1 = (const float*)d_in[2];
    const float* bo1 = (const float*)d_in[3];
    const float* Wo2 = (const float*)d_in[4];
    const float* bo2 = (const float*)d_in[5];
    const float* Wo3 = (const float*)d_in[6];
    const float* bo3 = (const float*)d_in[7];
    const float* Ww1 = (const float*)d_in[8];
    const float* bw1 = (const float*)d_in[9];
    const float* Ww2 = (const float*)d_in[10];
    const float* bw2 = (const float*)d_in[11];
    const float* Ww3 = (const float*)d_in[12];
    const float* bw3 = (const float*)d_in[13];
    const float* Wc1 = (const float*)d_in[14];
    const float* bc1 = (const float*)d_in[15];
    const float* Wc2 = (const float*)d_in[16];
    const float* bc2 = (const float*)d_in[17];
    const float* Wc3 = (const float*)d_in[18];
    const float* bc3 = (const float*)d_in[19];
    float* out = (float*)d_out;

    void *pA, *pB, *pC, *pW1o, *pW1w, *pW2o, *pW2w;
    cudaGetSymbolAddress(&pA, g_bufA);
    cudaGetSymbolAddress(&pB, g_bufB);
    cudaGetSymbolAddress(&pC, g_bufC);
    cudaGetSymbolAddress(&pW1o, g_wp1o);
    cudaGetSymbolAddress(&pW1w, g_wp1w);
    cudaGetSymbolAddress(&pW2o, g_wp2o);
    cudaGetSymbolAddress(&pW2w, g_wp2w);

    const size_t smem1 = 256 + (size_t)204 * 80 + (size_t)192 * 144;          //  43.2 KB
    const size_t smem2 = 256 + (size_t)204 * 144 + (size_t)192 * 272;         //  80.0 KB
    const size_t smem3 = (size_t)(2 * 64 * 342 + 576 * 3) * sizeof(float);    // 182.0 KB

    cudaFuncSetAttribute(conv3x3_rows<32>, cudaFuncAttributeMaxDynamicSharedMemorySize, (int)smem1);
    cudaFuncSetAttribute(conv3x3_rows<64>, cudaFuncAttributeMaxDynamicSharedMemorySize, (int)smem2);
    cudaFuncSetAttribute(conv3_select,     cudaFuncAttributeMaxDynamicSharedMemorySize, (int)smem3);

    float* pred = out + (size_t)BATCH * HW * HW * 3;

    head_kernel<<<BATCH, 256>>>(f4, Wc1, bc1, Wc2, bc2, Wc3, bc3, pred);
    prep_weights<<<36, 256>>>(Wo1, (__half*)pW1o, 32);
    prep_weights<<<36, 256>>>(Ww1, (__half*)pW1w, 32);
    prep_weights<<<72, 256>>>(Wo2, (__half*)pW2o, 64);
    prep_weights<<<72, 256>>>(Ww2, (__half*)pW2w, 64);

    dim3 gconv(HW / 32, HW / 4, BATCH);   // 16 x-tiles, 128 row-groups, 4 batches
    conv3x3_rows<32><<<gconv, 256, smem1>>>(x0, (__half*)pW1o, bo1, (float*)pA);
    conv3x3_rows<32><<<gconv, 256, smem1>>>(x0, (__half*)pW1w, bw1, (float*)pB);
    conv3x3_rows<64><<<gconv, 256, smem2>>>((float*)pA, (__half*)pW2o, bo2, (float*)pC);
    conv3x3_rows<64><<<gconv, 256, smem2>>>((float*)pB, (__half*)pW2w, bw2, (float*)pA);

    dim3 g3(HW / 16, HW / 16, BATCH);
    conv3_select<<<g3, 256, smem3>>>((float*)pC, (float*)pA, Wo3, bo3, Ww3, bw3, out);
}

// round 10
// speedup vs baseline: 1.4949x; 1.2265x over previous
#include <cuda_runtime.h>
#include <cuda_fp16.h>
#include <math.h>
#include <stdint.h>

#define BATCH 4
#define HW    512
#define CMID  64

// ---------------------------------------------------------------------------
// Scratch (allocation-free rule: __device__ globals)
// ---------------------------------------------------------------------------
__device__ __align__(256) float  g_bufC[(size_t)BATCH * HW * HW * CMID];  // conv2 offsets out
__device__ __align__(256) float  g_bufD[(size_t)BATCH * HW * HW * CMID];  // conv2 weights out
__device__ __align__(256) __half g_h1o[(size_t)BATCH * HW * HW * CMID];   // conv1 offsets out (fp16)
__device__ __align__(256) __half g_h1w[(size_t)BATCH * HW * HW * CMID];   // conv1 weights out (fp16)
__device__ __align__(256) __half g_wp1o[9 * 2 * 64 * 32];
__device__ __align__(256) __half g_wp1w[9 * 2 * 64 * 32];
__device__ __align__(256) __half g_wp2o[9 * 2 * 64 * 64];
__device__ __align__(256) __half g_wp2w[9 * 2 * 64 * 64];
__device__ int g_cls[BATCH];

__device__ __forceinline__ uint32_t smem_u32(const void* p) {
    uint32_t a;
    asm("{ .reg .u64 t; cvta.to.shared.u64 t, %1; cvt.u32.u64 %0, t; }"
        : "=r"(a) : "l"(p));
    return a;
}
__device__ __forceinline__ void ldm_x4(uint32_t* r, uint32_t addr) {
    asm volatile("ldmatrix.sync.aligned.m8n8.x4.shared.b16 {%0,%1,%2,%3}, [%4];"
                 : "=r"(r[0]), "=r"(r[1]), "=r"(r[2]), "=r"(r[3]) : "r"(addr));
}
__device__ __forceinline__ void mma16816(float* d, const uint32_t* a, const uint32_t* b) {
    asm volatile(
        "mma.sync.aligned.m16n8k16.row.col.f32.f16.f16.f32 "
        "{%0,%1,%2,%3}, {%4,%5,%6,%7}, {%8,%9}, {%0,%1,%2,%3};"
        : "+f"(d[0]), "+f"(d[1]), "+f"(d[2]), "+f"(d[3])
        : "r"(a[0]), "r"(a[1]), "r"(a[2]), "r"(a[3]), "r"(b[0]), "r"(b[1]));
}
// 16B async copy; src_sz = 16 (copy) or 0 (zero-fill 16B)
__device__ __forceinline__ void cp16(uint32_t dst, const void* src, int src_sz) {
    asm volatile("cp.async.ca.shared.global [%0], [%1], 16, %2;"
                 :: "r"(dst), "l"(src), "r"(src_sz) : "memory");
}
__device__ __forceinline__ void cp_commit_wait() {
    asm volatile("cp.async.commit_group;" ::: "memory");
    asm volatile("cp.async.wait_group 0;" ::: "memory");
}

// ---------------------------------------------------------------------------
// Weight prep: HWIO fp32 w[(tap*CIN+ci)*64+co] ->
//   wp[((tap*2+split)*64 + co)*CIN + ci]  (fp16 hi/lo split; hi+lo ~exact)
// ---------------------------------------------------------------------------
__global__ void prep_weights(const float* __restrict__ w, __half* __restrict__ wp,
                             int CIN)
{
    int total = 9 * CIN * 64;
    for (int i = blockIdx.x * 256 + threadIdx.x; i < total; i += gridDim.x * 256) {
        int co  = i % 64;
        int ci  = (i / 64) % CIN;
        int tap = i / (64 * CIN);
        float f = w[i];
        __half h = __float2half_rn(f);
        __half l = __float2half_rn(f - __half2float(h));
        wp[((size_t)(tap * 2 + 0) * 64 + co) * CIN + ci] = h;
        wp[((size_t)(tap * 2 + 1) * 64 + co) * CIN + ci] = l;
    }
}

// ---------------------------------------------------------------------------
// 3x3 SAME conv, CIN -> 64, ReLU, mma.sync fp16x2:
//   acc += a_fp16 * (b_hi + b_lo)
// Block: M = 4 output rows x 32 px (=128), N = 64 co. 8 warps = 4(Mrow) x 2(N).
// HALF_IN : input is fp16 NHWC -> A staging = pure cp.async copies.
// HALF_OUT: output fp16 NHWC (values identical to rounding fp32 out to fp16).
// ---------------------------------------------------------------------------
template <int CIN, bool HALF_IN, bool HALF_OUT>
__global__ void __launch_bounds__(256, 2)
conv3x3_rows(const void* __restrict__ in, const __half* __restrict__ wp,
             const float* __restrict__ bias, float* __restrict__ outf,
             __half* __restrict__ outh)
{
    constexpr int ADATA  = CIN * 2;          // bytes per A pixel row
    constexpr int APITCH = ADATA + 16;       // conv2: 144, conv1: 80
    constexpr int BDATA  = CIN * 2;
    constexpr int BPITCH = 2 * BDATA + 16;   // conv2: 272, conv1: 144
    constexpr int KSTEPS = CIN / 16;

    extern __shared__ char sm[];
    float* bias_s = (float*)sm;              // 256 B
    char*  As = sm + 256;                    // 204 * APITCH
    char*  Bs = As + 204 * APITCH;           // 192 * BPITCH

    const int tid  = threadIdx.x;
    const int lane = tid & 31;
    const int wid  = tid >> 5;
    const int wm   = wid >> 1;        // output row 0..3
    const int wn   = wid & 1;         // co half
    const int x0   = blockIdx.x * 32;
    const int y0   = blockIdx.y * 4;
    const int bz   = blockIdx.z;

    if (tid < 64) bias_s[tid] = bias[tid];

    float acc[2][4][4];
#pragma unroll
    for (int mf = 0; mf < 2; ++mf)
#pragma unroll
        for (int nf = 0; nf < 4; ++nf)
#pragma unroll
            for (int q = 0; q < 4; ++q) acc[mf][nf][q] = 0.f;

    const uint32_t AsU = smem_u32(As);
    const uint32_t BsU = smem_u32(Bs);

    // --- stage A once: 6 input rows (y0-1 .. y0+4) x 34 px
    if (HALF_IN) {
        // pure 16B async copies from fp16 NHWC
        const __half* ib = (const __half*)in + (size_t)bz * HW * HW * CIN;
        constexpr int CH = CIN / 8;          // 16B chunks per pixel
        for (int i = tid; i < 204 * CH; i += 256) {
            int c   = i % CH;
            int px  = i / CH;
            int irow = px / 34, col = px % 34;
            int gy = y0 - 1 + irow;
            int gx = x0 - 1 + col;
            bool ok = (unsigned)gy < HW && (unsigned)gx < HW;
            int cgy = ok ? gy : 0, cgx = ok ? gx : 0;
            cp16(AsU + px * APITCH + c * 16,
                 ib + ((size_t)cgy * HW + cgx) * CIN + c * 8, ok ? 16 : 0);
        }
    } else {
        // fp32 load + convert + STS
        const float* ib = (const float*)in + (size_t)bz * HW * HW * CIN;
        for (int i = tid; i < 204 * (CIN / 4); i += 256) {
            int ci4 = i % (CIN / 4);
            int px  = i / (CIN / 4);
            int irow = px / 34, c = px % 34;
            int gy = y0 - 1 + irow;
            int gx = x0 - 1 + c;
            float4 v = make_float4(0.f, 0.f, 0.f, 0.f);
            if ((unsigned)gy < HW && (unsigned)gx < HW)
                v = *(const float4*)&ib[((size_t)gy * HW + gx) * CIN + ci4 * 4];
            __half2 h0 = __float22half2_rn(make_float2(v.x, v.y));
            __half2 h1 = __float22half2_rn(make_float2(v.z, v.w));
            *(uint2*)(As + px * APITCH + ci4 * 8) =
                make_uint2(*(uint32_t*)&h0, *(uint32_t*)&h1);
        }
    }

    // --- B staging (3 taps of row ky, hi/lo interleaved) via cp.async
    auto stage_B = [&](int ky) {
        constexpr int CH = CIN / 8;             // uint4 chunks per split row
        for (int i = tid; i < 3 * 64 * 2 * CH; i += 256) {
            int c   = i % CH;
            int row = (i / CH) & 63;
            int s   = (i / (CH * 64)) & 1;
            int tap = i / (CH * 64 * 2);
            cp16(BsU + (tap * 64 + row) * BPITCH + s * BDATA + c * 16,
                 wp + ((size_t)((ky * 3 + tap) * 2 + s) * 64 + row) * CIN + c * 8, 16);
        }
    };

    stage_B(0);
    cp_commit_wait();
    __syncthreads();

    const int brow_in = (lane & 7) + ((lane >> 4) & 1) * 8;
    const int bcol    = ((lane >> 3) & 1) * 16;
    const int acol    = (lane >> 4) * 16;
    const int apx     = (lane & 15);

    for (int ky = 0; ky < 3; ++ky) {
#pragma unroll
        for (int kx = 0; kx < 3; ++kx) {
#pragma unroll
            for (int ks = 0; ks < KSTEPS; ++ks) {
                uint32_t a_r[2][4];
#pragma unroll
                for (int mf = 0; mf < 2; ++mf) {
                    int px = (wm + ky) * 34 + mf * 16 + apx + kx;
                    ldm_x4(a_r[mf], AsU + (uint32_t)(px * APITCH + ks * 32 + acol));
                }
                uint32_t b_h[2][4], b_l[2][4];
#pragma unroll
                for (int nh = 0; nh < 2; ++nh) {
                    int row = wn * 32 + nh * 16 + brow_in;
                    uint32_t roff = (uint32_t)((kx * 64 + row) * BPITCH + ks * 32 + bcol);
                    ldm_x4(b_h[nh], BsU + roff);
                    ldm_x4(b_l[nh], BsU + roff + BDATA);
                }
#pragma unroll
                for (int mf = 0; mf < 2; ++mf)
#pragma unroll
                    for (int nf = 0; nf < 4; ++nf) {
                        const uint32_t* bh = &b_h[nf >> 1][(nf & 1) * 2];
                        const uint32_t* bl = &b_l[nf >> 1][(nf & 1) * 2];
                        mma16816(acc[mf][nf], a_r[mf], bh);
                        mma16816(acc[mf][nf], a_r[mf], bl);
                    }
            }
        }
        if (ky < 2) {
            __syncthreads();       // compute done, B free
            stage_B(ky + 1);
            cp_commit_wait();
            __syncthreads();       // new B ready
        }
    }

    // --- epilogue: bias + relu
    const int prow  = lane >> 2;
    const int cbase = wn * 32 + 2 * (lane & 3);
    const int gy    = y0 + wm;
#pragma unroll
    for (int mf = 0; mf < 2; ++mf) {
#pragma unroll
        for (int nf = 0; nf < 4; ++nf) {
            int co = cbase + nf * 8;
            float b0 = bias_s[co], b1 = bias_s[co + 1];
            int gx = x0 + mf * 16 + prow;
            size_t o0 = (((size_t)bz * HW + gy) * HW + gx) * 64 + co;
            float f0 = fmaxf(acc[mf][nf][0] + b0, 0.f);
            float f1 = fmaxf(acc[mf][nf][1] + b1, 0.f);
            float f2 = fmaxf(acc[mf][nf][2] + b0, 0.f);
            float f3 = fmaxf(acc[mf][nf][3] + b1, 0.f);
            if (HALF_OUT) {
                __half2 v0 = __float22half2_rn(make_float2(f0, f1));
                __half2 v1 = __float22half2_rn(make_float2(f2, f3));
                *(uint32_t*)&outh[o0]           = *(uint32_t*)&v0;
                *(uint32_t*)&outh[o0 + 8 * 64]  = *(uint32_t*)&v1;   // gx + 8
            } else {
                *(float2*)&outf[o0]          = make_float2(f0, f1);
                *(float2*)&outf[o0 + 8 * 64] = make_float2(f2, f3);
            }
        }
    }
}

// ---------------------------------------------------------------------------
// Head: GAP(f4) -> FC chain -> softmax -> pred_cls + argmax cls
// ---------------------------------------------------------------------------
__global__ void head_kernel(const float* __restrict__ f4,
                            const float* __restrict__ Wc1, const float* __restrict__ bc1,
                            const float* __restrict__ Wc2, const float* __restrict__ bc2,
                            const float* __restrict__ Wc3, const float* __restrict__ bc3,
                            float* __restrict__ out_pred)
{
    __shared__ float gap[256];
    __shared__ float z1[128];
    __shared__ float z2[128];
    __shared__ float logits[3];

    const int b = blockIdx.x;
    const int tid = threadIdx.x;

    const float* p = f4 + (size_t)b * 1024 * 256 + tid;
    float s0 = 0.f, s1 = 0.f, s2 = 0.f, s3 = 0.f;
    for (int i = 0; i < 1024; i += 4) {
        s0 += p[(i + 0) * 256];
        s1 += p[(i + 1) * 256];
        s2 += p[(i + 2) * 256];
        s3 += p[(i + 3) * 256];
    }
    gap[tid] = (s0 + s1 + s2 + s3) * (1.0f / 1024.0f);
    __syncthreads();

    if (tid < 128) {
        float a = bc1[tid];
#pragma unroll 8
        for (int k = 0; k < 256; ++k) a = fmaf(gap[k], Wc1[k * 128 + tid], a);
        z1[tid] = fmaxf(a, 0.f);
    }
    __syncthreads();

    if (tid < 128) {
        float a = bc2[tid];
#pragma unroll 8
        for (int k = 0; k < 128; ++k) a = fmaf(z1[k], Wc2[k * 128 + tid], a);
        z2[tid] = fmaxf(a, 0.f);
    }
    __syncthreads();

    if (tid < 3) {
        float a = bc3[tid];
        for (int k = 0; k < 128; ++k) a = fmaf(z2[k], Wc3[k * 3 + tid], a);
        logits[tid] = a;
    }
    __syncthreads();

    if (tid == 0) {
        float l0 = logits[0], l1 = logits[1], l2 = logits[2];
        float m = fmaxf(l0, fmaxf(l1, l2));
        float e0 = expf(l0 - m), e1 = expf(l1 - m), e2 = expf(l2 - m);
        float inv = 1.f / (e0 + e1 + e2);
        out_pred[b * 3 + 0] = e0 * inv;
        out_pred[b * 3 + 1] = e1 * inv;
        out_pred[b * 3 + 2] = e2 * inv;
        int c = 0; float best = l0;
        if (l1 > best) { best = l1; c = 1; }
        if (l2 > best) { best = l2; c = 2; }
        g_cls[b] = c;
    }
}

// ---------------------------------------------------------------------------
// Final convs fused with channel gather (only selected channels computed).
// ---------------------------------------------------------------------------
__global__ void __launch_bounds__(256, 1)
conv3_select(const float* __restrict__ h2o, const float* __restrict__ h2w,
             const float* __restrict__ Wo3, const float* __restrict__ bo3,
             const float* __restrict__ Ww3, const float* __restrict__ bw3,
             float* __restrict__ out)
{
    extern __shared__ float smem[];
    float* ho = smem;                 // 64 * 342  (ci-major, pitch 19)
    float* hw = smem + 64 * 342;
    float* ws = smem + 2 * 64 * 342;  // 576 * 3 selected weights

    const int b   = blockIdx.z;
    const int y0  = blockIdx.y * 16;
    const int x0  = blockIdx.x * 16;
    const int tid = threadIdx.x;
    const int cls = g_cls[b];

    for (int i = tid; i < 576; i += 256) {
        ws[i * 3 + 0] = Wo3[i * 6 + 2 * cls];
        ws[i * 3 + 1] = Wo3[i * 6 + 2 * cls + 1];
        ws[i * 3 + 2] = Ww3[i * 3 + cls];
    }

    const float* po = h2o + (size_t)b * HW * HW * 64;
    const float* pw = h2w + (size_t)b * HW * HW * 64;
    for (int i = tid; i < 324 * 16; i += 256) {
        int ci4 = i & 15;
        int rc  = i >> 4;
        int r = rc / 18, c = rc % 18;
        int gy = y0 + r - 1, gx = x0 + c - 1;
        float4 vo = make_float4(0.f, 0.f, 0.f, 0.f);
        float4 vw = vo;
        if ((unsigned)gy < HW && (unsigned)gx < HW) {
            size_t g = ((size_t)gy * HW + gx) * 64 + ci4 * 4;
            vo = *(const float4*)&po[g];
            vw = *(const float4*)&pw[g];
        }
        int base = r * 19 + c;
        ho[(ci4 * 4 + 0) * 342 + base] = vo.x;
        ho[(ci4 * 4 + 1) * 342 + base] = vo.y;
        ho[(ci4 * 4 + 2) * 342 + base] = vo.z;
        ho[(ci4 * 4 + 3) * 342 + base] = vo.w;
        hw[(ci4 * 4 + 0) * 342 + base] = vw.x;
        hw[(ci4 * 4 + 1) * 342 + base] = vw.y;
        hw[(ci4 * 4 + 2) * 342 + base] = vw.z;
        hw[(ci4 * 4 + 3) * 342 + base] = vw.w;
    }
    __syncthreads();

    const int r = tid >> 4, c = tid & 15;
    float o0 = bo3[2 * cls], o1 = bo3[2 * cls + 1], wv = bw3[cls];

#pragma unroll 1
    for (int ky = 0; ky < 3; ++ky) {
#pragma unroll 1
        for (int kx = 0; kx < 3; ++kx) {
            int base = (r + ky) * 19 + (c + kx);
            const float* wp = &ws[(ky * 3 + kx) * 64 * 3];
#pragma unroll 8
            for (int ci = 0; ci < 64; ++ci) {
                float ao = ho[ci * 342 + base];
                float aw = hw[ci * 342 + base];
                o0 = fmaf(ao, wp[ci * 3 + 0], o0);
                o1 = fmaf(ao, wp[ci * 3 + 1], o1);
                wv = fmaf(aw, wp[ci * 3 + 2], wv);
            }
        }
    }

    int gy = y0 + r, gx = x0 + c;
    size_t pix = ((size_t)b * HW + gy) * HW + gx;
    *(float2*)&out[pix * 2] = make_float2(o0, o1);
    out[(size_t)BATCH * HW * HW * 2 + pix] = wv;
}

// ---------------------------------------------------------------------------
extern "C" void kernel_launch(void* const* d_in, const int* in_sizes, int n_in,
                              void* d_out, int out_size)
{
    (void)in_sizes; (void)n_in; (void)out_size;
    const float* x0  = (const float*)d_in[0];
    const float* f4  = (const float*)d_in[1];
    const float* Wo1 = (const float*)d_in[2];
    const float* bo1 = (const float*)d_in[3];
    const float* Wo2 = (const float*)d_in[4];
    const float* bo2 = (const float*)d_in[5];
    const float* Wo3 = (const float*)d_in[6];
    const float* bo3 = (const float*)d_in[7];
    const float* Ww1 = (const float*)d_in[8];
    const float* bw1 = (const float*)d_in[9];
    const float* Ww2 = (const float*)d_in[10];
    const float* bw2 = (const float*)d_in[11];
    const float* Ww3 = (const float*)d_in[12];
    const float* bw3 = (const float*)d_in[13];
    const float* Wc1 = (const float*)d_in[14];
    const float* bc1 = (const float*)d_in[15];
    const float* Wc2 = (const float*)d_in[16];
    const float* bc2 = (const float*)d_in[17];
    const float* Wc3 = (const float*)d_in[18];
    const float* bc3 = (const float*)d_in[19];
    float* out = (float*)d_out;

    void *pC, *pD, *pHo, *pHw, *pW1o, *pW1w, *pW2o, *pW2w;
    cudaGetSymbolAddress(&pC, g_bufC);
    cudaGetSymbolAddress(&pD, g_bufD);
    cudaGetSymbolAddress(&pHo, g_h1o);
    cudaGetSymbolAddress(&pHw, g_h1w);
    cudaGetSymbolAddress(&pW1o, g_wp1o);
    cudaGetSymbolAddress(&pW1w, g_wp1w);
    cudaGetSymbolAddress(&pW2o, g_wp2o);
    cudaGetSymbolAddress(&pW2w, g_wp2w);

    const size_t smem1 = 256 + (size_t)204 * 80 + (size_t)192 * 144;          //  43.2 KB
    const size_t smem2 = 256 + (size_t)204 * 144 + (size_t)192 * 272;         //  80.0 KB
    const size_t smem3 = (size_t)(2 * 64 * 342 + 576 * 3) * sizeof(float);    // 182.0 KB

    cudaFuncSetAttribute((const void*)conv3x3_rows<32, false, true>,
                         cudaFuncAttributeMaxDynamicSharedMemorySize, (int)smem1);
    cudaFuncSetAttribute((const void*)conv3x3_rows<64, true, false>,
                         cudaFuncAttributeMaxDynamicSharedMemorySize, (int)smem2);
    cudaFuncSetAttribute((const void*)conv3_select,
                         cudaFuncAttributeMaxDynamicSharedMemorySize, (int)smem3);

    float* pred = out + (size_t)BATCH * HW * HW * 3;

    head_kernel<<<BATCH, 256>>>(f4, Wc1, bc1, Wc2, bc2, Wc3, bc3, pred);
    prep_weights<<<36, 256>>>(Wo1, (__half*)pW1o, 32);
    prep_weights<<<36, 256>>>(Ww1, (__half*)pW1w, 32);
    prep_weights<<<72, 256>>>(Wo2, (__half*)pW2o, 64);
    prep_weights<<<72, 256>>>(Ww2, (__half*)pW2w, 64);

    dim3 gconv(HW / 32, HW / 4, BATCH);   // 16 x-tiles, 128 row-groups, 4 batches
    conv3x3_rows<32, false, true><<<gconv, 256, smem1>>>(
        x0, (__half*)pW1o, bo1, nullptr, (__half*)pHo);
    conv3x3_rows<32, false, true><<<gconv, 256, smem1>>>(
        x0, (__half*)pW1w, bw1, nullptr, (__half*)pHw);
    conv3x3_rows<64, true, false><<<gconv, 256, smem2>>>(
        (__half*)pHo, (__half*)pW2o, bo2, (float*)pC, nullptr);
    conv3x3_rows<64, true, false><<<gconv, 256, smem2>>>(
        (__half*)pHw, (__half*)pW2w, bw2, (float*)pD, nullptr);

    dim3 g3(HW / 16, HW / 16, BATCH);
    conv3_select<<<g3, 256, smem3>>>((float*)pC, (float*)pD, Wo3, bo3, Ww3, bw3, out);
}

// round 11
// speedup vs baseline: 1.8705x; 1.2512x over previous
#include <cuda_runtime.h>
#include <cuda_fp16.h>
#include <math.h>
#include <stdint.h>

#define BATCH 4
#define HW    512
#define CMID  64

// ---------------------------------------------------------------------------
// Scratch (allocation-free rule: __device__ globals)
// ---------------------------------------------------------------------------
__device__ __align__(256) float  g_bufC[(size_t)BATCH * HW * HW * CMID];  // conv2 offsets out
__device__ __align__(256) float  g_bufD[(size_t)BATCH * HW * HW * CMID];  // conv2 weights out
__device__ __align__(256) __half g_h1o[(size_t)BATCH * HW * HW * CMID];   // conv1 offsets out (fp16)
__device__ __align__(256) __half g_h1w[(size_t)BATCH * HW * HW * CMID];   // conv1 weights out (fp16)
__device__ __align__(256) __half g_wp1o[9 * 64 * 32];
__device__ __align__(256) __half g_wp1w[9 * 64 * 32];
__device__ __align__(256) __half g_wp2o[9 * 64 * 64];
__device__ __align__(256) __half g_wp2w[9 * 64 * 64];
__device__ int g_cls[BATCH];

__device__ __forceinline__ uint32_t smem_u32(const void* p) {
    uint32_t a;
    asm("{ .reg .u64 t; cvta.to.shared.u64 t, %1; cvt.u32.u64 %0, t; }"
        : "=r"(a) : "l"(p));
    return a;
}
__device__ __forceinline__ void ldm_x4(uint32_t* r, uint32_t addr) {
    asm volatile("ldmatrix.sync.aligned.m8n8.x4.shared.b16 {%0,%1,%2,%3}, [%4];"
                 : "=r"(r[0]), "=r"(r[1]), "=r"(r[2]), "=r"(r[3]) : "r"(addr));
}
__device__ __forceinline__ void mma16816(float* d, const uint32_t* a, const uint32_t* b) {
    asm volatile(
        "mma.sync.aligned.m16n8k16.row.col.f32.f16.f16.f32 "
        "{%0,%1,%2,%3}, {%4,%5,%6,%7}, {%8,%9}, {%0,%1,%2,%3};"
        : "+f"(d[0]), "+f"(d[1]), "+f"(d[2]), "+f"(d[3])
        : "r"(a[0]), "r"(a[1]), "r"(a[2]), "r"(a[3]), "r"(b[0]), "r"(b[1]));
}
// 16B async copy; src_sz = 16 (copy) or 0 (zero-fill 16B)
__device__ __forceinline__ void cp16(uint32_t dst, const void* src, int src_sz) {
    asm volatile("cp.async.ca.shared.global [%0], [%1], 16, %2;"
                 :: "r"(dst), "l"(src), "r"(src_sz) : "memory");
}
__device__ __forceinline__ void cp_commit_wait() {
    asm volatile("cp.async.commit_group;" ::: "memory");
    asm volatile("cp.async.wait_group 0;" ::: "memory");
}

// ---------------------------------------------------------------------------
// Weight prep: HWIO fp32 w[(tap*CIN+ci)*64+co] -> wp[(tap*64 + co)*CIN + ci]
// single fp16 plane (RN)
// ---------------------------------------------------------------------------
__global__ void prep_weights(const float* __restrict__ w, __half* __restrict__ wp,
                             int CIN)
{
    int total = 9 * CIN * 64;
    for (int i = blockIdx.x * 256 + threadIdx.x; i < total; i += gridDim.x * 256) {
        int co  = i % 64;
        int ci  = (i / 64) % CIN;
        int tap = i / (64 * CIN);
        wp[((size_t)tap * 64 + co) * CIN + ci] = __float2half_rn(w[i]);
    }
}

// ---------------------------------------------------------------------------
// 3x3 SAME conv, CIN -> 64, ReLU, full-fp16 mma.sync (fp32 accum).
// Block: M = 4 output rows x 32 px (=128), N = 64 co. 8 warps = 4(Mrow) x 2(N).
// HALF_IN : input is fp16 NHWC -> A staging = pure cp.async copies.
// HALF_OUT: output fp16 NHWC.
// ---------------------------------------------------------------------------
template <int CIN, bool HALF_IN, bool HALF_OUT>
__global__ void __launch_bounds__(256, 2)
conv3x3_rows(const void* __restrict__ in, const __half* __restrict__ wp,
             const float* __restrict__ bias, float* __restrict__ outf,
             __half* __restrict__ outh)
{
    constexpr int ADATA  = CIN * 2;          // bytes per A pixel row
    constexpr int APITCH = ADATA + 16;       // conv2: 144, conv1: 80
    constexpr int BPITCH = CIN * 2 + 16;     // single plane
    constexpr int KSTEPS = CIN / 16;

    extern __shared__ char sm[];
    float* bias_s = (float*)sm;              // 256 B
    char*  As = sm + 256;                    // 204 * APITCH
    char*  Bs = As + 204 * APITCH;           // 192 * BPITCH

    const int tid  = threadIdx.x;
    const int lane = tid & 31;
    const int wid  = tid >> 5;
    const int wm   = wid >> 1;        // output row 0..3
    const int wn   = wid & 1;         // co half
    const int x0   = blockIdx.x * 32;
    const int y0   = blockIdx.y * 4;
    const int bz   = blockIdx.z;

    if (tid < 64) bias_s[tid] = bias[tid];

    float acc[2][4][4];
#pragma unroll
    for (int mf = 0; mf < 2; ++mf)
#pragma unroll
        for (int nf = 0; nf < 4; ++nf)
#pragma unroll
            for (int q = 0; q < 4; ++q) acc[mf][nf][q] = 0.f;

    const uint32_t AsU = smem_u32(As);
    const uint32_t BsU = smem_u32(Bs);

    // --- stage A once: 6 input rows (y0-1 .. y0+4) x 34 px
    if (HALF_IN) {
        const __half* ib = (const __half*)in + (size_t)bz * HW * HW * CIN;
        constexpr int CH = CIN / 8;          // 16B chunks per pixel
        for (int i = tid; i < 204 * CH; i += 256) {
            int c   = i % CH;
            int px  = i / CH;
            int irow = px / 34, col = px % 34;
            int gy = y0 - 1 + irow;
            int gx = x0 - 1 + col;
            bool ok = (unsigned)gy < HW && (unsigned)gx < HW;
            int cgy = ok ? gy : 0, cgx = ok ? gx : 0;
            cp16(AsU + px * APITCH + c * 16,
                 ib + ((size_t)cgy * HW + cgx) * CIN + c * 8, ok ? 16 : 0);
        }
    } else {
        const float* ib = (const float*)in + (size_t)bz * HW * HW * CIN;
        for (int i = tid; i < 204 * (CIN / 4); i += 256) {
            int ci4 = i % (CIN / 4);
            int px  = i / (CIN / 4);
            int irow = px / 34, c = px % 34;
            int gy = y0 - 1 + irow;
            int gx = x0 - 1 + c;
            float4 v = make_float4(0.f, 0.f, 0.f, 0.f);
            if ((unsigned)gy < HW && (unsigned)gx < HW)
                v = *(const float4*)&ib[((size_t)gy * HW + gx) * CIN + ci4 * 4];
            __half2 h0 = __float22half2_rn(make_float2(v.x, v.y));
            __half2 h1 = __float22half2_rn(make_float2(v.z, v.w));
            *(uint2*)(As + px * APITCH + ci4 * 8) =
                make_uint2(*(uint32_t*)&h0, *(uint32_t*)&h1);
        }
    }

    // --- B staging (3 taps of row ky, single plane) via cp.async
    auto stage_B = [&](int ky) {
        constexpr int CH = CIN / 8;             // uint4 chunks per row
        for (int i = tid; i < 3 * 64 * CH; i += 256) {
            int c   = i % CH;
            int row = (i / CH) & 63;
            int tap = i / (CH * 64);
            cp16(BsU + (tap * 64 + row) * BPITCH + c * 16,
                 wp + ((size_t)(ky * 3 + tap) * 64 + row) * CIN + c * 8, 16);
        }
    };

    stage_B(0);
    cp_commit_wait();
    __syncthreads();

    const int brow_in = (lane & 7) + ((lane >> 4) & 1) * 8;
    const int bcol    = ((lane >> 3) & 1) * 16;
    const int acol    = (lane >> 4) * 16;
    const int apx     = (lane & 15);

    for (int ky = 0; ky < 3; ++ky) {
#pragma unroll
        for (int kx = 0; kx < 3; ++kx) {
#pragma unroll
            for (int ks = 0; ks < KSTEPS; ++ks) {
                uint32_t a_r[2][4];
#pragma unroll
                for (int mf = 0; mf < 2; ++mf) {
                    int px = (wm + ky) * 34 + mf * 16 + apx + kx;
                    ldm_x4(a_r[mf], AsU + (uint32_t)(px * APITCH + ks * 32 + acol));
                }
                uint32_t b_r[2][4];
#pragma unroll
                for (int nh = 0; nh < 2; ++nh) {
                    int row = wn * 32 + nh * 16 + brow_in;
                    ldm_x4(b_r[nh], BsU + (uint32_t)((kx * 64 + row) * BPITCH + ks * 32 + bcol));
                }
#pragma unroll
                for (int mf = 0; mf < 2; ++mf)
#pragma unroll
                    for (int nf = 0; nf < 4; ++nf)
                        mma16816(acc[mf][nf], a_r[mf], &b_r[nf >> 1][(nf & 1) * 2]);
            }
        }
        if (ky < 2) {
            __syncthreads();       // compute done, B free
            stage_B(ky + 1);
            cp_commit_wait();
            __syncthreads();       // new B ready
        }
    }

    // --- epilogue: bias + relu
    const int prow  = lane >> 2;
    const int cbase = wn * 32 + 2 * (lane & 3);
    const int gy    = y0 + wm;
#pragma unroll
    for (int mf = 0; mf < 2; ++mf) {
#pragma unroll
        for (int nf = 0; nf < 4; ++nf) {
            int co = cbase + nf * 8;
            float b0 = bias_s[co], b1 = bias_s[co + 1];
            int gx = x0 + mf * 16 + prow;
            size_t o0 = (((size_t)bz * HW + gy) * HW + gx) * 64 + co;
            float f0 = fmaxf(acc[mf][nf][0] + b0, 0.f);
            float f1 = fmaxf(acc[mf][nf][1] + b1, 0.f);
            float f2 = fmaxf(acc[mf][nf][2] + b0, 0.f);
            float f3 = fmaxf(acc[mf][nf][3] + b1, 0.f);
            if (HALF_OUT) {
                __half2 v0 = __float22half2_rn(make_float2(f0, f1));
                __half2 v1 = __float22half2_rn(make_float2(f2, f3));
                *(uint32_t*)&outh[o0]           = *(uint32_t*)&v0;
                *(uint32_t*)&outh[o0 + 8 * 64]  = *(uint32_t*)&v1;   // gx + 8
            } else {
                *(float2*)&outf[o0]          = make_float2(f0, f1);
                *(float2*)&outf[o0 + 8 * 64] = make_float2(f2, f3);
            }
        }
    }
}

// ---------------------------------------------------------------------------
// Head: GAP(f4) -> FC chain -> softmax -> pred_cls + argmax cls
// ---------------------------------------------------------------------------
__global__ void head_kernel(const float* __restrict__ f4,
                            const float* __restrict__ Wc1, const float* __restrict__ bc1,
                            const float* __restrict__ Wc2, const float* __restrict__ bc2,
                            const float* __restrict__ Wc3, const float* __restrict__ bc3,
                            float* __restrict__ out_pred)
{
    __shared__ float gap[256];
    __shared__ float z1[128];
    __shared__ float z2[128];
    __shared__ float logits[3];

    const int b = blockIdx.x;
    const int tid = threadIdx.x;

    const float* p = f4 + (size_t)b * 1024 * 256 + tid;
    float s0 = 0.f, s1 = 0.f, s2 = 0.f, s3 = 0.f;
    for (int i = 0; i < 1024; i += 4) {
        s0 += p[(i + 0) * 256];
        s1 += p[(i + 1) * 256];
        s2 += p[(i + 2) * 256];
        s3 += p[(i + 3) * 256];
    }
    gap[tid] = (s0 + s1 + s2 + s3) * (1.0f / 1024.0f);
    __syncthreads();

    if (tid < 128) {
        float a = bc1[tid];
#pragma unroll 8
        for (int k = 0; k < 256; ++k) a = fmaf(gap[k], Wc1[k * 128 + tid], a);
        z1[tid] = fmaxf(a, 0.f);
    }
    __syncthreads();

    if (tid < 128) {
        float a = bc2[tid];
#pragma unroll 8
        for (int k = 0; k < 128; ++k) a = fmaf(z1[k], Wc2[k * 128 + tid], a);
        z2[tid] = fmaxf(a, 0.f);
    }
    __syncthreads();

    if (tid < 3) {
        float a = bc3[tid];
        for (int k = 0; k < 128; ++k) a = fmaf(z2[k], Wc3[k * 3 + tid], a);
        logits[tid] = a;
    }
    __syncthreads();

    if (tid == 0) {
        float l0 = logits[0], l1 = logits[1], l2 = logits[2];
        float m = fmaxf(l0, fmaxf(l1, l2));
        float e0 = expf(l0 - m), e1 = expf(l1 - m), e2 = expf(l2 - m);
        float inv = 1.f / (e0 + e1 + e2);
        out_pred[b * 3 + 0] = e0 * inv;
        out_pred[b * 3 + 1] = e1 * inv;
        out_pred[b * 3 + 2] = e2 * inv;
        int c = 0; float best = l0;
        if (l1 > best) { best = l1; c = 1; }
        if (l2 > best) { best = l2; c = 2; }
        g_cls[b] = c;
    }
}

// ---------------------------------------------------------------------------
// Final convs fused with channel gather (only selected channels computed).
// ---------------------------------------------------------------------------
__global__ void __launch_bounds__(256, 1)
conv3_select(const float* __restrict__ h2o, const float* __restrict__ h2w,
             const float* __restrict__ Wo3, const float* __restrict__ bo3,
             const float* __restrict__ Ww3, const float* __restrict__ bw3,
             float* __restrict__ out)
{
    extern __shared__ float smem[];
    float* ho = smem;                 // 64 * 342  (ci-major, pitch 19)
    float* hw = smem + 64 * 342;
    float* ws = smem + 2 * 64 * 342;  // 576 * 3 selected weights

    const int b   = blockIdx.z;
    const int y0  = blockIdx.y * 16;
    const int x0  = blockIdx.x * 16;
    const int tid = threadIdx.x;
    const int cls = g_cls[b];

    for (int i = tid; i < 576; i += 256) {
        ws[i * 3 + 0] = Wo3[i * 6 + 2 * cls];
        ws[i * 3 + 1] = Wo3[i * 6 + 2 * cls + 1];
        ws[i * 3 + 2] = Ww3[i * 3 + cls];
    }

    const float* po = h2o + (size_t)b * HW * HW * 64;
    const float* pw = h2w + (size_t)b * HW * HW * 64;
    for (int i = tid; i < 324 * 16; i += 256) {
        int ci4 = i & 15;
        int rc  = i >> 4;
        int r = rc / 18, c = rc % 18;
        int gy = y0 + r - 1, gx = x0 + c - 1;
        float4 vo = make_float4(0.f, 0.f, 0.f, 0.f);
        float4 vw = vo;
        if ((unsigned)gy < HW && (unsigned)gx < HW) {
            size_t g = ((size_t)gy * HW + gx) * 64 + ci4 * 4;
            vo = *(const float4*)&po[g];
            vw = *(const float4*)&pw[g];
        }
        int base = r * 19 + c;
        ho[(ci4 * 4 + 0) * 342 + base] = vo.x;
        ho[(ci4 * 4 + 1) * 342 + base] = vo.y;
        ho[(ci4 * 4 + 2) * 342 + base] = vo.z;
        ho[(ci4 * 4 + 3) * 342 + base] = vo.w;
        hw[(ci4 * 4 + 0) * 342 + base] = vw.x;
        hw[(ci4 * 4 + 1) * 342 + base] = vw.y;
        hw[(ci4 * 4 + 2) * 342 + base] = vw.z;
        hw[(ci4 * 4 + 3) * 342 + base] = vw.w;
    }
    __syncthreads();

    const int r = tid >> 4, c = tid & 15;
    float o0 = bo3[2 * cls], o1 = bo3[2 * cls + 1], wv = bw3[cls];

#pragma unroll 1
    for (int ky = 0; ky < 3; ++ky) {
#pragma unroll 1
        for (int kx = 0; kx < 3; ++kx) {
            int base = (r + ky) * 19 + (c + kx);
            const float* wp = &ws[(ky * 3 + kx) * 64 * 3];
#pragma unroll 8
            for (int ci = 0; ci < 64; ++ci) {
                float ao = ho[ci * 342 + base];
                float aw = hw[ci * 342 + base];
                o0 = fmaf(ao, wp[ci * 3 + 0], o0);
                o1 = fmaf(ao, wp[ci * 3 + 1], o1);
                wv = fmaf(aw, wp[ci * 3 + 2], wv);
            }
        }
    }

    int gy = y0 + r, gx = x0 + c;
    size_t pix = ((size_t)b * HW + gy) * HW + gx;
    *(float2*)&out[pix * 2] = make_float2(o0, o1);
    out[(size_t)BATCH * HW * HW * 2 + pix] = wv;
}

// ---------------------------------------------------------------------------
extern "C" void kernel_launch(void* const* d_in, const int* in_sizes, int n_in,
                              void* d_out, int out_size)
{
    (void)in_sizes; (void)n_in; (void)out_size;
    const float* x0  = (const float*)d_in[0];
    const float* f4  = (const float*)d_in[1];
    const float* Wo1 = (const float*)d_in[2];
    const float* bo1 = (const float*)d_in[3];
    const float* Wo2 = (const float*)d_in[4];
    const float* bo2 = (const float*)d_in[5];
    const float* Wo3 = (const float*)d_in[6];
    const float* bo3 = (const float*)d_in[7];
    const float* Ww1 = (const float*)d_in[8];
    const float* bw1 = (const float*)d_in[9];
    const float* Ww2 = (const float*)d_in[10];
    const float* bw2 = (const float*)d_in[11];
    const float* Ww3 = (const float*)d_in[12];
    const float* bw3 = (const float*)d_in[13];
    const float* Wc1 = (const float*)d_in[14];
    const float* bc1 = (const float*)d_in[15];
    const float* Wc2 = (const float*)d_in[16];
    const float* bc2 = (const float*)d_in[17];
    const float* Wc3 = (const float*)d_in[18];
    const float* bc3 = (const float*)d_in[19];
    float* out = (float*)d_out;

    void *pC, *pD, *pHo, *pHw, *pW1o, *pW1w, *pW2o, *pW2w;
    cudaGetSymbolAddress(&pC, g_bufC);
    cudaGetSymbolAddress(&pD, g_bufD);
    cudaGetSymbolAddress(&pHo, g_h1o);
    cudaGetSymbolAddress(&pHw, g_h1w);
    cudaGetSymbolAddress(&pW1o, g_wp1o);
    cudaGetSymbolAddress(&pW1w, g_wp1w);
    cudaGetSymbolAddress(&pW2o, g_wp2o);
    cudaGetSymbolAddress(&pW2w, g_wp2w);

    const size_t smem1 = 256 + (size_t)204 * 80 + (size_t)192 * 80;           //  31.9 KB
    const size_t smem2 = 256 + (size_t)204 * 144 + (size_t)192 * 144;         //  57.3 KB
    const size_t smem3 = (size_t)(2 * 64 * 342 + 576 * 3) * sizeof(float);    // 182.0 KB

    cudaFuncSetAttribute((const void*)conv3x3_rows<32, false, true>,
                         cudaFuncAttributeMaxDynamicSharedMemorySize, (int)smem1);
    cudaFuncSetAttribute((const void*)conv3x3_rows<64, true, false>,
                         cudaFuncAttributeMaxDynamicSharedMemorySize, (int)smem2);
    cudaFuncSetAttribute((const void*)conv3_select,
                         cudaFuncAttributeMaxDynamicSharedMemorySize, (int)smem3);

    float* pred = out + (size_t)BATCH * HW * HW * 3;

    head_kernel<<<BATCH, 256>>>(f4, Wc1, bc1, Wc2, bc2, Wc3, bc3, pred);
    prep_weights<<<36, 256>>>(Wo1, (__half*)pW1o, 32);
    prep_weights<<<36, 256>>>(Ww1, (__half*)pW1w, 32);
    prep_weights<<<72, 256>>>(Wo2, (__half*)pW2o, 64);
    prep_weights<<<72, 256>>>(Ww2, (__half*)pW2w, 64);

    dim3 gconv(HW / 32, HW / 4, BATCH);   // 16 x-tiles, 128 row-groups, 4 batches
    conv3x3_rows<32, false, true><<<gconv, 256, smem1>>>(
        x0, (__half*)pW1o, bo1, nullptr, (__half*)pHo);
    conv3x3_rows<32, false, true><<<gconv, 256, smem1>>>(
        x0, (__half*)pW1w, bw1, nullptr, (__half*)pHw);
    conv3x3_rows<64, true, false><<<gconv, 256, smem2>>>(
        (__half*)pHo, (__half*)pW2o, bo2, (float*)pC, nullptr);
    conv3x3_rows<64, true, false><<<gconv, 256, smem2>>>(
        (__half*)pHw, (__half*)pW2w, bw2, (float*)pD, nullptr);

    dim3 g3(HW / 16, HW / 16, BATCH);
    conv3_select<<<g3, 256, smem3>>>((float*)pC, (float*)pD, Wo3, bo3, Ww3, bw3, out);
}

// round 12
// speedup vs baseline: 2.2825x; 1.2203x over previous
#include <cuda_runtime.h>
#include <cuda_fp16.h>
#include <math.h>
#include <stdint.h>

#define BATCH 4
#define HW    512
#define CMID  64

// ---------------------------------------------------------------------------
// Scratch (allocation-free rule: __device__ globals)
// ---------------------------------------------------------------------------
__device__ __align__(256) __half g_h1o[(size_t)BATCH * HW * HW * CMID];   // conv1 offsets out
__device__ __align__(256) __half g_h1w[(size_t)BATCH * HW * HW * CMID];   // conv1 weights out
__device__ __align__(256) __half g_h2o[(size_t)BATCH * HW * HW * CMID];   // conv2 offsets out
__device__ __align__(256) __half g_h2w[(size_t)BATCH * HW * HW * CMID];   // conv2 weights out
__device__ __align__(256) __half g_wp1o[9 * 64 * 32];
__device__ __align__(256) __half g_wp1w[9 * 64 * 32];
__device__ __align__(256) __half g_wp2o[9 * 64 * 64];
__device__ __align__(256) __half g_wp2w[9 * 64 * 64];
__device__ int g_cls[BATCH];

__device__ __forceinline__ uint32_t smem_u32(const void* p) {
    uint32_t a;
    asm("{ .reg .u64 t; cvta.to.shared.u64 t, %1; cvt.u32.u64 %0, t; }"
        : "=r"(a) : "l"(p));
    return a;
}
__device__ __forceinline__ void ldm_x4(uint32_t* r, uint32_t addr) {
    asm volatile("ldmatrix.sync.aligned.m8n8.x4.shared.b16 {%0,%1,%2,%3}, [%4];"
                 : "=r"(r[0]), "=r"(r[1]), "=r"(r[2]), "=r"(r[3]) : "r"(addr));
}
__device__ __forceinline__ void mma16816(float* d, const uint32_t* a, const uint32_t* b) {
    asm volatile(
        "mma.sync.aligned.m16n8k16.row.col.f32.f16.f16.f32 "
        "{%0,%1,%2,%3}, {%4,%5,%6,%7}, {%8,%9}, {%0,%1,%2,%3};"
        : "+f"(d[0]), "+f"(d[1]), "+f"(d[2]), "+f"(d[3])
        : "r"(a[0]), "r"(a[1]), "r"(a[2]), "r"(a[3]), "r"(b[0]), "r"(b[1]));
}
// 16B async copy; src_sz = 16 (copy) or 0 (zero-fill 16B)
__device__ __forceinline__ void cp16(uint32_t dst, const void* src, int src_sz) {
    asm volatile("cp.async.ca.shared.global [%0], [%1], 16, %2;"
                 :: "r"(dst), "l"(src), "r"(src_sz) : "memory");
}
__device__ __forceinline__ void cp_commit_wait() {
    asm volatile("cp.async.commit_group;" ::: "memory");
    asm volatile("cp.async.wait_group 0;" ::: "memory");
}

// ---------------------------------------------------------------------------
// Weight prep: HWIO fp32 w[(tap*CIN+ci)*64+co] -> wp[(tap*64 + co)*CIN + ci]
// ---------------------------------------------------------------------------
__global__ void prep_weights(const float* __restrict__ w, __half* __restrict__ wp,
                             int CIN)
{
    int total = 9 * CIN * 64;
    for (int i = blockIdx.x * 256 + threadIdx.x; i < total; i += gridDim.x * 256) {
        int co  = i % 64;
        int ci  = (i / 64) % CIN;
        int tap = i / (64 * CIN);
        wp[((size_t)tap * 64 + co) * CIN + ci] = __float2half_rn(w[i]);
    }
}

// ---------------------------------------------------------------------------
// 3x3 SAME conv, CIN -> 64, ReLU, full-fp16 mma.sync (fp32 accum), fp16 out.
// Both branches in ONE launch: gridDim.z = 2*BATCH, branch = bz / BATCH.
// Block: M = 4 output rows x 32 px (=128), N = 64 co. 8 warps = 4(Mrow) x 2(N).
// HALF_IN: input fp16 NHWC -> A staging = pure cp.async copies.
// ---------------------------------------------------------------------------
template <int CIN, bool HALF_IN>
__global__ void __launch_bounds__(256, 2)
conv3x3_rows(const void* __restrict__ in0, const void* __restrict__ in1,
             const __half* __restrict__ wp0, const __half* __restrict__ wp1,
             const float* __restrict__ bias0, const float* __restrict__ bias1,
             __half* __restrict__ out0, __half* __restrict__ out1)
{
    constexpr int ADATA  = CIN * 2;          // bytes per A pixel row
    constexpr int APITCH = ADATA + 16;       // conv2: 144, conv1: 80
    constexpr int BPITCH = CIN * 2 + 16;
    constexpr int KSTEPS = CIN / 16;

    extern __shared__ char sm[];
    float* bias_s = (float*)sm;              // 256 B
    char*  As = sm + 256;                    // 204 * APITCH
    char*  Bs = As + 204 * APITCH;           // 192 * BPITCH

    const int tid  = threadIdx.x;
    const int lane = tid & 31;
    const int wid  = tid >> 5;
    const int wm   = wid >> 1;        // output row 0..3
    const int wn   = wid & 1;         // co half
    const int x0   = blockIdx.x * 32;
    const int y0   = blockIdx.y * 4;
    const int bz   = blockIdx.z;
    const int batch = bz & (BATCH - 1);
    const int br    = bz >> 2;        // 0 = offsets branch, 1 = weights branch

    const void*   in   = br ? in1 : in0;
    const __half* wp   = br ? wp1 : wp0;
    const float*  bias = br ? bias1 : bias0;
    __half*       outh = br ? out1 : out0;

    if (tid < 64) bias_s[tid] = bias[tid];

    float acc[2][4][4];
#pragma unroll
    for (int mf = 0; mf < 2; ++mf)
#pragma unroll
        for (int nf = 0; nf < 4; ++nf)
#pragma unroll
            for (int q = 0; q < 4; ++q) acc[mf][nf][q] = 0.f;

    const uint32_t AsU = smem_u32(As);
    const uint32_t BsU = smem_u32(Bs);

    // --- stage A once: 6 input rows (y0-1 .. y0+4) x 34 px
    if (HALF_IN) {
        const __half* ib = (const __half*)in + (size_t)batch * HW * HW * CIN;
        constexpr int CH = CIN / 8;          // 16B chunks per pixel
        for (int i = tid; i < 204 * CH; i += 256) {
            int c   = i % CH;
            int px  = i / CH;
            int irow = px / 34, col = px % 34;
            int gy = y0 - 1 + irow;
            int gx = x0 - 1 + col;
            bool ok = (unsigned)gy < HW && (unsigned)gx < HW;
            int cgy = ok ? gy : 0, cgx = ok ? gx : 0;
            cp16(AsU + px * APITCH + c * 16,
                 ib + ((size_t)cgy * HW + cgx) * CIN + c * 8, ok ? 16 : 0);
        }
    } else {
        const float* ib = (const float*)in + (size_t)batch * HW * HW * CIN;
        for (int i = tid; i < 204 * (CIN / 4); i += 256) {
            int ci4 = i % (CIN / 4);
            int px  = i / (CIN / 4);
            int irow = px / 34, c = px % 34;
            int gy = y0 - 1 + irow;
            int gx = x0 - 1 + c;
            float4 v = make_float4(0.f, 0.f, 0.f, 0.f);
            if ((unsigned)gy < HW && (unsigned)gx < HW)
                v = *(const float4*)&ib[((size_t)gy * HW + gx) * CIN + ci4 * 4];
            __half2 h0 = __float22half2_rn(make_float2(v.x, v.y));
            __half2 h1 = __float22half2_rn(make_float2(v.z, v.w));
            *(uint2*)(As + px * APITCH + ci4 * 8) =
                make_uint2(*(uint32_t*)&h0, *(uint32_t*)&h1);
        }
    }

    // --- B staging (3 taps of row ky) via cp.async
    auto stage_B = [&](int ky) {
        constexpr int CH = CIN / 8;             // uint4 chunks per row
        for (int i = tid; i < 3 * 64 * CH; i += 256) {
            int c   = i % CH;
            int row = (i / CH) & 63;
            int tap = i / (CH * 64);
            cp16(BsU + (tap * 64 + row) * BPITCH + c * 16,
                 wp + ((size_t)(ky * 3 + tap) * 64 + row) * CIN + c * 8, 16);
        }
    };

    stage_B(0);
    cp_commit_wait();
    __syncthreads();

    const int brow_in = (lane & 7) + ((lane >> 4) & 1) * 8;
    const int bcol    = ((lane >> 3) & 1) * 16;
    const int acol    = (lane >> 4) * 16;
    const int apx     = (lane & 15);

    for (int ky = 0; ky < 3; ++ky) {
#pragma unroll
        for (int kx = 0; kx < 3; ++kx) {
#pragma unroll
            for (int ks = 0; ks < KSTEPS; ++ks) {
                uint32_t a_r[2][4];
#pragma unroll
                for (int mf = 0; mf < 2; ++mf) {
                    int px = (wm + ky) * 34 + mf * 16 + apx + kx;
                    ldm_x4(a_r[mf], AsU + (uint32_t)(px * APITCH + ks * 32 + acol));
                }
                uint32_t b_r[2][4];
#pragma unroll
                for (int nh = 0; nh < 2; ++nh) {
                    int row = wn * 32 + nh * 16 + brow_in;
                    ldm_x4(b_r[nh], BsU + (uint32_t)((kx * 64 + row) * BPITCH + ks * 32 + bcol));
                }
#pragma unroll
                for (int mf = 0; mf < 2; ++mf)
#pragma unroll
                    for (int nf = 0; nf < 4; ++nf)
                        mma16816(acc[mf][nf], a_r[mf], &b_r[nf >> 1][(nf & 1) * 2]);
            }
        }
        if (ky < 2) {
            __syncthreads();       // compute done, B free
            stage_B(ky + 1);
            cp_commit_wait();
            __syncthreads();       // new B ready
        }
    }

    // --- epilogue: bias + relu, fp16 NHWC store
    const int prow  = lane >> 2;
    const int cbase = wn * 32 + 2 * (lane & 3);
    const int gy    = y0 + wm;
#pragma unroll
    for (int mf = 0; mf < 2; ++mf) {
#pragma unroll
        for (int nf = 0; nf < 4; ++nf) {
            int co = cbase + nf * 8;
            float b0 = bias_s[co], b1 = bias_s[co + 1];
            int gx = x0 + mf * 16 + prow;
            size_t o0 = (((size_t)batch * HW + gy) * HW + gx) * 64 + co;
            float f0 = fmaxf(acc[mf][nf][0] + b0, 0.f);
            float f1 = fmaxf(acc[mf][nf][1] + b1, 0.f);
            float f2 = fmaxf(acc[mf][nf][2] + b0, 0.f);
            float f3 = fmaxf(acc[mf][nf][3] + b1, 0.f);
            __half2 v0 = __float22half2_rn(make_float2(f0, f1));
            __half2 v1 = __float22half2_rn(make_float2(f2, f3));
            *(uint32_t*)&outh[o0]          = *(uint32_t*)&v0;
            *(uint32_t*)&outh[o0 + 8 * 64] = *(uint32_t*)&v1;   // gx + 8
        }
    }
}

// ---------------------------------------------------------------------------
// Head: GAP(f4) -> FC chain -> softmax -> pred_cls + argmax cls
// ---------------------------------------------------------------------------
__global__ void head_kernel(const float* __restrict__ f4,
                            const float* __restrict__ Wc1, const float* __restrict__ bc1,
                            const float* __restrict__ Wc2, const float* __restrict__ bc2,
                            const float* __restrict__ Wc3, const float* __restrict__ bc3,
                            float* __restrict__ out_pred)
{
    __shared__ float gap[256];
    __shared__ float z1[128];
    __shared__ float z2[128];
    __shared__ float logits[3];

    const int b = blockIdx.x;
    const int tid = threadIdx.x;

    const float* p = f4 + (size_t)b * 1024 * 256 + tid;
    float s0 = 0.f, s1 = 0.f, s2 = 0.f, s3 = 0.f;
    for (int i = 0; i < 1024; i += 4) {
        s0 += p[(i + 0) * 256];
        s1 += p[(i + 1) * 256];
        s2 += p[(i + 2) * 256];
        s3 += p[(i + 3) * 256];
    }
    gap[tid] = (s0 + s1 + s2 + s3) * (1.0f / 1024.0f);
    __syncthreads();

    if (tid < 128) {
        float a = bc1[tid];
#pragma unroll 8
        for (int k = 0; k < 256; ++k) a = fmaf(gap[k], Wc1[k * 128 + tid], a);
        z1[tid] = fmaxf(a, 0.f);
    }
    __syncthreads();

    if (tid < 128) {
        float a = bc2[tid];
#pragma unroll 8
        for (int k = 0; k < 128; ++k) a = fmaf(z1[k], Wc2[k * 128 + tid], a);
        z2[tid] = fmaxf(a, 0.f);
    }
    __syncthreads();

    if (tid < 3) {
        float a = bc3[tid];
        for (int k = 0; k < 128; ++k) a = fmaf(z2[k], Wc3[k * 3 + tid], a);
        logits[tid] = a;
    }
    __syncthreads();

    if (tid == 0) {
        float l0 = logits[0], l1 = logits[1], l2 = logits[2];
        float m = fmaxf(l0, fmaxf(l1, l2));
        float e0 = expf(l0 - m), e1 = expf(l1 - m), e2 = expf(l2 - m);
        float inv = 1.f / (e0 + e1 + e2);
        out_pred[b * 3 + 0] = e0 * inv;
        out_pred[b * 3 + 1] = e1 * inv;
        out_pred[b * 3 + 2] = e2 * inv;
        int c = 0; float best = l0;
        if (l1 > best) { best = l1; c = 1; }
        if (l2 > best) { best = l2; c = 2; }
        g_cls[b] = c;
    }
}

// ---------------------------------------------------------------------------
// Final convs fused with channel gather; fp16 inputs, fp16 smem tiles (occ 2).
// ---------------------------------------------------------------------------
__global__ void __launch_bounds__(256, 2)
conv3_select(const __half* __restrict__ h2o, const __half* __restrict__ h2w,
             const float* __restrict__ Wo3, const float* __restrict__ bo3,
             const float* __restrict__ Ww3, const float* __restrict__ bw3,
             float* __restrict__ out)
{
    extern __shared__ char sm3[];
    __half* ho = (__half*)sm3;                 // 64 * 342  (ci-major, pitch 19)
    __half* hw = ho + 64 * 342;
    float*  ws = (float*)(hw + 64 * 342);      // 576 * 3 selected weights

    const int b   = blockIdx.z;
    const int y0  = blockIdx.y * 16;
    const int x0  = blockIdx.x * 16;
    const int tid = threadIdx.x;
    const int cls = g_cls[b];

    for (int i = tid; i < 576; i += 256) {
        ws[i * 3 + 0] = Wo3[i * 6 + 2 * cls];
        ws[i * 3 + 1] = Wo3[i * 6 + 2 * cls + 1];
        ws[i * 3 + 2] = Ww3[i * 3 + cls];
    }

    const __half* po = h2o + (size_t)b * HW * HW * 64;
    const __half* pw = h2w + (size_t)b * HW * HW * 64;
    for (int i = tid; i < 324 * 8; i += 256) {
        int ci8 = i & 7;                 // chunk of 8 ci
        int rc  = i >> 3;
        int r = rc / 18, c = rc % 18;
        int gy = y0 + r - 1, gx = x0 + c - 1;
        uint4 vo = make_uint4(0, 0, 0, 0), vw = vo;
        if ((unsigned)gy < HW && (unsigned)gx < HW) {
            size_t g = ((size_t)gy * HW + gx) * 64 + ci8 * 8;
            vo = *(const uint4*)&po[g];
            vw = *(const uint4*)&pw[g];
        }
        int base = r * 19 + c;
        const __half* vo_h = (const __half*)&vo;
        const __half* vw_h = (const __half*)&vw;
#pragma unroll
        for (int j = 0; j < 8; ++j) {
            ho[(ci8 * 8 + j) * 342 + base] = vo_h[j];
            hw[(ci8 * 8 + j) * 342 + base] = vw_h[j];
        }
    }
    __syncthreads();

    const int r = tid >> 4, c = tid & 15;
    float o0 = bo3[2 * cls], o1 = bo3[2 * cls + 1], wv = bw3[cls];

#pragma unroll 1
    for (int ky = 0; ky < 3; ++ky) {
#pragma unroll 1
        for (int kx = 0; kx < 3; ++kx) {
            int base = (r + ky) * 19 + (c + kx);
            const float* wp = &ws[(ky * 3 + kx) * 64 * 3];
#pragma unroll 8
            for (int ci = 0; ci < 64; ++ci) {
                float ao = __half2float(ho[ci * 342 + base]);
                float aw = __half2float(hw[ci * 342 + base]);
                o0 = fmaf(ao, wp[ci * 3 + 0], o0);
                o1 = fmaf(ao, wp[ci * 3 + 1], o1);
                wv = fmaf(aw, wp[ci * 3 + 2], wv);
            }
        }
    }

    int gy = y0 + r, gx = x0 + c;
    size_t pix = ((size_t)b * HW + gy) * HW + gx;
    *(float2*)&out[pix * 2] = make_float2(o0, o1);
    out[(size_t)BATCH * HW * HW * 2 + pix] = wv;
}

// ---------------------------------------------------------------------------
extern "C" void kernel_launch(void* const* d_in, const int* in_sizes, int n_in,
                              void* d_out, int out_size)
{
    (void)in_sizes; (void)n_in; (void)out_size;
    const float* x0  = (const float*)d_in[0];
    const float* f4  = (const float*)d_in[1];
    const float* Wo1 = (const float*)d_in[2];
    const float* bo1 = (const float*)d_in[3];
    const float* Wo2 = (const float*)d_in[4];
    const float* bo2 = (const float*)d_in[5];
    const float* Wo3 = (const float*)d_in[6];
    const float* bo3 = (const float*)d_in[7];
    const float* Ww1 = (const float*)d_in[8];
    const float* bw1 = (const float*)d_in[9];
    const float* Ww2 = (const float*)d_in[10];
    const float* bw2 = (const float*)d_in[11];
    const float* Ww3 = (const float*)d_in[12];
    const float* bw3 = (const float*)d_in[13];
    const float* Wc1 = (const float*)d_in[14];
    const float* bc1 = (const float*)d_in[15];
    const float* Wc2 = (const float*)d_in[16];
    const float* bc2 = (const float*)d_in[17];
    const float* Wc3 = (const float*)d_in[18];
    const float* bc3 = (const float*)d_in[19];
    float* out = (float*)d_out;

    void *pH1o, *pH1w, *pH2o, *pH2w, *pW1o, *pW1w, *pW2o, *pW2w;
    cudaGetSymbolAddress(&pH1o, g_h1o);
    cudaGetSymbolAddress(&pH1w, g_h1w);
    cudaGetSymbolAddress(&pH2o, g_h2o);
    cudaGetSymbolAddress(&pH2w, g_h2w);
    cudaGetSymbolAddress(&pW1o, g_wp1o);
    cudaGetSymbolAddress(&pW1w, g_wp1w);
    cudaGetSymbolAddress(&pW2o, g_wp2o);
    cudaGetSymbolAddress(&pW2w, g_wp2w);

    const size_t smem1 = 256 + (size_t)204 * 80 + (size_t)192 * 80;           //  31.9 KB
    const size_t smem2 = 256 + (size_t)204 * 144 + (size_t)192 * 144;         //  57.3 KB
    const size_t smem3 = (size_t)(2 * 64 * 342) * 2 + 576 * 3 * 4;            //  92.3 KB

    cudaFuncSetAttribute((const void*)conv3x3_rows<32, false>,
                         cudaFuncAttributeMaxDynamicSharedMemorySize, (int)smem1);
    cudaFuncSetAttribute((const void*)conv3x3_rows<64, true>,
                         cudaFuncAttributeMaxDynamicSharedMemorySize, (int)smem2);
    cudaFuncSetAttribute((const void*)conv3_select,
                         cudaFuncAttributeMaxDynamicSharedMemorySize, (int)smem3);

    float* pred = out + (size_t)BATCH * HW * HW * 3;

    head_kernel<<<BATCH, 256>>>(f4, Wc1, bc1, Wc2, bc2, Wc3, bc3, pred);
    prep_weights<<<36, 256>>>(Wo1, (__half*)pW1o, 32);
    prep_weights<<<36, 256>>>(Ww1, (__half*)pW1w, 32);
    prep_weights<<<72, 256>>>(Wo2, (__half*)pW2o, 64);
    prep_weights<<<72, 256>>>(Ww2, (__half*)pW2w, 64);

    dim3 gconv(HW / 32, HW / 4, 2 * BATCH);   // both branches in one launch
    conv3x3_rows<32, false><<<gconv, 256, smem1>>>(
        x0, x0, (__half*)pW1o, (__half*)pW1w, bo1, bw1,
        (__half*)pH1o, (__half*)pH1w);
    conv3x3_rows<64, true><<<gconv, 256, smem2>>>(
        pH1o, pH1w, (__half*)pW2o, (__half*)pW2w, bo2, bw2,
        (__half*)pH2o, (__half*)pH2w);

    dim3 g3(HW / 16, HW / 16, BATCH);
    conv3_select<<<g3, 256, smem3>>>((__half*)pH2o, (__half*)pH2w,
                                     Wo3, bo3, Ww3, bw3, out);
}

// round 13
// speedup vs baseline: 2.6558x; 1.1635x over previous
#include <cuda_runtime.h>
#include <cuda_fp16.h>
#include <math.h>
#include <stdint.h>

#define BATCH 4
#define HW    512
#define CMID  64

// ---------------------------------------------------------------------------
// Scratch (allocation-free rule: __device__ globals)
// ---------------------------------------------------------------------------
__device__ __align__(256) __half g_h1o[(size_t)BATCH * HW * HW * CMID];   // conv1 offsets out
__device__ __align__(256) __half g_h1w[(size_t)BATCH * HW * HW * CMID];   // conv1 weights out
__device__ __align__(256) __half g_h2o[(size_t)BATCH * HW * HW * CMID];   // conv2 offsets out
__device__ __align__(256) __half g_h2w[(size_t)BATCH * HW * HW * CMID];   // conv2 weights out
__device__ __align__(256) __half g_wp1o[9 * 64 * 32];
__device__ __align__(256) __half g_wp1w[9 * 64 * 32];
__device__ __align__(256) __half g_wp2o[9 * 64 * 64];
__device__ __align__(256) __half g_wp2w[9 * 64 * 64];
__device__ int g_cls[BATCH];

__device__ __forceinline__ uint32_t smem_u32(const void* p) {
    uint32_t a;
    asm("{ .reg .u64 t; cvta.to.shared.u64 t, %1; cvt.u32.u64 %0, t; }"
        : "=r"(a) : "l"(p));
    return a;
}
__device__ __forceinline__ void ldm_x4(uint32_t* r, uint32_t addr) {
    asm volatile("ldmatrix.sync.aligned.m8n8.x4.shared.b16 {%0,%1,%2,%3}, [%4];"
                 : "=r"(r[0]), "=r"(r[1]), "=r"(r[2]), "=r"(r[3]) : "r"(addr));
}
__device__ __forceinline__ void mma16816(float* d, const uint32_t* a, const uint32_t* b) {
    asm volatile(
        "mma.sync.aligned.m16n8k16.row.col.f32.f16.f16.f32 "
        "{%0,%1,%2,%3}, {%4,%5,%6,%7}, {%8,%9}, {%0,%1,%2,%3};"
        : "+f"(d[0]), "+f"(d[1]), "+f"(d[2]), "+f"(d[3])
        : "r"(a[0]), "r"(a[1]), "r"(a[2]), "r"(a[3]), "r"(b[0]), "r"(b[1]));
}
// 16B async copy; src_sz = 16 (copy) or 0 (zero-fill 16B)
__device__ __forceinline__ void cp16(uint32_t dst, const void* src, int src_sz) {
    asm volatile("cp.async.ca.shared.global [%0], [%1], 16, %2;"
                 :: "r"(dst), "l"(src), "r"(src_sz) : "memory");
}
__device__ __forceinline__ void cp_commit_wait() {
    asm volatile("cp.async.commit_group;" ::: "memory");
    asm volatile("cp.async.wait_group 0;" ::: "memory");
}

// ---------------------------------------------------------------------------
// Weight prep (all 4 tensors in ONE launch; blockIdx.y selects tensor):
// HWIO fp32 w[(tap*CIN+ci)*64+co] -> wp[(tap*64 + co)*CIN + ci]
// ---------------------------------------------------------------------------
__global__ void prep_all(const float* __restrict__ Wo1, const float* __restrict__ Ww1,
                         const float* __restrict__ Wo2, const float* __restrict__ Ww2,
                         __half* __restrict__ p1o, __half* __restrict__ p1w,
                         __half* __restrict__ p2o, __half* __restrict__ p2w)
{
    const int sel = blockIdx.y;
    const float* w  = sel == 0 ? Wo1 : sel == 1 ? Ww1 : sel == 2 ? Wo2 : Ww2;
    __half*      wp = sel == 0 ? p1o : sel == 1 ? p1w : sel == 2 ? p2o : p2w;
    const int CIN = (sel < 2) ? 32 : 64;

    int total = 9 * CIN * 64;
    for (int i = blockIdx.x * 256 + threadIdx.x; i < total; i += gridDim.x * 256) {
        int co  = i % 64;
        int ci  = (i / 64) % CIN;
        int tap = i / (64 * CIN);
        wp[((size_t)tap * 64 + co) * CIN + ci] = __float2half_rn(w[i]);
    }
}

// ---------------------------------------------------------------------------
// 3x3 SAME conv, CIN -> 64, ReLU, full-fp16 mma.sync (fp32 accum), fp16 out.
// Both branches in ONE launch: gridDim.z = 2*BATCH, branch = bz / BATCH.
// Block: M = 8 output rows x 32 px (=256 outputs), N = 64 co.
// 8 warps; warp wid owns output row wid: warp tile 32(M) x 64(N),
// acc[2][8][4] (64 regs). A strip: 10 rows x 34 px staged once.
// ---------------------------------------------------------------------------
template <int CIN, bool HALF_IN>
__global__ void __launch_bounds__(256, 2)
conv3x3_rows(const void* __restrict__ in0, const void* __restrict__ in1,
             const __half* __restrict__ wp0, const __half* __restrict__ wp1,
             const float* __restrict__ bias0, const float* __restrict__ bias1,
             __half* __restrict__ out0, __half* __restrict__ out1)
{
    constexpr int ADATA  = CIN * 2;          // bytes per A pixel row
    constexpr int APITCH = ADATA + 16;       // conv2: 144, conv1: 80
    constexpr int BPITCH = CIN * 2 + 16;
    constexpr int KSTEPS = CIN / 16;
    constexpr int NPX    = 10 * 34;          // 340 staged pixels

    extern __shared__ char sm[];
    float* bias_s = (float*)sm;              // 256 B
    char*  As = sm + 256;                    // NPX * APITCH
    char*  Bs = As + NPX * APITCH;           // 192 * BPITCH

    const int tid  = threadIdx.x;
    const int lane = tid & 31;
    const int wm   = tid >> 5;        // output row 0..7
    const int x0   = blockIdx.x * 32;
    const int y0   = blockIdx.y * 8;
    const int bz   = blockIdx.z;
    const int batch = bz & (BATCH - 1);
    const int br    = bz >> 2;        // 0 = offsets branch, 1 = weights branch

    const void*   in   = br ? in1 : in0;
    const __half* wp   = br ? wp1 : wp0;
    const float*  bias = br ? bias1 : bias0;
    __half*       outh = br ? out1 : out0;

    if (tid < 64) bias_s[tid] = bias[tid];

    float acc[2][8][4];
#pragma unroll
    for (int mf = 0; mf < 2; ++mf)
#pragma unroll
        for (int nf = 0; nf < 8; ++nf)
#pragma unroll
            for (int q = 0; q < 4; ++q) acc[mf][nf][q] = 0.f;

    const uint32_t AsU = smem_u32(As);
    const uint32_t BsU = smem_u32(Bs);

    // --- stage A once: 10 input rows (y0-1 .. y0+8) x 34 px
    if (HALF_IN) {
        const __half* ib = (const __half*)in + (size_t)batch * HW * HW * CIN;
        constexpr int CH = CIN / 8;          // 16B chunks per pixel
        for (int i = tid; i < NPX * CH; i += 256) {
            int c   = i % CH;
            int px  = i / CH;
            int irow = px / 34, col = px % 34;
            int gy = y0 - 1 + irow;
            int gx = x0 - 1 + col;
            bool ok = (unsigned)gy < HW && (unsigned)gx < HW;
            int cgy = ok ? gy : 0, cgx = ok ? gx : 0;
            cp16(AsU + px * APITCH + c * 16,
                 ib + ((size_t)cgy * HW + cgx) * CIN + c * 8, ok ? 16 : 0);
        }
    } else {
        const float* ib = (const float*)in + (size_t)batch * HW * HW * CIN;
        for (int i = tid; i < NPX * (CIN / 4); i += 256) {
            int ci4 = i % (CIN / 4);
            int px  = i / (CIN / 4);
            int irow = px / 34, c = px % 34;
            int gy = y0 - 1 + irow;
            int gx = x0 - 1 + c;
            float4 v = make_float4(0.f, 0.f, 0.f, 0.f);
            if ((unsigned)gy < HW && (unsigned)gx < HW)
                v = *(const float4*)&ib[((size_t)gy * HW + gx) * CIN + ci4 * 4];
            __half2 h0 = __float22half2_rn(make_float2(v.x, v.y));
            __half2 h1 = __float22half2_rn(make_float2(v.z, v.w));
            *(uint2*)(As + px * APITCH + ci4 * 8) =
                make_uint2(*(uint32_t*)&h0, *(uint32_t*)&h1);
        }
    }

    // --- B staging (3 taps of row ky) via cp.async
    auto stage_B = [&](int ky) {
        constexpr int CH = CIN / 8;             // uint4 chunks per row
        for (int i = tid; i < 3 * 64 * CH; i += 256) {
            int c   = i % CH;
            int row = (i / CH) & 63;
            int tap = i / (CH * 64);
            cp16(BsU + (tap * 64 + row) * BPITCH + c * 16,
                 wp + ((size_t)(ky * 3 + tap) * 64 + row) * CIN + c * 8, 16);
        }
    };

    stage_B(0);
    cp_commit_wait();
    __syncthreads();

    const int brow_in = (lane & 7) + ((lane >> 4) & 1) * 8;
    const int bcol    = ((lane >> 3) & 1) * 16;
    const int acol    = (lane >> 4) * 16;
    const int apx     = (lane & 15);

    for (int ky = 0; ky < 3; ++ky) {
#pragma unroll
        for (int kx = 0; kx < 3; ++kx) {
#pragma unroll
            for (int ks = 0; ks < KSTEPS; ++ks) {
                uint32_t a_r[2][4];
#pragma unroll
                for (int mf = 0; mf < 2; ++mf) {
                    int px = (wm + ky) * 34 + mf * 16 + apx + kx;
                    ldm_x4(a_r[mf], AsU + (uint32_t)(px * APITCH + ks * 32 + acol));
                }
                uint32_t b_r[4][4];
#pragma unroll
                for (int nh = 0; nh < 4; ++nh) {
                    int row = nh * 16 + brow_in;
                    ldm_x4(b_r[nh], BsU + (uint32_t)((kx * 64 + row) * BPITCH + ks * 32 + bcol));
                }
#pragma unroll
                for (int mf = 0; mf < 2; ++mf)
#pragma unroll
                    for (int nf = 0; nf < 8; ++nf)
                        mma16816(acc[mf][nf], a_r[mf], &b_r[nf >> 1][(nf & 1) * 2]);
            }
        }
        if (ky < 2) {
            __syncthreads();       // compute done, B free
            stage_B(ky + 1);
            cp_commit_wait();
            __syncthreads();       // new B ready
        }
    }

    // --- epilogue: bias + relu, fp16 NHWC store
    const int prow  = lane >> 2;
    const int cbase = 2 * (lane & 3);
    const int gy    = y0 + wm;
#pragma unroll
    for (int mf = 0; mf < 2; ++mf) {
#pragma unroll
        for (int nf = 0; nf < 8; ++nf) {
            int co = cbase + nf * 8;
            float b0 = bias_s[co], b1 = bias_s[co + 1];
            int gx = x0 + mf * 16 + prow;
            size_t o0 = (((size_t)batch * HW + gy) * HW + gx) * 64 + co;
            float f0 = fmaxf(acc[mf][nf][0] + b0, 0.f);
            float f1 = fmaxf(acc[mf][nf][1] + b1, 0.f);
            float f2 = fmaxf(acc[mf][nf][2] + b0, 0.f);
            float f3 = fmaxf(acc[mf][nf][3] + b1, 0.f);
            __half2 v0 = __float22half2_rn(make_float2(f0, f1));
            __half2 v1 = __float22half2_rn(make_float2(f2, f3));
            *(uint32_t*)&outh[o0]          = *(uint32_t*)&v0;
            *(uint32_t*)&outh[o0 + 8 * 64] = *(uint32_t*)&v1;   // gx + 8
        }
    }
}

// ---------------------------------------------------------------------------
// Head: GAP(f4) -> FC chain -> softmax -> pred_cls + argmax cls
// ---------------------------------------------------------------------------
__global__ void head_kernel(const float* __restrict__ f4,
                            const float* __restrict__ Wc1, const float* __restrict__ bc1,
                            const float* __restrict__ Wc2, const float* __restrict__ bc2,
                            const float* __restrict__ Wc3, const float* __restrict__ bc3,
                            float* __restrict__ out_pred)
{
    __shared__ float gap[256];
    __shared__ float z1[128];
    __shared__ float z2[128];
    __shared__ float logits[3];

    const int b = blockIdx.x;
    const int tid = threadIdx.x;

    const float* p = f4 + (size_t)b * 1024 * 256 + tid;
    float s0 = 0.f, s1 = 0.f, s2 = 0.f, s3 = 0.f;
    for (int i = 0; i < 1024; i += 4) {
        s0 += p[(i + 0) * 256];
        s1 += p[(i + 1) * 256];
        s2 += p[(i + 2) * 256];
        s3 += p[(i + 3) * 256];
    }
    gap[tid] = (s0 + s1 + s2 + s3) * (1.0f / 1024.0f);
    __syncthreads();

    if (tid < 128) {
        float a = bc1[tid];
#pragma unroll 8
        for (int k = 0; k < 256; ++k) a = fmaf(gap[k], Wc1[k * 128 + tid], a);
        z1[tid] = fmaxf(a, 0.f);
    }
    __syncthreads();

    if (tid < 128) {
        float a = bc2[tid];
#pragma unroll 8
        for (int k = 0; k < 128; ++k) a = fmaf(z1[k], Wc2[k * 128 + tid], a);
        z2[tid] = fmaxf(a, 0.f);
    }
    __syncthreads();

    if (tid < 3) {
        float a = bc3[tid];
        for (int k = 0; k < 128; ++k) a = fmaf(z2[k], Wc3[k * 3 + tid], a);
        logits[tid] = a;
    }
    __syncthreads();

    if (tid == 0) {
        float l0 = logits[0], l1 = logits[1], l2 = logits[2];
        float m = fmaxf(l0, fmaxf(l1, l2));
        float e0 = expf(l0 - m), e1 = expf(l1 - m), e2 = expf(l2 - m);
        float inv = 1.f / (e0 + e1 + e2);
        out_pred[b * 3 + 0] = e0 * inv;
        out_pred[b * 3 + 1] = e1 * inv;
        out_pred[b * 3 + 2] = e2 * inv;
        int c = 0; float best = l0;
        if (l1 > best) { best = l1; c = 1; }
        if (l2 > best) { best = l2; c = 2; }
        g_cls[b] = c;
    }
}

// ---------------------------------------------------------------------------
// Final convs fused with channel gather; fp16 inputs, fp16 smem tiles (occ 2).
// ---------------------------------------------------------------------------
__global__ void __launch_bounds__(256, 2)
conv3_select(const __half* __restrict__ h2o, const __half* __restrict__ h2w,
             const float* __restrict__ Wo3, const float* __restrict__ bo3,
             const float* __restrict__ Ww3, const float* __restrict__ bw3,
             float* __restrict__ out)
{
    extern __shared__ char sm3[];
    __half* ho = (__half*)sm3;                 // 64 * 342  (ci-major, pitch 19)
    __half* hw = ho + 64 * 342;
    float*  ws = (float*)(hw + 64 * 342);      // 576 * 3 selected weights

    const int b   = blockIdx.z;
    const int y0  = blockIdx.y * 16;
    const int x0  = blockIdx.x * 16;
    const int tid = threadIdx.x;
    const int cls = g_cls[b];

    for (int i = tid; i < 576; i += 256) {
        ws[i * 3 + 0] = Wo3[i * 6 + 2 * cls];
        ws[i * 3 + 1] = Wo3[i * 6 + 2 * cls + 1];
        ws[i * 3 + 2] = Ww3[i * 3 + cls];
    }

    const __half* po = h2o + (size_t)b * HW * HW * 64;
    const __half* pw = h2w + (size_t)b * HW * HW * 64;
    for (int i = tid; i < 324 * 8; i += 256) {
        int ci8 = i & 7;                 // chunk of 8 ci
        int rc  = i >> 3;
        int r = rc / 18, c = rc % 18;
        int gy = y0 + r - 1, gx = x0 + c - 1;
        uint4 vo = make_uint4(0, 0, 0, 0), vw = vo;
        if ((unsigned)gy < HW && (unsigned)gx < HW) {
            size_t g = ((size_t)gy * HW + gx) * 64 + ci8 * 8;
            vo = *(const uint4*)&po[g];
            vw = *(const uint4*)&pw[g];
        }
        int base = r * 19 + c;
        const __half* vo_h = (const __half*)&vo;
        const __half* vw_h = (const __half*)&vw;
#pragma unroll
        for (int j = 0; j < 8; ++j) {
            ho[(ci8 * 8 + j) * 342 + base] = vo_h[j];
            hw[(ci8 * 8 + j) * 342 + base] = vw_h[j];
        }
    }
    __syncthreads();

    const int r = tid >> 4, c = tid & 15;
    float o0 = bo3[2 * cls], o1 = bo3[2 * cls + 1], wv = bw3[cls];

#pragma unroll 1
    for (int ky = 0; ky < 3; ++ky) {
#pragma unroll 1
        for (int kx = 0; kx < 3; ++kx) {
            int base = (r + ky) * 19 + (c + kx);
            const float* wp = &ws[(ky * 3 + kx) * 64 * 3];
#pragma unroll 8
            for (int ci = 0; ci < 64; ++ci) {
                float ao = __half2float(ho[ci * 342 + base]);
                float aw = __half2float(hw[ci * 342 + base]);
                o0 = fmaf(ao, wp[ci * 3 + 0], o0);
                o1 = fmaf(ao, wp[ci * 3 + 1], o1);
                wv = fmaf(aw, wp[ci * 3 + 2], wv);
            }
        }
    }

    int gy = y0 + r, gx = x0 + c;
    size_t pix = ((size_t)b * HW + gy) * HW + gx;
    *(float2*)&out[pix * 2] = make_float2(o0, o1);
    out[(size_t)BATCH * HW * HW * 2 + pix] = wv;
}

// ---------------------------------------------------------------------------
extern "C" void kernel_launch(void* const* d_in, const int* in_sizes, int n_in,
                              void* d_out, int out_size)
{
    (void)in_sizes; (void)n_in; (void)out_size;
    const float* x0  = (const float*)d_in[0];
    const float* f4  = (const float*)d_in[1];
    const float* Wo1 = (const float*)d_in[2];
    const float* bo1 = (const float*)d_in[3];
    const float* Wo2 = (const float*)d_in[4];
    const float* bo2 = (const float*)d_in[5];
    const float* Wo3 = (const float*)d_in[6];
    const float* bo3 = (const float*)d_in[7];
    const float* Ww1 = (const float*)d_in[8];
    const float* bw1 = (const float*)d_in[9];
    const float* Ww2 = (const float*)d_in[10];
    const float* bw2 = (const float*)d_in[11];
    const float* Ww3 = (const float*)d_in[12];
    const float* bw3 = (const float*)d_in[13];
    const float* Wc1 = (const float*)d_in[14];
    const float* bc1 = (const float*)d_in[15];
    const float* Wc2 = (const float*)d_in[16];
    const float* bc2 = (const float*)d_in[17];
    const float* Wc3 = (const float*)d_in[18];
    const float* bc3 = (const float*)d_in[19];
    float* out = (float*)d_out;

    void *pH1o, *pH1w, *pH2o, *pH2w, *pW1o, *pW1w, *pW2o, *pW2w;
    cudaGetSymbolAddress(&pH1o, g_h1o);
    cudaGetSymbolAddress(&pH1w, g_h1w);
    cudaGetSymbolAddress(&pH2o, g_h2o);
    cudaGetSymbolAddress(&pH2w, g_h2w);
    cudaGetSymbolAddress(&pW1o, g_wp1o);
    cudaGetSymbolAddress(&pW1w, g_wp1w);
    cudaGetSymbolAddress(&pW2o, g_wp2o);
    cudaGetSymbolAddress(&pW2w, g_wp2w);

    const size_t smem1 = 256 + (size_t)340 * 80 + (size_t)192 * 80;           //  41.8 KB
    const size_t smem2 = 256 + (size_t)340 * 144 + (size_t)192 * 144;         //  75.1 KB
    const size_t smem3 = (size_t)(2 * 64 * 342) * 2 + 576 * 3 * 4;            //  92.3 KB

    cudaFuncSetAttribute((const void*)conv3x3_rows<32, false>,
                         cudaFuncAttributeMaxDynamicSharedMemorySize, (int)smem1);
    cudaFuncSetAttribute((const void*)conv3x3_rows<64, true>,
                         cudaFuncAttributeMaxDynamicSharedMemorySize, (int)smem2);
    cudaFuncSetAttribute((const void*)conv3_select,
                         cudaFuncAttributeMaxDynamicSharedMemorySize, (int)smem3);

    float* pred = out + (size_t)BATCH * HW * HW * 3;

    head_kernel<<<BATCH, 256>>>(f4, Wc1, bc1, Wc2, bc2, Wc3, bc3, pred);
    prep_all<<<dim3(36, 4), 256>>>(Wo1, Ww1, Wo2, Ww2,
                                   (__half*)pW1o, (__half*)pW1w,
                                   (__half*)pW2o, (__half*)pW2w);

    dim3 gconv(HW / 32, HW / 8, 2 * BATCH);   // 16 x-tiles, 64 row-groups, 8 (branch,batch)
    conv3x3_rows<32, false><<<gconv, 256, smem1>>>(
        x0, x0, (__half*)pW1o, (__half*)pW1w, bo1, bw1,
        (__half*)pH1o, (__half*)pH1w);
    conv3x3_rows<64, true><<<gconv, 256, smem2>>>(
        pH1o, pH1w, (__half*)pW2o, (__half*)pW2w, bo2, bw2,
        (__half*)pH2o, (__half*)pH2w);

    dim3 g3(HW / 16, HW / 16, BATCH);
    conv3_select<<<g3, 256, smem3>>>((__half*)pH2o, (__half*)pH2w,
                                     Wo3, bo3, Ww3, bw3, out);
}

// round 14
// speedup vs baseline: 2.9192x; 1.0992x over previous
#include <cuda_runtime.h>
#include <cuda_fp16.h>
#include <math.h>
#include <stdint.h>

#define BATCH 4
#define HW    512
#define CMID  64

// ---------------------------------------------------------------------------
// Scratch (allocation-free rule: __device__ globals)
// ---------------------------------------------------------------------------
__device__ __align__(256) __half g_h1o[(size_t)BATCH * HW * HW * CMID];   // conv1 offsets out
__device__ __align__(256) __half g_h1w[(size_t)BATCH * HW * HW * CMID];   // conv1 weights out
__device__ __align__(256) __half g_h2o[(size_t)BATCH * HW * HW * CMID];   // conv2 offsets out
__device__ __align__(256) __half g_h2w[(size_t)BATCH * HW * HW * CMID];   // conv2 weights out
__device__ __align__(256) __half g_wp1o[9 * 64 * 32];
__device__ __align__(256) __half g_wp1w[9 * 64 * 32];
__device__ __align__(256) __half g_wp2o[9 * 64 * 64];
__device__ __align__(256) __half g_wp2w[9 * 64 * 64];
__device__ int g_cls[BATCH];

__device__ __forceinline__ uint32_t smem_u32(const void* p) {
    uint32_t a;
    asm("{ .reg .u64 t; cvta.to.shared.u64 t, %1; cvt.u32.u64 %0, t; }"
        : "=r"(a) : "l"(p));
    return a;
}
__device__ __forceinline__ void ldm_x4(uint32_t* r, uint32_t addr) {
    asm volatile("ldmatrix.sync.aligned.m8n8.x4.shared.b16 {%0,%1,%2,%3}, [%4];"
                 : "=r"(r[0]), "=r"(r[1]), "=r"(r[2]), "=r"(r[3]) : "r"(addr));
}
__device__ __forceinline__ void mma16816(float* d, const uint32_t* a, const uint32_t* b) {
    asm volatile(
        "mma.sync.aligned.m16n8k16.row.col.f32.f16.f16.f32 "
        "{%0,%1,%2,%3}, {%4,%5,%6,%7}, {%8,%9}, {%0,%1,%2,%3};"
        : "+f"(d[0]), "+f"(d[1]), "+f"(d[2]), "+f"(d[3])
        : "r"(a[0]), "r"(a[1]), "r"(a[2]), "r"(a[3]), "r"(b[0]), "r"(b[1]));
}
// 16B async copy; src_sz = 16 (copy) or 0 (zero-fill 16B)
__device__ __forceinline__ void cp16(uint32_t dst, const void* src, int src_sz) {
    asm volatile("cp.async.ca.shared.global [%0], [%1], 16, %2;"
                 :: "r"(dst), "l"(src), "r"(src_sz) : "memory");
}
__device__ __forceinline__ void cp_commit() {
    asm volatile("cp.async.commit_group;" ::: "memory");
}
__device__ __forceinline__ void cp_wait_all() {
    asm volatile("cp.async.wait_group 0;" ::: "memory");
}

// ---------------------------------------------------------------------------
// Weight prep (all 4 tensors in ONE launch; blockIdx.y selects tensor):
// HWIO fp32 w[(tap*CIN+ci)*64+co] -> wp[(tap*64 + co)*CIN + ci]
// ---------------------------------------------------------------------------
__global__ void prep_all(const float* __restrict__ Wo1, const float* __restrict__ Ww1,
                         const float* __restrict__ Wo2, const float* __restrict__ Ww2,
                         __half* __restrict__ p1o, __half* __restrict__ p1w,
                         __half* __restrict__ p2o, __half* __restrict__ p2w)
{
    const int sel = blockIdx.y;
    const float* w  = sel == 0 ? Wo1 : sel == 1 ? Ww1 : sel == 2 ? Wo2 : Ww2;
    __half*      wp = sel == 0 ? p1o : sel == 1 ? p1w : sel == 2 ? p2o : p2w;
    const int CIN = (sel < 2) ? 32 : 64;

    int total = 9 * CIN * 64;
    for (int i = blockIdx.x * 256 + threadIdx.x; i < total; i += gridDim.x * 256) {
        int co  = i % 64;
        int ci  = (i / 64) % CIN;
        int tap = i / (64 * CIN);
        wp[((size_t)tap * 64 + co) * CIN + ci] = __float2half_rn(w[i]);
    }
}

// ---------------------------------------------------------------------------
// 3x3 SAME conv, CIN -> 64, ReLU, full-fp16 mma.sync (fp32 accum), fp16 out.
// Both branches in ONE launch: gridDim.z = 2*BATCH, branch = bz / BATCH.
// Block: M = 8 output rows x 32 px (=256 outputs), N = 64 co.
// 8 warps; warp wid owns output row wid: warp tile 32(M) x 64(N).
// CIN==32: ALL 9 B taps staged once -> no inner-loop syncs at all.
// CIN==64: B double-buffered, prefetch ky+1 overlaps ky's MMAs.
// ---------------------------------------------------------------------------
template <int CIN, bool HALF_IN>
__global__ void __launch_bounds__(256, 2)
conv3x3_rows(const void* __restrict__ in0, const void* __restrict__ in1,
             const __half* __restrict__ wp0, const __half* __restrict__ wp1,
             const float* __restrict__ bias0, const float* __restrict__ bias1,
             __half* __restrict__ out0, __half* __restrict__ out1)
{
    constexpr int ADATA  = CIN * 2;          // bytes per A pixel row
    constexpr int APITCH = ADATA + 16;       // conv2: 144, conv1: 80
    constexpr int BPITCH = CIN * 2 + 16;
    constexpr int KSTEPS = CIN / 16;
    constexpr int NPX    = 10 * 34;          // 340 staged pixels
    constexpr bool ALLB  = (CIN == 32);      // conv1: all taps resident
    constexpr int BSZ    = 3 * 64 * BPITCH;  // one ky-group of B

    extern __shared__ char sm[];
    float* bias_s = (float*)sm;              // 256 B
    char*  As = sm + 256;                    // NPX * APITCH
    char*  Bs = As + NPX * APITCH;           // ALLB ? 9*64*BPITCH : 2*BSZ

    const int tid  = threadIdx.x;
    const int lane = tid & 31;
    const int wm   = tid >> 5;        // output row 0..7
    const int x0   = blockIdx.x * 32;
    const int y0   = blockIdx.y * 8;
    const int bz   = blockIdx.z;
    const int batch = bz & (BATCH - 1);
    const int br    = bz >> 2;        // 0 = offsets branch, 1 = weights branch

    const void*   in   = br ? in1 : in0;
    const __half* wp   = br ? wp1 : wp0;
    const float*  bias = br ? bias1 : bias0;
    __half*       outh = br ? out1 : out0;

    if (tid < 64) bias_s[tid] = bias[tid];

    float acc[2][8][4];
#pragma unroll
    for (int mf = 0; mf < 2; ++mf)
#pragma unroll
        for (int nf = 0; nf < 8; ++nf)
#pragma unroll
            for (int q = 0; q < 4; ++q) acc[mf][nf][q] = 0.f;

    const uint32_t AsU = smem_u32(As);
    const uint32_t BsU = smem_u32(Bs);

    // --- stage A once: 10 input rows (y0-1 .. y0+8) x 34 px
    if (HALF_IN) {
        const __half* ib = (const __half*)in + (size_t)batch * HW * HW * CIN;
        constexpr int CH = CIN / 8;          // 16B chunks per pixel
        for (int i = tid; i < NPX * CH; i += 256) {
            int c   = i % CH;
            int px  = i / CH;
            int irow = px / 34, col = px % 34;
            int gy = y0 - 1 + irow;
            int gx = x0 - 1 + col;
            bool ok = (unsigned)gy < HW && (unsigned)gx < HW;
            int cgy = ok ? gy : 0, cgx = ok ? gx : 0;
            cp16(AsU + px * APITCH + c * 16,
                 ib + ((size_t)cgy * HW + cgx) * CIN + c * 8, ok ? 16 : 0);
        }
    } else {
        const float* ib = (const float*)in + (size_t)batch * HW * HW * CIN;
        for (int i = tid; i < NPX * (CIN / 4); i += 256) {
            int ci4 = i % (CIN / 4);
            int px  = i / (CIN / 4);
            int irow = px / 34, c = px % 34;
            int gy = y0 - 1 + irow;
            int gx = x0 - 1 + c;
            float4 v = make_float4(0.f, 0.f, 0.f, 0.f);
            if ((unsigned)gy < HW && (unsigned)gx < HW)
                v = *(const float4*)&ib[((size_t)gy * HW + gx) * CIN + ci4 * 4];
            __half2 h0 = __float22half2_rn(make_float2(v.x, v.y));
            __half2 h1 = __float22half2_rn(make_float2(v.z, v.w));
            *(uint2*)(As + px * APITCH + ci4 * 8) =
                make_uint2(*(uint32_t*)&h0, *(uint32_t*)&h1);
        }
    }

    // --- B staging via cp.async
    constexpr int CH = CIN / 8;                 // uint4 chunks per row
    auto stage_B3 = [&](int ky, uint32_t dstBase) {   // 3 taps of row ky
        for (int i = tid; i < 3 * 64 * CH; i += 256) {
            int c   = i % CH;
            int row = (i / CH) & 63;
            int tap = i / (CH * 64);
            cp16(dstBase + (tap * 64 + row) * BPITCH + c * 16,
                 wp + ((size_t)(ky * 3 + tap) * 64 + row) * CIN + c * 8, 16);
        }
    };

    if (ALLB) {
        // all 9 taps at once
        for (int i = tid; i < 9 * 64 * CH; i += 256) {
            int c   = i % CH;
            int row = (i / CH) & 63;
            int tap = i / (CH * 64);
            cp16(BsU + (tap * 64 + row) * BPITCH + c * 16,
                 wp + ((size_t)tap * 64 + row) * CIN + c * 8, 16);
        }
    } else {
        stage_B3(0, BsU);
    }
    cp_commit();
    cp_wait_all();
    __syncthreads();

    const int brow_in = (lane & 7) + ((lane >> 4) & 1) * 8;
    const int bcol    = ((lane >> 3) & 1) * 16;
    const int acol    = (lane >> 4) * 16;
    const int apx     = (lane & 15);

    for (int ky = 0; ky < 3; ++ky) {
        // prefetch next ky's B into the other buffer (overlaps MMAs below)
        if (!ALLB && ky < 2) {
            stage_B3(ky + 1, BsU + ((ky + 1) & 1) * BSZ);
            cp_commit();
        }
        const uint32_t Bbase = ALLB ? (BsU + ky * BSZ) : (BsU + (ky & 1) * BSZ);

#pragma unroll
        for (int kx = 0; kx < 3; ++kx) {
#pragma unroll
            for (int ks = 0; ks < KSTEPS; ++ks) {
                uint32_t a_r[2][4];
#pragma unroll
                for (int mf = 0; mf < 2; ++mf) {
                    int px = (wm + ky) * 34 + mf * 16 + apx + kx;
                    ldm_x4(a_r[mf], AsU + (uint32_t)(px * APITCH + ks * 32 + acol));
                }
                uint32_t b_r[4][4];
#pragma unroll
                for (int nh = 0; nh < 4; ++nh) {
                    int row = nh * 16 + brow_in;
                    ldm_x4(b_r[nh], Bbase + (uint32_t)((kx * 64 + row) * BPITCH + ks * 32 + bcol));
                }
#pragma unroll
                for (int mf = 0; mf < 2; ++mf)
#pragma unroll
                    for (int nf = 0; nf < 8; ++nf)
                        mma16816(acc[mf][nf], a_r[mf], &b_r[nf >> 1][(nf & 1) * 2]);
            }
        }
        if (!ALLB && ky < 2) {
            cp_wait_all();     // prefetched B landed
            __syncthreads();   // all warps done reading old buffer + new B visible
        }
    }

    // --- epilogue: bias + relu, fp16 NHWC store
    const int prow  = lane >> 2;
    const int cbase = 2 * (lane & 3);
    const int gy    = y0 + wm;
#pragma unroll
    for (int mf = 0; mf < 2; ++mf) {
#pragma unroll
        for (int nf = 0; nf < 8; ++nf) {
            int co = cbase + nf * 8;
            float b0 = bias_s[co], b1 = bias_s[co + 1];
            int gx = x0 + mf * 16 + prow;
            size_t o0 = (((size_t)batch * HW + gy) * HW + gx) * 64 + co;
            float f0 = fmaxf(acc[mf][nf][0] + b0, 0.f);
            float f1 = fmaxf(acc[mf][nf][1] + b1, 0.f);
            float f2 = fmaxf(acc[mf][nf][2] + b0, 0.f);
            float f3 = fmaxf(acc[mf][nf][3] + b1, 0.f);
            __half2 v0 = __float22half2_rn(make_float2(f0, f1));
            __half2 v1 = __float22half2_rn(make_float2(f2, f3));
            *(uint32_t*)&outh[o0]          = *(uint32_t*)&v0;
            *(uint32_t*)&outh[o0 + 8 * 64] = *(uint32_t*)&v1;   // gx + 8
        }
    }
}

// ---------------------------------------------------------------------------
// Head: GAP(f4) -> FC chain -> softmax -> pred_cls + argmax cls
// ---------------------------------------------------------------------------
__global__ void head_kernel(const float* __restrict__ f4,
                            const float* __restrict__ Wc1, const float* __restrict__ bc1,
                            const float* __restrict__ Wc2, const float* __restrict__ bc2,
                            const float* __restrict__ Wc3, const float* __restrict__ bc3,
                            float* __restrict__ out_pred)
{
    __shared__ float gap[256];
    __shared__ float z1[128];
    __shared__ float z2[128];
    __shared__ float logits[3];

    const int b = blockIdx.x;
    const int tid = threadIdx.x;

    const float* p = f4 + (size_t)b * 1024 * 256 + tid;
    float s0 = 0.f, s1 = 0.f, s2 = 0.f, s3 = 0.f;
    for (int i = 0; i < 1024; i += 4) {
        s0 += p[(i + 0) * 256];
        s1 += p[(i + 1) * 256];
        s2 += p[(i + 2) * 256];
        s3 += p[(i + 3) * 256];
    }
    gap[tid] = (s0 + s1 + s2 + s3) * (1.0f / 1024.0f);
    __syncthreads();

    if (tid < 128) {
        float a = bc1[tid];
#pragma unroll 8
        for (int k = 0; k < 256; ++k) a = fmaf(gap[k], Wc1[k * 128 + tid], a);
        z1[tid] = fmaxf(a, 0.f);
    }
    __syncthreads();

    if (tid < 128) {
        float a = bc2[tid];
#pragma unroll 8
        for (int k = 0; k < 128; ++k) a = fmaf(z1[k], Wc2[k * 128 + tid], a);
        z2[tid] = fmaxf(a, 0.f);
    }
    __syncthreads();

    if (tid < 3) {
        float a = bc3[tid];
        for (int k = 0; k < 128; ++k) a = fmaf(z2[k], Wc3[k * 3 + tid], a);
        logits[tid] = a;
    }
    __syncthreads();

    if (tid == 0) {
        float l0 = logits[0], l1 = logits[1], l2 = logits[2];
        float m = fmaxf(l0, fmaxf(l1, l2));
        float e0 = expf(l0 - m), e1 = expf(l1 - m), e2 = expf(l2 - m);
        float inv = 1.f / (e0 + e1 + e2);
        out_pred[b * 3 + 0] = e0 * inv;
        out_pred[b * 3 + 1] = e1 * inv;
        out_pred[b * 3 + 2] = e2 * inv;
        int c = 0; float best = l0;
        if (l1 > best) { best = l1; c = 1; }
        if (l2 > best) { best = l2; c = 2; }
        g_cls[b] = c;
    }
}

// ---------------------------------------------------------------------------
// Final convs fused with channel gather; fp16 inputs, px-major fp16 tiles
// (pure cp.async staging, vector LDS in compute). FMA order over ci unchanged
// vs previous rounds -> bit-identical results.
// ---------------------------------------------------------------------------
__global__ void __launch_bounds__(256, 2)
conv3_select(const __half* __restrict__ h2o, const __half* __restrict__ h2w,
             const float* __restrict__ Wo3, const float* __restrict__ bo3,
             const float* __restrict__ Ww3, const float* __restrict__ bw3,
             float* __restrict__ out)
{
    constexpr int PITCH = 64 * 2 + 16;      // 144 B per pixel row
    extern __shared__ char sm3[];
    char*  ho = sm3;                        // 324 * PITCH
    char*  hw = ho + 324 * PITCH;           // 324 * PITCH
    float* ws = (float*)(hw + 324 * PITCH); // 576 * 3 selected weights

    const int b   = blockIdx.z;
    const int y0  = blockIdx.y * 16;
    const int x0  = blockIdx.x * 16;
    const int tid = threadIdx.x;
    const int cls = g_cls[b];

    for (int i = tid; i < 576; i += 256) {
        ws[i * 3 + 0] = Wo3[i * 6 + 2 * cls];
        ws[i * 3 + 1] = Wo3[i * 6 + 2 * cls + 1];
        ws[i * 3 + 2] = Ww3[i * 3 + cls];
    }

    const uint32_t hoU = smem_u32(ho);
    const uint32_t hwU = smem_u32(hw);
    const __half* po = h2o + (size_t)b * HW * HW * 64;
    const __half* pw = h2w + (size_t)b * HW * HW * 64;
    for (int i = tid; i < 324 * 8; i += 256) {
        int c  = i & 7;                 // 16B chunk (8 ci)
        int px = i >> 3;
        int r = px / 18, cc = px % 18;
        int gy = y0 + r - 1, gx = x0 + cc - 1;
        bool ok = (unsigned)gy < HW && (unsigned)gx < HW;
        int cgy = ok ? gy : 0, cgx = ok ? gx : 0;
        size_t g = ((size_t)cgy * HW + cgx) * 64 + c * 8;
        cp16(hoU + px * PITCH + c * 16, po + g, ok ? 16 : 0);
        cp16(hwU + px * PITCH + c * 16, pw + g, ok ? 16 : 0);
    }
    cp_commit();
    cp_wait_all();
    __syncthreads();

    const int r = tid >> 4, c = tid & 15;
    float o0 = bo3[2 * cls], o1 = bo3[2 * cls + 1], wv = bw3[cls];

#pragma unroll 1
    for (int ky = 0; ky < 3; ++ky) {
#pragma unroll 1
        for (int kx = 0; kx < 3; ++kx) {
            int px = (r + ky) * 18 + (c + kx);
            const char* hop = ho + px * PITCH;
            const char* hwp = hw + px * PITCH;
            const float* wp = &ws[(ky * 3 + kx) * 64 * 3];
#pragma unroll
            for (int ch = 0; ch < 8; ++ch) {
                uint4 vo = *(const uint4*)(hop + ch * 16);
                uint4 vw = *(const uint4*)(hwp + ch * 16);
                const __half* oh = (const __half*)&vo;
                const __half* wh = (const __half*)&vw;
#pragma unroll
                for (int j = 0; j < 8; ++j) {
                    int ci = ch * 8 + j;
                    float ao = __half2float(oh[j]);
                    float aw = __half2float(wh[j]);
                    o0 = fmaf(ao, wp[ci * 3 + 0], o0);
                    o1 = fmaf(ao, wp[ci * 3 + 1], o1);
                    wv = fmaf(aw, wp[ci * 3 + 2], wv);
                }
            }
        }
    }

    int gy = y0 + r, gx = x0 + c;
    size_t pix = ((size_t)b * HW + gy) * HW + gx;
    *(float2*)&out[pix * 2] = make_float2(o0, o1);
    out[(size_t)BATCH * HW * HW * 2 + pix] = wv;
}

// ---------------------------------------------------------------------------
extern "C" void kernel_launch(void* const* d_in, const int* in_sizes, int n_in,
                              void* d_out, int out_size)
{
    (void)in_sizes; (void)n_in; (void)out_size;
    const float* x0  = (const float*)d_in[0];
    const float* f4  = (const float*)d_in[1];
    const float* Wo1 = (const float*)d_in[2];
    const float* bo1 = (const float*)d_in[3];
    const float* Wo2 = (const float*)d_in[4];
    const float* bo2 = (const float*)d_in[5];
    const float* Wo3 = (const float*)d_in[6];
    const float* bo3 = (const float*)d_in[7];
    const float* Ww1 = (const float*)d_in[8];
    const float* bw1 = (const float*)d_in[9];
    const float* Ww2 = (const float*)d_in[10];
    const float* bw2 = (const float*)d_in[11];
    const float* Ww3 = (const float*)d_in[12];
    const float* bw3 = (const float*)d_in[13];
    const float* Wc1 = (const float*)d_in[14];
    const float* bc1 = (const float*)d_in[15];
    const float* Wc2 = (const float*)d_in[16];
    const float* bc2 = (const float*)d_in[17];
    const float* Wc3 = (const float*)d_in[18];
    const float* bc3 = (const float*)d_in[19];
    float* out = (float*)d_out;

    void *pH1o, *pH1w, *pH2o, *pH2w, *pW1o, *pW1w, *pW2o, *pW2w;
    cudaGetSymbolAddress(&pH1o, g_h1o);
    cudaGetSymbolAddress(&pH1w, g_h1w);
    cudaGetSymbolAddress(&pH2o, g_h2o);
    cudaGetSymbolAddress(&pH2w, g_h2w);
    cudaGetSymbolAddress(&pW1o, g_wp1o);
    cudaGetSymbolAddress(&pW1w, g_wp1w);
    cudaGetSymbolAddress(&pW2o, g_wp2o);
    cudaGetSymbolAddress(&pW2w, g_wp2w);

    const size_t smem1 = 256 + (size_t)340 * 80 + (size_t)9 * 64 * 80;        //  71.8 KB
    const size_t smem2 = 256 + (size_t)340 * 144 + (size_t)2 * 3 * 64 * 144;  // 102.1 KB
    const size_t smem3 = (size_t)2 * 324 * 144 + 576 * 3 * 4;                 //  97.9 KB

    cudaFuncSetAttribute((const void*)conv3x3_rows<32, false>,
                         cudaFuncAttributeMaxDynamicSharedMemorySize, (int)smem1);
    cudaFuncSetAttribute((const void*)conv3x3_rows<64, true>,
                         cudaFuncAttributeMaxDynamicSharedMemorySize, (int)smem2);
    cudaFuncSetAttribute((const void*)conv3_select,
                         cudaFuncAttributeMaxDynamicSharedMemorySize, (int)smem3);

    float* pred = out + (size_t)BATCH * HW * HW * 3;

    head_kernel<<<BATCH, 256>>>(f4, Wc1, bc1, Wc2, bc2, Wc3, bc3, pred);
    prep_all<<<dim3(36, 4), 256>>>(Wo1, Ww1, Wo2, Ww2,
                                   (__half*)pW1o, (__half*)pW1w,
                                   (__half*)pW2o, (__half*)pW2w);

    dim3 gconv(HW / 32, HW / 8, 2 * BATCH);   // 16 x-tiles, 64 row-groups, 8 (branch,batch)
    conv3x3_rows<32, false><<<gconv, 256, smem1>>>(
        x0, x0, (__half*)pW1o, (__half*)pW1w, bo1, bw1,
        (__half*)pH1o, (__half*)pH1w);
    conv3x3_rows<64, true><<<gconv, 256, smem2>>>(
        pH1o, pH1w, (__half*)pW2o, (__half*)pW2w, bo2, bw2,
        (__half*)pH2o, (__half*)pH2w);

    dim3 g3(HW / 16, HW / 16, BATCH);
    conv3_select<<<g3, 256, smem3>>>((__half*)pH2o, (__half*)pH2w,
                                     Wo3, bo3, Ww3, bw3, out);
}

// round 15
// speedup vs baseline: 3.0188x; 1.0341x over previous
#include <cuda_runtime.h>
#include <cuda_fp16.h>
#include <math.h>
#include <stdint.h>

#define BATCH 4
#define HW    512
#define CMID  64

// ---------------------------------------------------------------------------
// Scratch (allocation-free rule: __device__ globals)
// ---------------------------------------------------------------------------
__device__ __align__(256) __half g_h1o[(size_t)BATCH * HW * HW * CMID];   // conv1 offsets out
__device__ __align__(256) __half g_h1w[(size_t)BATCH * HW * HW * CMID];   // conv1 weights out
__device__ __align__(256) __half g_h2o[(size_t)BATCH * HW * HW * CMID];   // conv2 offsets out
__device__ __align__(256) __half g_h2w[(size_t)BATCH * HW * HW * CMID];   // conv2 weights out
__device__ __align__(256) __half g_wp1o[9 * 64 * 32];
__device__ __align__(256) __half g_wp1w[9 * 64 * 32];
__device__ __align__(256) __half g_wp2o[9 * 64 * 64];
__device__ __align__(256) __half g_wp2w[9 * 64 * 64];
__device__ int g_cls[BATCH];

__device__ __forceinline__ uint32_t smem_u32(const void* p) {
    uint32_t a;
    asm("{ .reg .u64 t; cvta.to.shared.u64 t, %1; cvt.u32.u64 %0, t; }"
        : "=r"(a) : "l"(p));
    return a;
}
__device__ __forceinline__ void ldm_x4(uint32_t* r, uint32_t addr) {
    asm volatile("ldmatrix.sync.aligned.m8n8.x4.shared.b16 {%0,%1,%2,%3}, [%4];"
                 : "=r"(r[0]), "=r"(r[1]), "=r"(r[2]), "=r"(r[3]) : "r"(addr));
}
__device__ __forceinline__ void mma16816(float* d, const uint32_t* a, const uint32_t* b) {
    asm volatile(
        "mma.sync.aligned.m16n8k16.row.col.f32.f16.f16.f32 "
        "{%0,%1,%2,%3}, {%4,%5,%6,%7}, {%8,%9}, {%0,%1,%2,%3};"
        : "+f"(d[0]), "+f"(d[1]), "+f"(d[2]), "+f"(d[3])
        : "r"(a[0]), "r"(a[1]), "r"(a[2]), "r"(a[3]), "r"(b[0]), "r"(b[1]));
}
// 16B async copy; src_sz = 16 (copy) or 0 (zero-fill 16B)
__device__ __forceinline__ void cp16(uint32_t dst, const void* src, int src_sz) {
    asm volatile("cp.async.ca.shared.global [%0], [%1], 16, %2;"
                 :: "r"(dst), "l"(src), "r"(src_sz) : "memory");
}
__device__ __forceinline__ void cp_commit() {
    asm volatile("cp.async.commit_group;" ::: "memory");
}
__device__ __forceinline__ void cp_wait_all() {
    asm volatile("cp.async.wait_group 0;" ::: "memory");
}

// ---------------------------------------------------------------------------
// Weight prep (all 4 tensors in ONE launch; blockIdx.y selects tensor):
// HWIO fp32 w[(tap*CIN+ci)*64+co] -> wp[(tap*64 + co)*CIN + ci]
// ---------------------------------------------------------------------------
__global__ void prep_all(const float* __restrict__ Wo1, const float* __restrict__ Ww1,
                         const float* __restrict__ Wo2, const float* __restrict__ Ww2,
                         __half* __restrict__ p1o, __half* __restrict__ p1w,
                         __half* __restrict__ p2o, __half* __restrict__ p2w)
{
    const int sel = blockIdx.y;
    const float* w  = sel == 0 ? Wo1 : sel == 1 ? Ww1 : sel == 2 ? Wo2 : Ww2;
    __half*      wp = sel == 0 ? p1o : sel == 1 ? p1w : sel == 2 ? p2o : p2w;
    const int CIN = (sel < 2) ? 32 : 64;

    int total = 9 * CIN * 64;
    for (int i = blockIdx.x * 256 + threadIdx.x; i < total; i += gridDim.x * 256) {
        int co  = i % 64;
        int ci  = (i / 64) % CIN;
        int tap = i / (64 * CIN);
        wp[((size_t)tap * 64 + co) * CIN + ci] = __float2half_rn(w[i]);
    }
}

// ---------------------------------------------------------------------------
// 3x3 SAME conv, CIN -> 64, ReLU, full-fp16 mma.sync (fp32 accum), fp16 out.
// Both branches in ONE launch: gridDim.z = 2*BATCH, branch = bz / BATCH.
// Block: M = 8 output rows x 32 px (=256 outputs), N = 64 co.
// 8 warps; warp wid owns output row wid: warp tile 32(M) x 64(N).
// CIN==32: ALL 9 B taps staged once -> no inner-loop syncs.
// CIN==64: B double-buffered, prefetch ky+1 overlaps ky's MMAs.
// Epilogue: smem-staged (conflict-free STS.32, pitch 144B) then fully
// coalesced STG.128 -- values bit-identical to direct store.
// ---------------------------------------------------------------------------
template <int CIN, bool HALF_IN>
__global__ void __launch_bounds__(256, 2)
conv3x3_rows(const void* __restrict__ in0, const void* __restrict__ in1,
             const __half* __restrict__ wp0, const __half* __restrict__ wp1,
             const float* __restrict__ bias0, const float* __restrict__ bias1,
             __half* __restrict__ out0, __half* __restrict__ out1)
{
    constexpr int ADATA  = CIN * 2;          // bytes per A pixel row
    constexpr int APITCH = ADATA + 16;       // conv2: 144, conv1: 80
    constexpr int BPITCH = CIN * 2 + 16;
    constexpr int KSTEPS = CIN / 16;
    constexpr int NPX    = 10 * 34;          // 340 staged pixels
    constexpr bool ALLB  = (CIN == 32);      // conv1: all taps resident
    constexpr int BSZ    = 3 * 64 * BPITCH;  // one ky-group of B
    constexpr int OPITCH = 144;              // epilogue staging pitch (bytes)

    extern __shared__ char sm[];
    float* bias_s = (float*)sm;              // 256 B
    char*  As = sm + 256;                    // NPX * APITCH
    char*  Bs = As + NPX * APITCH;           // ALLB ? 9*64*BPITCH : 2*BSZ
    char*  Os = sm + 256;                    // epilogue staging (reuses As/Bs)

    const int tid  = threadIdx.x;
    const int lane = tid & 31;
    const int wm   = tid >> 5;        // output row 0..7
    const int x0   = blockIdx.x * 32;
    const int y0   = blockIdx.y * 8;
    const int bz   = blockIdx.z;
    const int batch = bz & (BATCH - 1);
    const int br    = bz >> 2;        // 0 = offsets branch, 1 = weights branch

    const void*   in   = br ? in1 : in0;
    const __half* wp   = br ? wp1 : wp0;
    const float*  bias = br ? bias1 : bias0;
    __half*       outh = br ? out1 : out0;

    if (tid < 64) bias_s[tid] = bias[tid];

    float acc[2][8][4];
#pragma unroll
    for (int mf = 0; mf < 2; ++mf)
#pragma unroll
        for (int nf = 0; nf < 8; ++nf)
#pragma unroll
            for (int q = 0; q < 4; ++q) acc[mf][nf][q] = 0.f;

    const uint32_t AsU = smem_u32(As);
    const uint32_t BsU = smem_u32(Bs);
    const uint32_t OsU = smem_u32(Os);

    // --- stage A once: 10 input rows (y0-1 .. y0+8) x 34 px
    if (HALF_IN) {
        const __half* ib = (const __half*)in + (size_t)batch * HW * HW * CIN;
        constexpr int CH = CIN / 8;          // 16B chunks per pixel
        for (int i = tid; i < NPX * CH; i += 256) {
            int c   = i % CH;
            int px  = i / CH;
            int irow = px / 34, col = px % 34;
            int gy = y0 - 1 + irow;
            int gx = x0 - 1 + col;
            bool ok = (unsigned)gy < HW && (unsigned)gx < HW;
            int cgy = ok ? gy : 0, cgx = ok ? gx : 0;
            cp16(AsU + px * APITCH + c * 16,
                 ib + ((size_t)cgy * HW + cgx) * CIN + c * 8, ok ? 16 : 0);
        }
    } else {
        const float* ib = (const float*)in + (size_t)batch * HW * HW * CIN;
        for (int i = tid; i < NPX * (CIN / 4); i += 256) {
            int ci4 = i % (CIN / 4);
            int px  = i / (CIN / 4);
            int irow = px / 34, c = px % 34;
            int gy = y0 - 1 + irow;
            int gx = x0 - 1 + c;
            float4 v = make_float4(0.f, 0.f, 0.f, 0.f);
            if ((unsigned)gy < HW && (unsigned)gx < HW)
                v = *(const float4*)&ib[((size_t)gy * HW + gx) * CIN + ci4 * 4];
            __half2 h0 = __float22half2_rn(make_float2(v.x, v.y));
            __half2 h1 = __float22half2_rn(make_float2(v.z, v.w));
            *(uint2*)(As + px * APITCH + ci4 * 8) =
                make_uint2(*(uint32_t*)&h0, *(uint32_t*)&h1);
        }
    }

    // --- B staging via cp.async
    constexpr int CH = CIN / 8;                 // uint4 chunks per row
    auto stage_B3 = [&](int ky, uint32_t dstBase) {   // 3 taps of row ky
        for (int i = tid; i < 3 * 64 * CH; i += 256) {
            int c   = i % CH;
            int row = (i / CH) & 63;
            int tap = i / (CH * 64);
            cp16(dstBase + (tap * 64 + row) * BPITCH + c * 16,
                 wp + ((size_t)(ky * 3 + tap) * 64 + row) * CIN + c * 8, 16);
        }
    };

    if (ALLB) {
        for (int i = tid; i < 9 * 64 * CH; i += 256) {
            int c   = i % CH;
            int row = (i / CH) & 63;
            int tap = i / (CH * 64);
            cp16(BsU + (tap * 64 + row) * BPITCH + c * 16,
                 wp + ((size_t)tap * 64 + row) * CIN + c * 8, 16);
        }
    } else {
        stage_B3(0, BsU);
    }
    cp_commit();
    cp_wait_all();
    __syncthreads();

    const int brow_in = (lane & 7) + ((lane >> 4) & 1) * 8;
    const int bcol    = ((lane >> 3) & 1) * 16;
    const int acol    = (lane >> 4) * 16;
    const int apx     = (lane & 15);

    for (int ky = 0; ky < 3; ++ky) {
        if (!ALLB && ky < 2) {
            stage_B3(ky + 1, BsU + ((ky + 1) & 1) * BSZ);
            cp_commit();
        }
        const uint32_t Bbase = ALLB ? (BsU + ky * BSZ) : (BsU + (ky & 1) * BSZ);

#pragma unroll
        for (int kx = 0; kx < 3; ++kx) {
#pragma unroll
            for (int ks = 0; ks < KSTEPS; ++ks) {
                uint32_t a_r[2][4];
#pragma unroll
                for (int mf = 0; mf < 2; ++mf) {
                    int px = (wm + ky) * 34 + mf * 16 + apx + kx;
                    ldm_x4(a_r[mf], AsU + (uint32_t)(px * APITCH + ks * 32 + acol));
                }
                uint32_t b_r[4][4];
#pragma unroll
                for (int nh = 0; nh < 4; ++nh) {
                    int row = nh * 16 + brow_in;
                    ldm_x4(b_r[nh], Bbase + (uint32_t)((kx * 64 + row) * BPITCH + ks * 32 + bcol));
                }
#pragma unroll
                for (int mf = 0; mf < 2; ++mf)
#pragma unroll
                    for (int nf = 0; nf < 8; ++nf)
                        mma16816(acc[mf][nf], a_r[mf], &b_r[nf >> 1][(nf & 1) * 2]);
            }
        }
        if (!ALLB && ky < 2) {
            cp_wait_all();     // prefetched B landed
            __syncthreads();   // all warps done reading old buffer + new B visible
        }
    }

    // --- epilogue: bias + relu -> smem staging (conflict-free) -> coalesced STG
    __syncthreads();   // A/B smem dead; safe to reuse as Os
    {
        const int prow  = lane >> 2;
        const int cbase = 2 * (lane & 3);
#pragma unroll
        for (int mf = 0; mf < 2; ++mf) {
#pragma unroll
            for (int nf = 0; nf < 8; ++nf) {
                int co = cbase + nf * 8;
                float b0 = bias_s[co], b1 = bias_s[co + 1];
                float f0 = fmaxf(acc[mf][nf][0] + b0, 0.f);
                float f1 = fmaxf(acc[mf][nf][1] + b1, 0.f);
                float f2 = fmaxf(acc[mf][nf][2] + b0, 0.f);
                float f3 = fmaxf(acc[mf][nf][3] + b1, 0.f);
                __half2 v0 = __float22half2_rn(make_float2(f0, f1));
                __half2 v1 = __float22half2_rn(make_float2(f2, f3));
                int opx0 = wm * 32 + mf * 16 + prow;        // local output px
                *(uint32_t*)(Os + opx0 * OPITCH + co * 2)       = *(uint32_t*)&v0;
                *(uint32_t*)(Os + (opx0 + 8) * OPITCH + co * 2) = *(uint32_t*)&v1;
            }
        }
    }
    __syncthreads();
    {
        // 256 px x 128B, threads cover consecutive 16B chunks -> 512B/warp STG
        for (int i = tid; i < 256 * 8; i += 256) {
            int c   = i & 7;
            int opx = i >> 3;
            int wmw = opx >> 5, lpx = opx & 31;
            uint4 v = *(const uint4*)(Os + opx * OPITCH + c * 16);
            size_t g = (((size_t)batch * HW + (y0 + wmw)) * HW + (x0 + lpx)) * 64 + c * 8;
            *(uint4*)&outh[g] = v;
        }
    }
    (void)OsU;
}

// ---------------------------------------------------------------------------
// Head: GAP(f4) -> FC chain -> softmax -> pred_cls + argmax cls
// ---------------------------------------------------------------------------
__global__ void head_kernel(const float* __restrict__ f4,
                            const float* __restrict__ Wc1, const float* __restrict__ bc1,
                            const float* __restrict__ Wc2, const float* __restrict__ bc2,
                            const float* __restrict__ Wc3, const float* __restrict__ bc3,
                            float* __restrict__ out_pred)
{
    __shared__ float gap[256];
    __shared__ float z1[128];
    __shared__ float z2[128];
    __shared__ float logits[3];

    const int b = blockIdx.x;
    const int tid = threadIdx.x;

    const float* p = f4 + (size_t)b * 1024 * 256 + tid;
    float s0 = 0.f, s1 = 0.f, s2 = 0.f, s3 = 0.f;
    for (int i = 0; i < 1024; i += 4) {
        s0 += p[(i + 0) * 256];
        s1 += p[(i + 1) * 256];
        s2 += p[(i + 2) * 256];
        s3 += p[(i + 3) * 256];
    }
    gap[tid] = (s0 + s1 + s2 + s3) * (1.0f / 1024.0f);
    __syncthreads();

    if (tid < 128) {
        float a = bc1[tid];
#pragma unroll 8
        for (int k = 0; k < 256; ++k) a = fmaf(gap[k], Wc1[k * 128 + tid], a);
        z1[tid] = fmaxf(a, 0.f);
    }
    __syncthreads();

    if (tid < 128) {
        float a = bc2[tid];
#pragma unroll 8
        for (int k = 0; k < 128; ++k) a = fmaf(z1[k], Wc2[k * 128 + tid], a);
        z2[tid] = fmaxf(a, 0.f);
    }
    __syncthreads();

    if (tid < 3) {
        float a = bc3[tid];
        for (int k = 0; k < 128; ++k) a = fmaf(z2[k], Wc3[k * 3 + tid], a);
        logits[tid] = a;
    }
    __syncthreads();

    if (tid == 0) {
        float l0 = logits[0], l1 = logits[1], l2 = logits[2];
        float m = fmaxf(l0, fmaxf(l1, l2));
        float e0 = expf(l0 - m), e1 = expf(l1 - m), e2 = expf(l2 - m);
        float inv = 1.f / (e0 + e1 + e2);
        out_pred[b * 3 + 0] = e0 * inv;
        out_pred[b * 3 + 1] = e1 * inv;
        out_pred[b * 3 + 2] = e2 * inv;
        int c = 0; float best = l0;
        if (l1 > best) { best = l1; c = 1; }
        if (l2 > best) { best = l2; c = 2; }
        g_cls[b] = c;
    }
}

// ---------------------------------------------------------------------------
// Final convs fused with channel gather; fp16 inputs, px-major fp16 tiles
// (pure cp.async staging, vector LDS in compute). FMA order over ci unchanged
// vs previous rounds -> bit-identical results.
// ---------------------------------------------------------------------------
__global__ void __launch_bounds__(256, 2)
conv3_select(const __half* __restrict__ h2o, const __half* __restrict__ h2w,
             const float* __restrict__ Wo3, const float* __restrict__ bo3,
             const float* __restrict__ Ww3, const float* __restrict__ bw3,
             float* __restrict__ out)
{
    constexpr int PITCH = 64 * 2 + 16;      // 144 B per pixel row
    extern __shared__ char sm3[];
    char*  ho = sm3;                        // 324 * PITCH
    char*  hw = ho + 324 * PITCH;           // 324 * PITCH
    float* ws = (float*)(hw + 324 * PITCH); // 576 * 3 selected weights

    const int b   = blockIdx.z;
    const int y0  = blockIdx.y * 16;
    const int x0  = blockIdx.x * 16;
    const int tid = threadIdx.x;
    const int cls = g_cls[b];

    for (int i = tid; i < 576; i += 256) {
        ws[i * 3 + 0] = Wo3[i * 6 + 2 * cls];
        ws[i * 3 + 1] = Wo3[i * 6 + 2 * cls + 1];
        ws[i * 3 + 2] = Ww3[i * 3 + cls];
    }

    const uint32_t hoU = smem_u32(ho);
    const uint32_t hwU = smem_u32(hw);
    const __half* po = h2o + (size_t)b * HW * HW * 64;
    const __half* pw = h2w + (size_t)b * HW * HW * 64;
    for (int i = tid; i < 324 * 8; i += 256) {
        int c  = i & 7;                 // 16B chunk (8 ci)
        int px = i >> 3;
        int r = px / 18, cc = px % 18;
        int gy = y0 + r - 1, gx = x0 + cc - 1;
        bool ok = (unsigned)gy < HW && (unsigned)gx < HW;
        int cgy = ok ? gy : 0, cgx = ok ? gx : 0;
        size_t g = ((size_t)cgy * HW + cgx) * 64 + c * 8;
        cp16(hoU + px * PITCH + c * 16, po + g, ok ? 16 : 0);
        cp16(hwU + px * PITCH + c * 16, pw + g, ok ? 16 : 0);
    }
    cp_commit();
    cp_wait_all();
    __syncthreads();

    const int r = tid >> 4, c = tid & 15;
    float o0 = bo3[2 * cls], o1 = bo3[2 * cls + 1], wv = bw3[cls];

#pragma unroll 1
    for (int ky = 0; ky < 3; ++ky) {
#pragma unroll 1
        for (int kx = 0; kx < 3; ++kx) {
            int px = (r + ky) * 18 + (c + kx);
            const char* hop = ho + px * PITCH;
            const char* hwp = hw + px * PITCH;
            const float* wp = &ws[(ky * 3 + kx) * 64 * 3];
#pragma unroll
            for (int ch = 0; ch < 8; ++ch) {
                uint4 vo = *(const uint4*)(hop + ch * 16);
                uint4 vw = *(const uint4*)(hwp + ch * 16);
                const __half* oh = (const __half*)&vo;
                const __half* wh = (const __half*)&vw;
#pragma unroll
                for (int j = 0; j < 8; ++j) {
                    int ci = ch * 8 + j;
                    float ao = __half2float(oh[j]);
                    float aw = __half2float(wh[j]);
                    o0 = fmaf(ao, wp[ci * 3 + 0], o0);
                    o1 = fmaf(ao, wp[ci * 3 + 1], o1);
                    wv = fmaf(aw, wp[ci * 3 + 2], wv);
                }
            }
        }
    }

    int gy = y0 + r, gx = x0 + c;
    size_t pix = ((size_t)b * HW + gy) * HW + gx;
    *(float2*)&out[pix * 2] = make_float2(o0, o1);
    out[(size_t)BATCH * HW * HW * 2 + pix] = wv;
}

// ---------------------------------------------------------------------------
extern "C" void kernel_launch(void* const* d_in, const int* in_sizes, int n_in,
                              void* d_out, int out_size)
{
    (void)in_sizes; (void)n_in; (void)out_size;
    const float* x0  = (const float*)d_in[0];
    const float* f4  = (const float*)d_in[1];
    const float* Wo1 = (const float*)d_in[2];
    const float* bo1 = (const float*)d_in[3];
    const float* Wo2 = (const float*)d_in[4];
    const float* bo2 = (const float*)d_in[5];
    const float* Wo3 = (const float*)d_in[6];
    const float* bo3 = (const float*)d_in[7];
    const float* Ww1 = (const float*)d_in[8];
    const float* bw1 = (const float*)d_in[9];
    const float* Ww2 = (const float*)d_in[10];
    const float* bw2 = (const float*)d_in[11];
    const float* Ww3 = (const float*)d_in[12];
    const float* bw3 = (const float*)d_in[13];
    const float* Wc1 = (const float*)d_in[14];
    const float* bc1 = (const float*)d_in[15];
    const float* Wc2 = (const float*)d_in[16];
    const float* bc2 = (const float*)d_in[17];
    const float* Wc3 = (const float*)d_in[18];
    const float* bc3 = (const float*)d_in[19];
    float* out = (float*)d_out;

    void *pH1o, *pH1w, *pH2o, *pH2w, *pW1o, *pW1w, *pW2o, *pW2w;
    cudaGetSymbolAddress(&pH1o, g_h1o);
    cudaGetSymbolAddress(&pH1w, g_h1w);
    cudaGetSymbolAddress(&pH2o, g_h2o);
    cudaGetSymbolAddress(&pH2w, g_h2w);
    cudaGetSymbolAddress(&pW1o, g_wp1o);
    cudaGetSymbolAddress(&pW1w, g_wp1w);
    cudaGetSymbolAddress(&pW2o, g_wp2o);
    cudaGetSymbolAddress(&pW2w, g_wp2w);

    const size_t smem1 = 256 + (size_t)340 * 80 + (size_t)9 * 64 * 80;        //  71.8 KB
    const size_t smem2 = 256 + (size_t)340 * 144 + (size_t)2 * 3 * 64 * 144;  // 102.1 KB
    const size_t smem3 = (size_t)2 * 324 * 144 + 576 * 3 * 4;                 //  97.9 KB

    cudaFuncSetAttribute((const void*)conv3x3_rows<32, false>,
                         cudaFuncAttributeMaxDynamicSharedMemorySize, (int)smem1);
    cudaFuncSetAttribute((const void*)conv3x3_rows<64, true>,
                         cudaFuncAttributeMaxDynamicSharedMemorySize, (int)smem2);
    cudaFuncSetAttribute((const void*)conv3_select,
                         cudaFuncAttributeMaxDynamicSharedMemorySize, (int)smem3);

    float* pred = out + (size_t)BATCH * HW * HW * 3;

    head_kernel<<<BATCH, 256>>>(f4, Wc1, bc1, Wc2, bc2, Wc3, bc3, pred);
    prep_all<<<dim3(36, 4), 256>>>(Wo1, Ww1, Wo2, Ww2,
                                   (__half*)pW1o, (__half*)pW1w,
                                   (__half*)pW2o, (__half*)pW2w);

    dim3 gconv(HW / 32, HW / 8, 2 * BATCH);   // 16 x-tiles, 64 row-groups, 8 (branch,batch)
    conv3x3_rows<32, false><<<gconv, 256, smem1>>>(
        x0, x0, (__half*)pW1o, (__half*)pW1w, bo1, bw1,
        (__half*)pH1o, (__half*)pH1w);
    conv3x3_rows<64, true><<<gconv, 256, smem2>>>(
        pH1o, pH1w, (__half*)pW2o, (__half*)pW2w, bo2, bw2,
        (__half*)pH2o, (__half*)pH2w);

    dim3 g3(HW / 16, HW / 16, BATCH);
    conv3_select<<<g3, 256, smem3>>>((__half*)pH2o, (__half*)pH2w,
                                     Wo3, bo3, Ww3, bw3, out);
}

// round 16
// speedup vs baseline: 3.6208x; 1.1994x over previous
#include <cuda_runtime.h>
#include <cuda_fp16.h>
#include <math.h>
#include <stdint.h>

#define BATCH 4
#define HW    512
#define CMID  64

// ---------------------------------------------------------------------------
// Scratch (allocation-free rule: __device__ globals)
// ---------------------------------------------------------------------------
__device__ __align__(256) __half g_h1o[(size_t)BATCH * HW * HW * CMID];   // conv1 offsets out
__device__ __align__(256) __half g_h1w[(size_t)BATCH * HW * HW * CMID];   // conv1 weights out
__device__ __align__(256) __half g_h2o[(size_t)BATCH * HW * HW * CMID];   // conv2 offsets out
__device__ __align__(256) __half g_h2w[(size_t)BATCH * HW * HW * CMID];   // conv2 weights out
__device__ __align__(256) __half g_wp1o[9 * 64 * 32];
__device__ __align__(256) __half g_wp1w[9 * 64 * 32];
__device__ __align__(256) __half g_wp2o[9 * 64 * 64];
__device__ __align__(256) __half g_wp2w[9 * 64 * 64];
__device__ int g_cls[BATCH];

__device__ __forceinline__ uint32_t smem_u32(const void* p) {
    uint32_t a;
    asm("{ .reg .u64 t; cvta.to.shared.u64 t, %1; cvt.u32.u64 %0, t; }"
        : "=r"(a) : "l"(p));
    return a;
}
__device__ __forceinline__ void ldm_x4(uint32_t* r, uint32_t addr) {
    asm volatile("ldmatrix.sync.aligned.m8n8.x4.shared.b16 {%0,%1,%2,%3}, [%4];"
                 : "=r"(r[0]), "=r"(r[1]), "=r"(r[2]), "=r"(r[3]) : "r"(addr));
}
__device__ __forceinline__ void mma16816(float* d, const uint32_t* a, const uint32_t* b) {
    asm volatile(
        "mma.sync.aligned.m16n8k16.row.col.f32.f16.f16.f32 "
        "{%0,%1,%2,%3}, {%4,%5,%6,%7}, {%8,%9}, {%0,%1,%2,%3};"
        : "+f"(d[0]), "+f"(d[1]), "+f"(d[2]), "+f"(d[3])
        : "r"(a[0]), "r"(a[1]), "r"(a[2]), "r"(a[3]), "r"(b[0]), "r"(b[1]));
}
// 16B async copy; src_sz = 16 (copy) or 0 (zero-fill 16B)
__device__ __forceinline__ void cp16(uint32_t dst, const void* src, int src_sz) {
    asm volatile("cp.async.ca.shared.global [%0], [%1], 16, %2;"
                 :: "r"(dst), "l"(src), "r"(src_sz) : "memory");
}
__device__ __forceinline__ void cp_commit() {
    asm volatile("cp.async.commit_group;" ::: "memory");
}
__device__ __forceinline__ void cp_wait_all() {
    asm volatile("cp.async.wait_group 0;" ::: "memory");
}

// ---------------------------------------------------------------------------
// Weight prep (all 4 tensors in ONE launch; blockIdx.y selects tensor):
// HWIO fp32 w[(tap*CIN+ci)*64+co] -> wp[(tap*64 + co)*CIN + ci]
// ---------------------------------------------------------------------------
__global__ void prep_all(const float* __restrict__ Wo1, const float* __restrict__ Ww1,
                         const float* __restrict__ Wo2, const float* __restrict__ Ww2,
                         __half* __restrict__ p1o, __half* __restrict__ p1w,
                         __half* __restrict__ p2o, __half* __restrict__ p2w)
{
    const int sel = blockIdx.y;
    const float* w  = sel == 0 ? Wo1 : sel == 1 ? Ww1 : sel == 2 ? Wo2 : Ww2;
    __half*      wp = sel == 0 ? p1o : sel == 1 ? p1w : sel == 2 ? p2o : p2w;
    const int CIN = (sel < 2) ? 32 : 64;

    int total = 9 * CIN * 64;
    for (int i = blockIdx.x * 256 + threadIdx.x; i < total; i += gridDim.x * 256) {
        int co  = i % 64;
        int ci  = (i / 64) % CIN;
        int tap = i / (64 * CIN);
        wp[((size_t)tap * 64 + co) * CIN + ci] = __float2half_rn(w[i]);
    }
}

// ---------------------------------------------------------------------------
// conv1: 32 -> 64, ReLU, full-fp16 mma (fp32 accum), fp16 out. PERSISTENT-B:
// each block loops 8 y-tiles, staging the full 9-tap B ONCE. Both branches
// in one launch via gridDim.z = 2*BATCH. Block tile: 8 rows x 32 px.
// ---------------------------------------------------------------------------
__global__ void __launch_bounds__(256, 2)
conv1_pers(const float* __restrict__ in,
           const __half* __restrict__ wp0, const __half* __restrict__ wp1,
           const float* __restrict__ bias0, const float* __restrict__ bias1,
           __half* __restrict__ out0, __half* __restrict__ out1)
{
    constexpr int CIN    = 32;
    constexpr int APITCH = CIN * 2 + 16;     // 80
    constexpr int BPITCH = CIN * 2 + 16;     // 80
    constexpr int NPX    = 10 * 34;          // 340
    constexpr int BSZ    = 3 * 64 * BPITCH;
    constexpr int OPITCH = 144;

    extern __shared__ char sm[];
    float* bias_s = (float*)sm;                      // 256 B
    char*  As = sm + 256;                            // 27200 B
    char*  Bs = As + NPX * APITCH;                   // 46080 B
    char*  Os = Bs + 9 * 64 * BPITCH;                // 36864 B

    const int tid  = threadIdx.x;
    const int lane = tid & 31;
    const int wm   = tid >> 5;
    const int x0   = blockIdx.x * 32;
    const int bz   = blockIdx.z;
    const int batch = bz & (BATCH - 1);
    const int br    = bz >> 2;

    const __half* wp   = br ? wp1 : wp0;
    const float*  bias = br ? bias1 : bias0;
    __half*       outh = br ? out1 : out0;
    const float*  ib   = in + (size_t)batch * HW * HW * CIN;

    if (tid < 64) bias_s[tid] = bias[tid];

    const uint32_t AsU = smem_u32(As);
    const uint32_t BsU = smem_u32(Bs);

    // --- stage ALL 9 B taps once per block
    {
        constexpr int CH = CIN / 8;   // 4
        for (int i = tid; i < 9 * 64 * CH; i += 256) {
            int c   = i % CH;
            int row = (i / CH) & 63;
            int tap = i / (CH * 64);
            cp16(BsU + (tap * 64 + row) * BPITCH + c * 16,
                 wp + ((size_t)tap * 64 + row) * CIN + c * 8, 16);
        }
        cp_commit();
        cp_wait_all();
    }

    const int brow_in = (lane & 7) + ((lane >> 4) & 1) * 8;
    const int bcol    = ((lane >> 3) & 1) * 16;
    const int acol    = (lane >> 4) * 16;
    const int apx     = (lane & 15);

    for (int it = 0; it < 8; ++it) {
        const int y0 = (blockIdx.y * 8 + it) * 8;

        // --- stage A: 10 rows x 34 px, fp32 -> fp16
        for (int i = tid; i < NPX * (CIN / 4); i += 256) {
            int ci4 = i % (CIN / 4);
            int px  = i / (CIN / 4);
            int irow = px / 34, c = px % 34;
            int gy = y0 - 1 + irow;
            int gx = x0 - 1 + c;
            float4 v = make_float4(0.f, 0.f, 0.f, 0.f);
            if ((unsigned)gy < HW && (unsigned)gx < HW)
                v = *(const float4*)&ib[((size_t)gy * HW + gx) * CIN + ci4 * 4];
            __half2 h0 = __float22half2_rn(make_float2(v.x, v.y));
            __half2 h1 = __float22half2_rn(make_float2(v.z, v.w));
            *(uint2*)(As + px * APITCH + ci4 * 8) =
                make_uint2(*(uint32_t*)&h0, *(uint32_t*)&h1);
        }
        __syncthreads();   // A ready; prior iter's Os reads done

        float acc[2][8][4];
#pragma unroll
        for (int mf = 0; mf < 2; ++mf)
#pragma unroll
            for (int nf = 0; nf < 8; ++nf)
#pragma unroll
                for (int q = 0; q < 4; ++q) acc[mf][nf][q] = 0.f;

        for (int ky = 0; ky < 3; ++ky) {
            const uint32_t Bbase = BsU + ky * BSZ;
#pragma unroll
            for (int kx = 0; kx < 3; ++kx) {
#pragma unroll
                for (int ks = 0; ks < 2; ++ks) {
                    uint32_t a_r[2][4];
#pragma unroll
                    for (int mf = 0; mf < 2; ++mf) {
                        int px = (wm + ky) * 34 + mf * 16 + apx + kx;
                        ldm_x4(a_r[mf], AsU + (uint32_t)(px * APITCH + ks * 32 + acol));
                    }
                    uint32_t b_r[4][4];
#pragma unroll
                    for (int nh = 0; nh < 4; ++nh) {
                        int row = nh * 16 + brow_in;
                        ldm_x4(b_r[nh], Bbase + (uint32_t)((kx * 64 + row) * BPITCH + ks * 32 + bcol));
                    }
#pragma unroll
                    for (int mf = 0; mf < 2; ++mf)
#pragma unroll
                        for (int nf = 0; nf < 8; ++nf)
                            mma16816(acc[mf][nf], a_r[mf], &b_r[nf >> 1][(nf & 1) * 2]);
                }
            }
        }
        __syncthreads();   // all ldm done (A may be rewritten next iter)

        // --- epilogue: bias+relu -> Os -> coalesced STG
        {
            const int prow  = lane >> 2;
            const int cbase = 2 * (lane & 3);
#pragma unroll
            for (int mf = 0; mf < 2; ++mf) {
#pragma unroll
                for (int nf = 0; nf < 8; ++nf) {
                    int co = cbase + nf * 8;
                    float b0 = bias_s[co], b1 = bias_s[co + 1];
                    float f0 = fmaxf(acc[mf][nf][0] + b0, 0.f);
                    float f1 = fmaxf(acc[mf][nf][1] + b1, 0.f);
                    float f2 = fmaxf(acc[mf][nf][2] + b0, 0.f);
                    float f3 = fmaxf(acc[mf][nf][3] + b1, 0.f);
                    __half2 v0 = __float22half2_rn(make_float2(f0, f1));
                    __half2 v1 = __float22half2_rn(make_float2(f2, f3));
                    int opx0 = wm * 32 + mf * 16 + prow;
                    *(uint32_t*)(Os + opx0 * OPITCH + co * 2)       = *(uint32_t*)&v0;
                    *(uint32_t*)(Os + (opx0 + 8) * OPITCH + co * 2) = *(uint32_t*)&v1;
                }
            }
        }
        __syncthreads();
        for (int i = tid; i < 256 * 8; i += 256) {
            int c   = i & 7;
            int opx = i >> 3;
            int wmw = opx >> 5, lpx = opx & 31;
            uint4 v = *(const uint4*)(Os + opx * OPITCH + c * 16);
            size_t g = (((size_t)batch * HW + (y0 + wmw)) * HW + (x0 + lpx)) * 64 + c * 8;
            *(uint4*)&outh[g] = v;
        }
    }
}

// ---------------------------------------------------------------------------
// conv2: 64 -> 64 (unchanged from committed R15 winner).
// ---------------------------------------------------------------------------
__global__ void __launch_bounds__(256, 2)
conv2_hmma(const __half* __restrict__ in0, const __half* __restrict__ in1,
           const __half* __restrict__ wp0, const __half* __restrict__ wp1,
           const float* __restrict__ bias0, const float* __restrict__ bias1,
           __half* __restrict__ out0, __half* __restrict__ out1)
{
    constexpr int CIN    = 64;
    constexpr int APITCH = CIN * 2 + 16;     // 144
    constexpr int BPITCH = CIN * 2 + 16;
    constexpr int KSTEPS = 4;
    constexpr int NPX    = 10 * 34;
    constexpr int BSZ    = 3 * 64 * BPITCH;
    constexpr int OPITCH = 144;

    extern __shared__ char sm[];
    float* bias_s = (float*)sm;
    char*  As = sm + 256;
    char*  Bs = As + NPX * APITCH;
    char*  Os = sm + 256;                    // epilogue staging reuses As/Bs

    const int tid  = threadIdx.x;
    const int lane = tid & 31;
    const int wm   = tid >> 5;
    const int x0   = blockIdx.x * 32;
    const int y0   = blockIdx.y * 8;
    const int bz   = blockIdx.z;
    const int batch = bz & (BATCH - 1);
    const int br    = bz >> 2;

    const __half* in   = br ? in1 : in0;
    const __half* wp   = br ? wp1 : wp0;
    const float*  bias = br ? bias1 : bias0;
    __half*       outh = br ? out1 : out0;

    if (tid < 64) bias_s[tid] = bias[tid];

    float acc[2][8][4];
#pragma unroll
    for (int mf = 0; mf < 2; ++mf)
#pragma unroll
        for (int nf = 0; nf < 8; ++nf)
#pragma unroll
            for (int q = 0; q < 4; ++q) acc[mf][nf][q] = 0.f;

    const uint32_t AsU = smem_u32(As);
    const uint32_t BsU = smem_u32(Bs);

    {
        const __half* ib = in + (size_t)batch * HW * HW * CIN;
        constexpr int CH = CIN / 8;
        for (int i = tid; i < NPX * CH; i += 256) {
            int c   = i % CH;
            int px  = i / CH;
            int irow = px / 34, col = px % 34;
            int gy = y0 - 1 + irow;
            int gx = x0 - 1 + col;
            bool ok = (unsigned)gy < HW && (unsigned)gx < HW;
            int cgy = ok ? gy : 0, cgx = ok ? gx : 0;
            cp16(AsU + px * APITCH + c * 16,
                 ib + ((size_t)cgy * HW + cgx) * CIN + c * 8, ok ? 16 : 0);
        }
    }

    constexpr int CH = CIN / 8;
    auto stage_B3 = [&](int ky, uint32_t dstBase) {
        for (int i = tid; i < 3 * 64 * CH; i += 256) {
            int c   = i % CH;
            int row = (i / CH) & 63;
            int tap = i / (CH * 64);
            cp16(dstBase + (tap * 64 + row) * BPITCH + c * 16,
                 wp + ((size_t)(ky * 3 + tap) * 64 + row) * CIN + c * 8, 16);
        }
    };

    stage_B3(0, BsU);
    cp_commit();
    cp_wait_all();
    __syncthreads();

    const int brow_in = (lane & 7) + ((lane >> 4) & 1) * 8;
    const int bcol    = ((lane >> 3) & 1) * 16;
    const int acol    = (lane >> 4) * 16;
    const int apx     = (lane & 15);

    for (int ky = 0; ky < 3; ++ky) {
        if (ky < 2) {
            stage_B3(ky + 1, BsU + ((ky + 1) & 1) * BSZ);
            cp_commit();
        }
        const uint32_t Bbase = BsU + (ky & 1) * BSZ;

#pragma unroll
        for (int kx = 0; kx < 3; ++kx) {
#pragma unroll
            for (int ks = 0; ks < KSTEPS; ++ks) {
                uint32_t a_r[2][4];
#pragma unroll
                for (int mf = 0; mf < 2; ++mf) {
                    int px = (wm + ky) * 34 + mf * 16 + apx + kx;
                    ldm_x4(a_r[mf], AsU + (uint32_t)(px * APITCH + ks * 32 + acol));
                }
                uint32_t b_r[4][4];
#pragma unroll
                for (int nh = 0; nh < 4; ++nh) {
                    int row = nh * 16 + brow_in;
                    ldm_x4(b_r[nh], Bbase + (uint32_t)((kx * 64 + row) * BPITCH + ks * 32 + bcol));
                }
#pragma unroll
                for (int mf = 0; mf < 2; ++mf)
#pragma unroll
                    for (int nf = 0; nf < 8; ++nf)
                        mma16816(acc[mf][nf], a_r[mf], &b_r[nf >> 1][(nf & 1) * 2]);
            }
        }
        if (ky < 2) {
            cp_wait_all();
            __syncthreads();
        }
    }

    __syncthreads();
    {
        const int prow  = lane >> 2;
        const int cbase = 2 * (lane & 3);
#pragma unroll
        for (int mf = 0; mf < 2; ++mf) {
#pragma unroll
            for (int nf = 0; nf < 8; ++nf) {
                int co = cbase + nf * 8;
                float b0 = bias_s[co], b1 = bias_s[co + 1];
                float f0 = fmaxf(acc[mf][nf][0] + b0, 0.f);
                float f1 = fmaxf(acc[mf][nf][1] + b1, 0.f);
                float f2 = fmaxf(acc[mf][nf][2] + b0, 0.f);
                float f3 = fmaxf(acc[mf][nf][3] + b1, 0.f);
                __half2 v0 = __float22half2_rn(make_float2(f0, f1));
                __half2 v1 = __float22half2_rn(make_float2(f2, f3));
                int opx0 = wm * 32 + mf * 16 + prow;
                *(uint32_t*)(Os + opx0 * OPITCH + co * 2)       = *(uint32_t*)&v0;
                *(uint32_t*)(Os + (opx0 + 8) * OPITCH + co * 2) = *(uint32_t*)&v1;
            }
        }
    }
    __syncthreads();
    for (int i = tid; i < 256 * 8; i += 256) {
        int c   = i & 7;
        int opx = i >> 3;
        int wmw = opx >> 5, lpx = opx & 31;
        uint4 v = *(const uint4*)(Os + opx * OPITCH + c * 16);
        size_t g = (((size_t)batch * HW + (y0 + wmw)) * HW + (x0 + lpx)) * 64 + c * 8;
        *(uint4*)&outh[g] = v;
    }
}

// ---------------------------------------------------------------------------
// Head: GAP(f4) -> FC chain -> softmax -> pred_cls + argmax cls
// ---------------------------------------------------------------------------
__global__ void head_kernel(const float* __restrict__ f4,
                            const float* __restrict__ Wc1, const float* __restrict__ bc1,
                            const float* __restrict__ Wc2, const float* __restrict__ bc2,
                            const float* __restrict__ Wc3, const float* __restrict__ bc3,
                            float* __restrict__ out_pred)
{
    __shared__ float gap[256];
    __shared__ float z1[128];
    __shared__ float z2[128];
    __shared__ float logits[3];

    const int b = blockIdx.x;
    const int tid = threadIdx.x;

    const float* p = f4 + (size_t)b * 1024 * 256 + tid;
    float s0 = 0.f, s1 = 0.f, s2 = 0.f, s3 = 0.f;
    for (int i = 0; i < 1024; i += 4) {
        s0 += p[(i + 0) * 256];
        s1 += p[(i + 1) * 256];
        s2 += p[(i + 2) * 256];
        s3 += p[(i + 3) * 256];
    }
    gap[tid] = (s0 + s1 + s2 + s3) * (1.0f / 1024.0f);
    __syncthreads();

    if (tid < 128) {
        float a = bc1[tid];
#pragma unroll 8
        for (int k = 0; k < 256; ++k) a = fmaf(gap[k], Wc1[k * 128 + tid], a);
        z1[tid] = fmaxf(a, 0.f);
    }
    __syncthreads();

    if (tid < 128) {
        float a = bc2[tid];
#pragma unroll 8
        for (int k = 0; k < 128; ++k) a = fmaf(z1[k], Wc2[k * 128 + tid], a);
        z2[tid] = fmaxf(a, 0.f);
    }
    __syncthreads();

    if (tid < 3) {
        float a = bc3[tid];
        for (int k = 0; k < 128; ++k) a = fmaf(z2[k], Wc3[k * 3 + tid], a);
        logits[tid] = a;
    }
    __syncthreads();

    if (tid == 0) {
        float l0 = logits[0], l1 = logits[1], l2 = logits[2];
        float m = fmaxf(l0, fmaxf(l1, l2));
        float e0 = expf(l0 - m), e1 = expf(l1 - m), e2 = expf(l2 - m);
        float inv = 1.f / (e0 + e1 + e2);
        out_pred[b * 3 + 0] = e0 * inv;
        out_pred[b * 3 + 1] = e1 * inv;
        out_pred[b * 3 + 2] = e2 * inv;
        int c = 0; float best = l0;
        if (l1 > best) { best = l1; c = 1; }
        if (l2 > best) { best = l2; c = 2; }
        g_cls[b] = c;
    }
}

// ---------------------------------------------------------------------------
// Final gather-conv as two thin HMMA GEMMs:
//   GEMM-o: [256 px x K=576] (ho) x [K x 8] (Wo3 sel ch -> n0,n1)  -> o0,o1
//   GEMM-w: [256 px x K=576] (hw) x [K x 8] (Ww3 sel ch -> n0)     -> wv
// Block = 16x16 output px; 8 warps, warp owns 2 m16 tiles (2 output rows).
// ---------------------------------------------------------------------------
__global__ void __launch_bounds__(256, 2)
conv3_select(const __half* __restrict__ h2o, const __half* __restrict__ h2w,
             const float* __restrict__ Wo3, const float* __restrict__ bo3,
             const float* __restrict__ Ww3, const float* __restrict__ bw3,
             float* __restrict__ out)
{
    constexpr int PITCH = 64 * 2 + 16;      // 144 B per pixel row
    constexpr int BP    = 576 * 2 + 16;     // 1168 B per n-row
    extern __shared__ char sm3[];
    char* ho = sm3;                         // 324 * 144
    char* hw = ho + 324 * PITCH;            // 324 * 144
    char* Bo = hw + 324 * PITCH;            // 8 * 1168
    char* Bw = Bo + 8 * BP;                 // 8 * 1168

    const int b   = blockIdx.z;
    const int y0  = blockIdx.y * 16;
    const int x0  = blockIdx.x * 16;
    const int tid = threadIdx.x;
    const int lane = tid & 31;
    const int wid  = tid >> 5;
    const int cls  = g_cls[b];

    const uint32_t hoU = smem_u32(ho);
    const uint32_t hwU = smem_u32(hw);
    const uint32_t BoU = smem_u32(Bo);
    const uint32_t BwU = smem_u32(Bw);

    // --- stage activation tiles (pure cp.async, px-major)
    const __half* po = h2o + (size_t)b * HW * HW * 64;
    const __half* pw = h2w + (size_t)b * HW * HW * 64;
    for (int i = tid; i < 324 * 8; i += 256) {
        int c  = i & 7;
        int px = i >> 3;
        int r = px / 18, cc = px % 18;
        int gy = y0 + r - 1, gx = x0 + cc - 1;
        bool ok = (unsigned)gy < HW && (unsigned)gx < HW;
        int cgy = ok ? gy : 0, cgx = ok ? gx : 0;
        size_t g = ((size_t)cgy * HW + cgx) * 64 + c * 8;
        cp16(hoU + px * PITCH + c * 16, po + g, ok ? 16 : 0);
        cp16(hwU + px * PITCH + c * 16, pw + g, ok ? 16 : 0);
    }
    cp_commit();

    // --- build B tiles: zero unused n-rows (disjoint from fills, no sync needed)
    for (int i = tid; i < (6 + 7) * (BP / 4); i += 256) {
        int j = i / (BP / 4);
        int w4 = i % (BP / 4);
        char* base = (j < 6) ? (Bo + (2 + j) * BP) : (Bw + (1 + j - 6) * BP);
        ((uint32_t*)base)[w4] = 0;
    }
    for (int i = tid; i < 576; i += 256) {          // k = tap*64 + ci
        *(__half*)(Bo + 0 * BP + i * 2) = __float2half_rn(Wo3[i * 6 + 2 * cls]);
        *(__half*)(Bo + 1 * BP + i * 2) = __float2half_rn(Wo3[i * 6 + 2 * cls + 1]);
        *(__half*)(Bw + 0 * BP + i * 2) = __float2half_rn(Ww3[i * 3 + cls]);
    }
    cp_wait_all();
    __syncthreads();

    float acc_o[2][4], acc_w[2][4];
#pragma unroll
    for (int mf = 0; mf < 2; ++mf)
#pragma unroll
        for (int q = 0; q < 4; ++q) { acc_o[mf][q] = 0.f; acc_w[mf][q] = 0.f; }

    const int mt0  = wid * 2;                 // output rows mt0, mt0+1
    const int apx  = lane & 15;
    const int acol = (lane >> 4) * 16;
    // B ldm: lanes0-7 rows(n) col k+0-7; 8-15 k+8-15; 16-23 k+16-23; 24-31 k+24-31
    const uint32_t boff = (uint32_t)((lane & 7) * BP + (lane >> 3) * 16);

    for (int tap = 0; tap < 9; ++tap) {
        const int ky = tap / 3, kx = tap % 3;
#pragma unroll
        for (int kp = 0; kp < 2; ++kp) {       // k32 chunks within tap
            const uint32_t kbyte = (uint32_t)((tap * 64 + kp * 32) * 2);
            uint32_t b_o[4], b_w[4];
            ldm_x4(b_o, BoU + boff + kbyte);
            ldm_x4(b_w, BwU + boff + kbyte);
#pragma unroll
            for (int ks2 = 0; ks2 < 2; ++ks2) {
                uint32_t a_o[2][4], a_w[2][4];
#pragma unroll
                for (int mf = 0; mf < 2; ++mf) {
                    int px = (mt0 + mf + ky) * 18 + apx + kx;
                    uint32_t off = (uint32_t)(px * PITCH + (kp * 32 + ks2 * 16) * 2 + acol);
                    ldm_x4(a_o[mf], hoU + off);
                    ldm_x4(a_w[mf], hwU + off);
                }
#pragma unroll
                for (int mf = 0; mf < 2; ++mf) {
                    mma16816(acc_o[mf], a_o[mf], &b_o[ks2 * 2]);
                    mma16816(acc_w[mf], a_w[mf], &b_w[ks2 * 2]);
                }
            }
        }
    }

    // --- epilogue: lanes with (lane&3)==0 hold n-cols 0,1
    if ((lane & 3) == 0) {
        const float bo0 = bo3[2 * cls], bo1 = bo3[2 * cls + 1], bwv = bw3[cls];
        const int pr = lane >> 2;              // 0..7
#pragma unroll
        for (int mf = 0; mf < 2; ++mf) {
            int gy = y0 + mt0 + mf;
#pragma unroll
            for (int h = 0; h < 2; ++h) {
                int gx = x0 + pr + h * 8;
                float o0 = acc_o[mf][h * 2 + 0] + bo0;
                float o1 = acc_o[mf][h * 2 + 1] + bo1;
                float wv = acc_w[mf][h * 2 + 0] + bwv;
                size_t pix = ((size_t)b * HW + gy) * HW + gx;
                *(float2*)&out[pix * 2] = make_float2(o0, o1);
                out[(size_t)BATCH * HW * HW * 2 + pix] = wv;
            }
        }
    }
}

// ---------------------------------------------------------------------------
extern "C" void kernel_launch(void* const* d_in, const int* in_sizes, int n_in,
                              void* d_out, int out_size)
{
    (void)in_sizes; (void)n_in; (void)out_size;
    const float* x0  = (const float*)d_in[0];
    const float* f4  = (const float*)d_in[1];
    const float* Wo1 = (const float*)d_in[2];
    const float* bo1 = (const float*)d_in[3];
    const float* Wo2 = (const float*)d_in[4];
    const float* bo2 = (const float*)d_in[5];
    const float* Wo3 = (const float*)d_in[6];
    const float* bo3 = (const float*)d_in[7];
    const float* Ww1 = (const float*)d_in[8];
    const float* bw1 = (const float*)d_in[9];
    const float* Ww2 = (const float*)d_in[10];
    const float* bw2 = (const float*)d_in[11];
    const float* Ww3 = (const float*)d_in[12];
    const float* bw3 = (const float*)d_in[13];
    const float* Wc1 = (const float*)d_in[14];
    const float* bc1 = (const float*)d_in[15];
    const float* Wc2 = (const float*)d_in[16];
    const float* bc2 = (const float*)d_in[17];
    const float* Wc3 = (const float*)d_in[18];
    const float* bc3 = (const float*)d_in[19];
    float* out = (float*)d_out;

    void *pH1o, *pH1w, *pH2o, *pH2w, *pW1o, *pW1w, *pW2o, *pW2w;
    cudaGetSymbolAddress(&pH1o, g_h1o);
    cudaGetSymbolAddress(&pH1w, g_h1w);
    cudaGetSymbolAddress(&pH2o, g_h2o);
    cudaGetSymbolAddress(&pH2w, g_h2w);
    cudaGetSymbolAddress(&pW1o, g_wp1o);
    cudaGetSymbolAddress(&pW1w, g_wp1w);
    cudaGetSymbolAddress(&pW2o, g_wp2o);
    cudaGetSymbolAddress(&pW2w, g_wp2w);

    const size_t smem1 = 256 + (size_t)340 * 80 + (size_t)9 * 64 * 80
                       + (size_t)256 * 144;                                   // 107.8 KB
    const size_t smem2 = 256 + (size_t)340 * 144 + (size_t)2 * 3 * 64 * 144;  // 102.1 KB
    const size_t smem3 = (size_t)2 * 324 * 144 + (size_t)16 * 1168;           // 109.4 KB

    cudaFuncSetAttribute((const void*)conv1_pers,
                         cudaFuncAttributeMaxDynamicSharedMemorySize, (int)smem1);
    cudaFuncSetAttribute((const void*)conv2_hmma,
                         cudaFuncAttributeMaxDynamicSharedMemorySize, (int)smem2);
    cudaFuncSetAttribute((const void*)conv3_select,
                         cudaFuncAttributeMaxDynamicSharedMemorySize, (int)smem3);

    float* pred = out + (size_t)BATCH * HW * HW * 3;

    head_kernel<<<BATCH, 256>>>(f4, Wc1, bc1, Wc2, bc2, Wc3, bc3, pred);
    prep_all<<<dim3(36, 4), 256>>>(Wo1, Ww1, Wo2, Ww2,
                                   (__half*)pW1o, (__half*)pW1w,
                                   (__half*)pW2o, (__half*)pW2w);

    dim3 g1(HW / 32, HW / 64, 2 * BATCH);   // persistent: each block does 8 y-tiles
    conv1_pers<<<g1, 256, smem1>>>(
        x0, (__half*)pW1o, (__half*)pW1w, bo1, bw1,
        (__half*)pH1o, (__half*)pH1w);

    dim3 g2(HW / 32, HW / 8, 2 * BATCH);
    conv2_hmma<<<g2, 256, smem2>>>(
        (__half*)pH1o, (__half*)pH1w, (__half*)pW2o, (__half*)pW2w, bo2, bw2,
        (__half*)pH2o, (__half*)pH2w);

    dim3 g3(HW / 16, HW / 16, BATCH);
    conv3_select<<<g3, 256, smem3>>>((__half*)pH2o, (__half*)pH2w,
                                     Wo3, bo3, Ww3, bw3, out);
}